// round 1
// baseline (speedup 1.0000x reference)
#include <cuda_runtime.h>
#include <cuda_bf16.h>
#include <math.h>

#define BATCH 2
#define SEQ 2048
#define DMODEL 4096
#define NQH 32
#define NKVH 8
#define HDIM 128

// ---------------- scratch (device globals; allocation-free) ----------------
__device__ float g_q[(size_t)BATCH * SEQ * NQH * HDIM];     // 16.8M floats
__device__ float g_k[(size_t)BATCH * SEQ * NKVH * HDIM];    // 4.2M
__device__ float g_v[(size_t)BATCH * SEQ * NKVH * HDIM];    // 4.2M
__device__ float g_attn[(size_t)BATCH * SEQ * NQH * HDIM];  // 16.8M

// ---------------- SGEMM: C[M,N] = A[M,K] @ B[K,N], row-major, fp32 ----------
// 128x128 block tile, BK=16, 256 threads, 8x8 per thread.
#define GBM 128
#define GBN 128
#define GBK 16
#define GTM 8
#define GTN 8
#define AS_PAD 132  // padded BM for the transposed A tile

__global__ __launch_bounds__(256) void sgemm_kernel(
    const float* __restrict__ A, const float* __restrict__ B,
    float* __restrict__ C, int M, int N, int K)
{
    __shared__ float As[GBK][AS_PAD];  // transposed: As[k][m]
    __shared__ float Bs[GBK][GBN];

    const int tid  = threadIdx.x;
    const int trow = tid >> 4;   // 0..15
    const int tcol = tid & 15;   // 0..15
    const int bm = blockIdx.y * GBM;
    const int bn = blockIdx.x * GBN;

    float acc[GTM][GTN];
#pragma unroll
    for (int i = 0; i < GTM; i++)
#pragma unroll
        for (int j = 0; j < GTN; j++) acc[i][j] = 0.f;

    for (int k0 = 0; k0 < K; k0 += GBK) {
        // Load A tile (128x16) as float4, store transposed.
#pragma unroll
        for (int it = 0; it < 2; it++) {
            int s = tid + it * 256;          // 0..511 float4 slots
            int ar = s >> 2;                 // 0..127
            int ac = (s & 3) * 4;            // 0,4,8,12
            float4 a = *reinterpret_cast<const float4*>(
                &A[(size_t)(bm + ar) * K + k0 + ac]);
            As[ac + 0][ar] = a.x;
            As[ac + 1][ar] = a.y;
            As[ac + 2][ar] = a.z;
            As[ac + 3][ar] = a.w;
            // Load B tile (16x128) as float4, natural layout.
            int br = s >> 5;                 // 0..15
            int bc = (s & 31) * 4;           // 0..124
            *reinterpret_cast<float4*>(&Bs[br][bc]) =
                *reinterpret_cast<const float4*>(
                    &B[(size_t)(k0 + br) * N + bn + bc]);
        }
        __syncthreads();

#pragma unroll
        for (int kk = 0; kk < GBK; kk++) {
            float ra[GTM], rb[GTN];
            float4 a0 = *reinterpret_cast<const float4*>(&As[kk][trow * GTM]);
            float4 a1 = *reinterpret_cast<const float4*>(&As[kk][trow * GTM + 4]);
            ra[0]=a0.x; ra[1]=a0.y; ra[2]=a0.z; ra[3]=a0.w;
            ra[4]=a1.x; ra[5]=a1.y; ra[6]=a1.z; ra[7]=a1.w;
            float4 b0 = *reinterpret_cast<const float4*>(&Bs[kk][tcol * GTN]);
            float4 b1 = *reinterpret_cast<const float4*>(&Bs[kk][tcol * GTN + 4]);
            rb[0]=b0.x; rb[1]=b0.y; rb[2]=b0.z; rb[3]=b0.w;
            rb[4]=b1.x; rb[5]=b1.y; rb[6]=b1.z; rb[7]=b1.w;
#pragma unroll
            for (int i = 0; i < GTM; i++)
#pragma unroll
                for (int j = 0; j < GTN; j++)
                    acc[i][j] += ra[i] * rb[j];
        }
        __syncthreads();
    }

#pragma unroll
    for (int i = 0; i < GTM; i++) {
        size_t crow = (size_t)(bm + trow * GTM + i) * N + bn + tcol * GTN;
#pragma unroll
        for (int j = 0; j < GTN; j += 4) {
            float4 v = make_float4(acc[i][j], acc[i][j+1], acc[i][j+2], acc[i][j+3]);
            *reinterpret_cast<float4*>(&C[crow + j]) = v;
        }
    }
}

// ---------------- RoPE (interleaved pairs) ----------------------------------
__global__ __launch_bounds__(256) void rope_kernel(
    float* __restrict__ t, const float* __restrict__ fc,
    const float* __restrict__ fs, int n_heads, int total)
{
    int idx = blockIdx.x * blockDim.x + threadIdx.x;  // over B*S*n_heads*64
    if (idx >= total) return;
    int i = idx & 63;
    int h = (idx >> 6) % n_heads;
    int row = idx / (n_heads * 64);
    int s = row % SEQ;
    float c  = fc[s * 64 + i];
    float sn = fs[s * 64 + i];
    float* p = t + (size_t)row * (n_heads * HDIM) + h * HDIM + 2 * i;
    float a = p[0], b = p[1];
    p[0] = a * c - b * sn;
    p[1] = a * sn + b * c;
}

// ---------------- Flash attention (causal, GQA), fp32 -----------------------
// Grid: (S/64, 32 heads, 2 batch). 256 threads: ty=tid/16 (rows), tx=tid%16.
// Thread owns score rows ty*4+r (r<4), score cols tx+16c (c<4),
// O cols tx+16c (c<8).
#define FBM 64
#define FBN 64
#define KS_PAD 129
#define PS_PAD 65
#define FLASH_SMEM_BYTES ((FBM*HDIM + FBN*KS_PAD + FBN*HDIM + FBM*PS_PAD) * 4)

__global__ __launch_bounds__(256) void flash_kernel(
    const float* __restrict__ Q, const float* __restrict__ K,
    const float* __restrict__ V, float* __restrict__ O)
{
    extern __shared__ float sm[];
    float* Qs = sm;                       // [64][128]
    float* Ks = Qs + FBM * HDIM;          // [64][129]
    float* Vs = Ks + FBN * KS_PAD;        // [64][128]
    float* Ps = Vs + FBN * HDIM;          // [64][65]

    const int qt = blockIdx.x;
    const int h  = blockIdx.y;
    const int b  = blockIdx.z;
    const int kvh = h >> 2;               // GQA: repeat(xk,4) => kv head = h/4
    const int tid = threadIdx.x;
    const int ty = tid >> 4;
    const int tx = tid & 15;
    const float scale = 0.0883883476483184f;  // 1/sqrt(128)
    const int q0 = qt * FBM;

    // Load Q tile
    const float* Qg = Q + ((size_t)(b * SEQ + q0)) * (NQH * HDIM) + h * HDIM;
    for (int t = tid; t < FBM * HDIM; t += 256) {
        int j = t >> 7, d = t & 127;
        Qs[j * HDIM + d] = Qg[(size_t)j * (NQH * HDIM) + d];
    }

    float m[4], l[4], o[4][8];
#pragma unroll
    for (int r = 0; r < 4; r++) {
        m[r] = -INFINITY; l[r] = 0.f;
#pragma unroll
        for (int c = 0; c < 8; c++) o[r][c] = 0.f;
    }

    const int ntiles = qt + 1;  // causal: only k-tiles <= q-tile
    for (int kt = 0; kt < ntiles; kt++) {
        __syncthreads();  // protect prev Vs/Ps reads (and Qs store on iter 0)
        const float* Kg = K + ((size_t)(b * SEQ + kt * FBN)) * (NKVH * HDIM) + kvh * HDIM;
        const float* Vg = V + ((size_t)(b * SEQ + kt * FBN)) * (NKVH * HDIM) + kvh * HDIM;
        for (int t = tid; t < FBN * HDIM; t += 256) {
            int j = t >> 7, d = t & 127;
            Ks[j * KS_PAD + d] = Kg[(size_t)j * (NKVH * HDIM) + d];
            Vs[j * HDIM  + d] = Vg[(size_t)j * (NKVH * HDIM) + d];
        }
        __syncthreads();

        // S = Q @ K^T  (4x4 per thread)
        float s[4][4];
#pragma unroll
        for (int r = 0; r < 4; r++)
#pragma unroll
            for (int c = 0; c < 4; c++) s[r][c] = 0.f;

        for (int d = 0; d < HDIM; d++) {
            float qr[4], kc[4];
#pragma unroll
            for (int r = 0; r < 4; r++) qr[r] = Qs[(ty * 4 + r) * HDIM + d];
#pragma unroll
            for (int c = 0; c < 4; c++) kc[c] = Ks[(tx + 16 * c) * KS_PAD + d];
#pragma unroll
            for (int r = 0; r < 4; r++)
#pragma unroll
                for (int c = 0; c < 4; c++)
                    s[r][c] += qr[r] * kc[c];
        }

        const bool diag = (kt == qt);
#pragma unroll
        for (int r = 0; r < 4; r++) {
            int ig = q0 + ty * 4 + r;
#pragma unroll
            for (int c = 0; c < 4; c++) {
                float val = s[r][c] * scale;
                if (diag) {
                    int jg = kt * FBN + tx + 16 * c;
                    if (jg > ig) val = -1e9f;
                }
                s[r][c] = val;
            }
        }

        // Online softmax update
#pragma unroll
        for (int r = 0; r < 4; r++) {
            float mt = fmaxf(fmaxf(s[r][0], s[r][1]), fmaxf(s[r][2], s[r][3]));
#pragma unroll
            for (int off = 8; off > 0; off >>= 1)
                mt = fmaxf(mt, __shfl_xor_sync(0xffffffffu, mt, off, 16));
            float mn = fmaxf(m[r], mt);
            float alpha = __expf(m[r] - mn);
            float psum = 0.f;
#pragma unroll
            for (int c = 0; c < 4; c++) {
                float p = __expf(s[r][c] - mn);
                s[r][c] = p;
                psum += p;
            }
#pragma unroll
            for (int off = 8; off > 0; off >>= 1)
                psum += __shfl_xor_sync(0xffffffffu, psum, off, 16);
            l[r] = l[r] * alpha + psum;
            m[r] = mn;
#pragma unroll
            for (int c = 0; c < 8; c++) o[r][c] *= alpha;
#pragma unroll
            for (int c = 0; c < 4; c++)
                Ps[(ty * 4 + r) * PS_PAD + tx + 16 * c] = s[r][c];
        }
        __syncthreads();

        // O += P @ V
        for (int j = 0; j < FBN; j++) {
            float pr[4];
#pragma unroll
            for (int r = 0; r < 4; r++) pr[r] = Ps[(ty * 4 + r) * PS_PAD + j];
            float vv[8];
#pragma unroll
            for (int c = 0; c < 8; c++) vv[c] = Vs[j * HDIM + tx + 16 * c];
#pragma unroll
            for (int r = 0; r < 4; r++)
#pragma unroll
                for (int c = 0; c < 8; c++)
                    o[r][c] += pr[r] * vv[c];
        }
    }

    // Write normalized output
    float* Og = O + ((size_t)(b * SEQ + q0)) * (NQH * HDIM) + h * HDIM;
#pragma unroll
    for (int r = 0; r < 4; r++) {
        float inv = 1.f / l[r];
#pragma unroll
        for (int c = 0; c < 8; c++)
            Og[(size_t)(ty * 4 + r) * (NQH * HDIM) + tx + 16 * c] = o[r][c] * inv;
    }
}

// ---------------- host launcher ---------------------------------------------
extern "C" void kernel_launch(void* const* d_in, const int* in_sizes, int n_in,
                              void* d_out, int out_size)
{
    const float* x   = (const float*)d_in[0];
    const float* w_q = (const float*)d_in[1];
    const float* w_k = (const float*)d_in[2];
    const float* w_v = (const float*)d_in[3];
    const float* w_o = (const float*)d_in[4];
    const float* fc  = (const float*)d_in[5];
    const float* fs  = (const float*)d_in[6];
    // d_in[7] = mask (causal -1e9) — implemented analytically in flash_kernel
    float* out = (float*)d_out;

    float *q, *k, *v, *att;
    cudaGetSymbolAddress((void**)&q,   g_q);
    cudaGetSymbolAddress((void**)&k,   g_k);
    cudaGetSymbolAddress((void**)&v,   g_v);
    cudaGetSymbolAddress((void**)&att, g_attn);

    cudaFuncSetAttribute(flash_kernel,
                         cudaFuncAttributeMaxDynamicSharedMemorySize,
                         FLASH_SMEM_BYTES);

    const int M = BATCH * SEQ;  // 4096
    dim3 blk(256);

    // QKV projections
    sgemm_kernel<<<dim3(DMODEL / GBN, M / GBM), blk>>>(x, w_q, q, M, DMODEL, DMODEL);
    sgemm_kernel<<<dim3((NKVH * HDIM) / GBN, M / GBM), blk>>>(x, w_k, k, M, NKVH * HDIM, DMODEL);
    sgemm_kernel<<<dim3((NKVH * HDIM) / GBN, M / GBM), blk>>>(x, w_v, v, M, NKVH * HDIM, DMODEL);

    // RoPE on q and k
    {
        int tq = M * NQH * 64;
        rope_kernel<<<(tq + 255) / 256, 256>>>(q, fc, fs, NQH, tq);
        int tk = M * NKVH * 64;
        rope_kernel<<<(tk + 255) / 256, 256>>>(k, fc, fs, NKVH, tk);
    }

    // Causal flash attention
    flash_kernel<<<dim3(SEQ / FBM, NQH, BATCH), 256, FLASH_SMEM_BYTES>>>(q, k, v, att);

    // Output projection
    sgemm_kernel<<<dim3(DMODEL / GBN, M / GBM), blk>>>(att, w_o, out, M, DMODEL, DMODEL);
}

// round 3
// speedup vs baseline: 1.8307x; 1.8307x over previous
#include <cuda_runtime.h>
#include <cuda_bf16.h>
#include <math.h>
#include <stdint.h>

#define BATCH 2
#define SEQ 2048
#define DMODEL 4096
#define NQH 32
#define NKVH 8
#define HDIM 128

// ---------------- scratch (device globals; allocation-free) ----------------
__device__ float g_q[(size_t)BATCH * SEQ * NQH * HDIM];
__device__ float g_k[(size_t)BATCH * SEQ * NKVH * HDIM];
__device__ float g_v[(size_t)BATCH * SEQ * NKVH * HDIM];
__device__ float g_attn[(size_t)BATCH * SEQ * NQH * HDIM];

// bf16 hi/lo split buffers
__device__ __nv_bfloat16 g_xh[(size_t)BATCH * SEQ * DMODEL];
__device__ __nv_bfloat16 g_xl[(size_t)BATCH * SEQ * DMODEL];
__device__ __nv_bfloat16 g_wqt_h[(size_t)DMODEL * DMODEL];   // transposed [N,K]
__device__ __nv_bfloat16 g_wqt_l[(size_t)DMODEL * DMODEL];
__device__ __nv_bfloat16 g_wkt_h[(size_t)(NKVH*HDIM) * DMODEL];
__device__ __nv_bfloat16 g_wkt_l[(size_t)(NKVH*HDIM) * DMODEL];
__device__ __nv_bfloat16 g_wvt_h[(size_t)(NKVH*HDIM) * DMODEL];
__device__ __nv_bfloat16 g_wvt_l[(size_t)(NKVH*HDIM) * DMODEL];
__device__ __nv_bfloat16 g_wot_h[(size_t)DMODEL * DMODEL];
__device__ __nv_bfloat16 g_wot_l[(size_t)DMODEL * DMODEL];
__device__ __nv_bfloat16 g_atth[(size_t)BATCH * SEQ * DMODEL];
__device__ __nv_bfloat16 g_attl[(size_t)BATCH * SEQ * DMODEL];

__device__ __forceinline__ uint32_t smem_to_u32(const void* p) {
    uint32_t a;
    asm("{ .reg .u64 t; cvta.to.shared.u64 t, %1; cvt.u32.u64 %0, t; }"
        : "=r"(a) : "l"(p));
    return a;
}

#define CP_ASYNC_16(dst, src) \
    asm volatile("cp.async.cg.shared.global [%0], [%1], 16;" :: "r"(dst), "l"(src) : "memory")
#define CP_COMMIT() asm volatile("cp.async.commit_group;" ::: "memory")
#define CP_WAIT_1()  asm volatile("cp.async.wait_group 1;" ::: "memory")

#define LDMATRIX_X4(r0, r1, r2, r3, addr) \
    asm volatile("ldmatrix.sync.aligned.m8n8.x4.shared.b16 {%0,%1,%2,%3}, [%4];" \
        : "=r"(r0), "=r"(r1), "=r"(r2), "=r"(r3) : "r"(addr))

#define MMA_BF16(d, a, b0, b1) \
    asm volatile("mma.sync.aligned.m16n8k16.row.col.f32.bf16.bf16.f32 " \
        "{%0,%1,%2,%3}, {%4,%5,%6,%7}, {%8,%9}, {%0,%1,%2,%3};" \
        : "+f"((d)[0]), "+f"((d)[1]), "+f"((d)[2]), "+f"((d)[3]) \
        : "r"((a)[0]), "r"((a)[1]), "r"((a)[2]), "r"((a)[3]), "r"(b0), "r"(b1))

// ---------------- split-bf16 GEMM via mma.sync (HMMA) ------------------------
// C[M,N] = A[M,K] @ B^T,  A hi/lo bf16 row-major [M,K], B hi/lo bf16 [N,K].
// CTA tile 128x128, BK=32, 8 warps (warp tile 32x64), 3-stage cp.async.
#define TBK 32
#define APITCH 80                       // bytes per smem row (64B data + 16 pad)
#define TILE_B (128 * APITCH)           // 10240 B per tile
#define STAGE_B (4 * TILE_B)            // Ah, Al, Bh, Bl
#define NSTAGE 3
#define GEMM_SMEM (NSTAGE * STAGE_B)    // 122880 B

__global__ __launch_bounds__(256, 1) void gemm_mma_kernel(
    const __nv_bfloat16* __restrict__ Ah, const __nv_bfloat16* __restrict__ Al,
    const __nv_bfloat16* __restrict__ Bh, const __nv_bfloat16* __restrict__ Bl,
    float* __restrict__ C, int M, int N, int K)
{
    extern __shared__ __align__(128) char smem_raw[];
    const uint32_t sbase = smem_to_u32(smem_raw);
    const int tid  = threadIdx.x;
    const int lane = tid & 31;
    const int wid  = tid >> 5;
    const int wm   = wid & 3;          // 4 warps along M
    const int wn   = wid >> 2;         // 2 warps along N
    const int bm = blockIdx.y * 128;
    const int bn = blockIdx.x * 128;

    const __nv_bfloat16* gsrc[4] = {Ah, Al, Bh, Bl};
    const int rbase4[4] = {bm, bm, bn, bn};

    auto issue_stage = [&](int it, int buf) {
        const int k0 = it * TBK;
#pragma unroll
        for (int t = 0; t < 4; t++) {
            const __nv_bfloat16* gp = gsrc[t] + (size_t)rbase4[t] * K + k0;
            const uint32_t db = sbase + buf * STAGE_B + t * TILE_B;
#pragma unroll
            for (int i = 0; i < 2; i++) {
                int c = tid + i * 256;         // 512 chunks of 16B per tile
                int r = c >> 2, ch = c & 3;
                const void* src = gp + (size_t)r * K + ch * 8;
                uint32_t dst = db + r * APITCH + ch * 16;
                CP_ASYNC_16(dst, src);
            }
        }
        CP_COMMIT();
    };

    // ldmatrix lane-address components
    const int lrow = (lane & 7) + ((lane >> 3) & 1) * 8;  // A: row within 16
    const int lk   = (lane >> 4) * 8;                     // A: k col block
    const int nrow = (lane >> 4) * 8 + (lane & 7);        // B: n within 16
    const int kadd = ((lane >> 3) & 1) * 8;               // B: k col block

    float acc[2][8][4];
#pragma unroll
    for (int mt = 0; mt < 2; mt++)
#pragma unroll
        for (int nt = 0; nt < 8; nt++)
#pragma unroll
            for (int j = 0; j < 4; j++) acc[mt][nt][j] = 0.f;

    const int NITER = K / TBK;
    issue_stage(0, 0);
    issue_stage(1, 1);

    for (int it = 0; it < NITER; it++) {
        CP_WAIT_1();
        __syncthreads();
        if (it + 2 < NITER) issue_stage(it + 2, (it + 2) % NSTAGE);
        else CP_COMMIT();  // keep group accounting consistent

        const uint32_t base = sbase + (it % NSTAGE) * STAGE_B;
#pragma unroll
        for (int kk = 0; kk < 2; kk++) {
            uint32_t bh[8][2], bl[8][2];
#pragma unroll
            for (int p = 0; p < 4; p++) {
                uint32_t ab = base + 2 * TILE_B +
                              (wn * 64 + p * 16 + nrow) * APITCH + (kk * 16 + kadd) * 2;
                LDMATRIX_X4(bh[2*p][0], bh[2*p][1], bh[2*p+1][0], bh[2*p+1][1], ab);
                ab += TILE_B;
                LDMATRIX_X4(bl[2*p][0], bl[2*p][1], bl[2*p+1][0], bl[2*p+1][1], ab);
            }
#pragma unroll
            for (int mt = 0; mt < 2; mt++) {
                uint32_t ah[4], al[4];
                uint32_t aa = base + (wm * 32 + mt * 16 + lrow) * APITCH +
                              (kk * 16 + lk) * 2;
                LDMATRIX_X4(ah[0], ah[1], ah[2], ah[3], aa);
                aa += TILE_B;
                LDMATRIX_X4(al[0], al[1], al[2], al[3], aa);
#pragma unroll
                for (int nt = 0; nt < 8; nt++) {
                    MMA_BF16(acc[mt][nt], ah, bh[nt][0], bh[nt][1]);
                    MMA_BF16(acc[mt][nt], al, bh[nt][0], bh[nt][1]);
                    MMA_BF16(acc[mt][nt], ah, bl[nt][0], bl[nt][1]);
                }
            }
        }
    }

    // epilogue: fp32 accumulators -> C
    const int g  = lane >> 2;
    const int t2 = (lane & 3) * 2;
#pragma unroll
    for (int mt = 0; mt < 2; mt++) {
#pragma unroll
        for (int nt = 0; nt < 8; nt++) {
            int row = bm + wm * 32 + mt * 16 + g;
            int col = bn + wn * 64 + nt * 8 + t2;
            *(float2*)&C[(size_t)row * N + col] =
                make_float2(acc[mt][nt][0], acc[mt][nt][1]);
            *(float2*)&C[(size_t)(row + 8) * N + col] =
                make_float2(acc[mt][nt][2], acc[mt][nt][3]);
        }
    }
}

// ---------------- fp32 -> bf16 hi/lo split (elementwise) --------------------
__device__ __forceinline__ uint32_t pack2bf(float a, float b) {
    __nv_bfloat162 t = __floats2bfloat162_rn(a, b);
    return *reinterpret_cast<uint32_t*>(&t);
}
__global__ __launch_bounds__(256) void convert_split_kernel(
    const float* __restrict__ in, __nv_bfloat16* __restrict__ oh,
    __nv_bfloat16* __restrict__ ol, int n4)
{
    int i = blockIdx.x * blockDim.x + threadIdx.x;
    if (i >= n4) return;
    float4 v = ((const float4*)in)[i];
    __nv_bfloat16 h0 = __float2bfloat16(v.x), h1 = __float2bfloat16(v.y);
    __nv_bfloat16 h2 = __float2bfloat16(v.z), h3 = __float2bfloat16(v.w);
    float l0 = v.x - __bfloat162float(h0), l1 = v.y - __bfloat162float(h1);
    float l2 = v.z - __bfloat162float(h2), l3 = v.w - __bfloat162float(h3);
    ((uint2*)oh)[i] = make_uint2(pack2bf(__bfloat162float(h0), __bfloat162float(h1)),
                                 pack2bf(__bfloat162float(h2), __bfloat162float(h3)));
    ((uint2*)ol)[i] = make_uint2(pack2bf(l0, l1), pack2bf(l2, l3));
}

// ---------------- fp32 [K,N] -> transposed bf16 hi/lo [N,K] -----------------
__global__ __launch_bounds__(256) void transpose_split_kernel(
    const float* __restrict__ in, __nv_bfloat16* __restrict__ oh,
    __nv_bfloat16* __restrict__ ol, int K, int N)
{
    __shared__ float tile[32][33];
    const int k0 = blockIdx.y * 32, n0 = blockIdx.x * 32;
    const int tx = threadIdx.x & 31, ty = threadIdx.x >> 5;  // 32x8
#pragma unroll
    for (int i = 0; i < 32; i += 8)
        tile[ty + i][tx] = in[(size_t)(k0 + ty + i) * N + n0 + tx];
    __syncthreads();
#pragma unroll
    for (int i = 0; i < 32; i += 8) {
        float v = tile[tx][ty + i];  // = in[k0+tx][n0+ty+i]
        __nv_bfloat16 h = __float2bfloat16(v);
        float l = v - __bfloat162float(h);
        size_t o = (size_t)(n0 + ty + i) * K + k0 + tx;
        oh[o] = h;
        ol[o] = __float2bfloat16(l);
    }
}

// ---------------- RoPE (interleaved pairs) ----------------------------------
__global__ __launch_bounds__(256) void rope_kernel(
    float* __restrict__ t, const float* __restrict__ fc,
    const float* __restrict__ fs, int n_heads, int total)
{
    int idx = blockIdx.x * blockDim.x + threadIdx.x;
    if (idx >= total) return;
    int i = idx & 63;
    int h = (idx >> 6) % n_heads;
    int row = idx / (n_heads * 64);
    int s = row % SEQ;
    float c  = fc[s * 64 + i];
    float sn = fs[s * 64 + i];
    float* p = t + (size_t)row * (n_heads * HDIM) + h * HDIM + 2 * i;
    float a = p[0], b = p[1];
    p[0] = a * c - b * sn;
    p[1] = a * sn + b * c;
}

// ---------------- Flash attention (causal, GQA), fp32 -----------------------
#define FBM 64
#define FBN 64
#define KS_PAD 129
#define PS_PAD 65
#define FLASH_SMEM_BYTES ((FBM*HDIM + FBN*KS_PAD + FBN*HDIM + FBM*PS_PAD) * 4)

__global__ __launch_bounds__(256) void flash_kernel(
    const float* __restrict__ Q, const float* __restrict__ K,
    const float* __restrict__ V, float* __restrict__ O)
{
    extern __shared__ float smf[];
    float* Qs = smf;
    float* Ks = Qs + FBM * HDIM;
    float* Vs = Ks + FBN * KS_PAD;
    float* Ps = Vs + FBN * HDIM;

    const int qt = blockIdx.x;
    const int h  = blockIdx.y;
    const int b  = blockIdx.z;
    const int kvh = h >> 2;
    const int tid = threadIdx.x;
    const int ty = tid >> 4;
    const int tx = tid & 15;
    const float scale = 0.0883883476483184f;
    const int q0 = qt * FBM;

    const float* Qg = Q + ((size_t)(b * SEQ + q0)) * (NQH * HDIM) + h * HDIM;
    for (int t = tid; t < FBM * HDIM; t += 256) {
        int j = t >> 7, d = t & 127;
        Qs[j * HDIM + d] = Qg[(size_t)j * (NQH * HDIM) + d];
    }

    float m[4], l[4], o[4][8];
#pragma unroll
    for (int r = 0; r < 4; r++) {
        m[r] = -INFINITY; l[r] = 0.f;
#pragma unroll
        for (int c = 0; c < 8; c++) o[r][c] = 0.f;
    }

    const int ntiles = qt + 1;
    for (int kt = 0; kt < ntiles; kt++) {
        __syncthreads();
        const float* Kg = K + ((size_t)(b * SEQ + kt * FBN)) * (NKVH * HDIM) + kvh * HDIM;
        const float* Vg = V + ((size_t)(b * SEQ + kt * FBN)) * (NKVH * HDIM) + kvh * HDIM;
        for (int t = tid; t < FBN * HDIM; t += 256) {
            int j = t >> 7, d = t & 127;
            Ks[j * KS_PAD + d] = Kg[(size_t)j * (NKVH * HDIM) + d];
            Vs[j * HDIM  + d] = Vg[(size_t)j * (NKVH * HDIM) + d];
        }
        __syncthreads();

        float s[4][4];
#pragma unroll
        for (int r = 0; r < 4; r++)
#pragma unroll
            for (int c = 0; c < 4; c++) s[r][c] = 0.f;

        for (int d = 0; d < HDIM; d++) {
            float qr[4], kc[4];
#pragma unroll
            for (int r = 0; r < 4; r++) qr[r] = Qs[(ty * 4 + r) * HDIM + d];
#pragma unroll
            for (int c = 0; c < 4; c++) kc[c] = Ks[(tx + 16 * c) * KS_PAD + d];
#pragma unroll
            for (int r = 0; r < 4; r++)
#pragma unroll
                for (int c = 0; c < 4; c++)
                    s[r][c] += qr[r] * kc[c];
        }

        const bool diag = (kt == qt);
#pragma unroll
        for (int r = 0; r < 4; r++) {
            int ig = q0 + ty * 4 + r;
#pragma unroll
            for (int c = 0; c < 4; c++) {
                float val = s[r][c] * scale;
                if (diag) {
                    int jg = kt * FBN + tx + 16 * c;
                    if (jg > ig) val = -1e9f;
                }
                s[r][c] = val;
            }
        }

#pragma unroll
        for (int r = 0; r < 4; r++) {
            float mt = fmaxf(fmaxf(s[r][0], s[r][1]), fmaxf(s[r][2], s[r][3]));
#pragma unroll
            for (int off = 8; off > 0; off >>= 1)
                mt = fmaxf(mt, __shfl_xor_sync(0xffffffffu, mt, off, 16));
            float mn = fmaxf(m[r], mt);
            float alpha = __expf(m[r] - mn);
            float psum = 0.f;
#pragma unroll
            for (int c = 0; c < 4; c++) {
                float p = __expf(s[r][c] - mn);
                s[r][c] = p;
                psum += p;
            }
#pragma unroll
            for (int off = 8; off > 0; off >>= 1)
                psum += __shfl_xor_sync(0xffffffffu, psum, off, 16);
            l[r] = l[r] * alpha + psum;
            m[r] = mn;
#pragma unroll
            for (int c = 0; c < 8; c++) o[r][c] *= alpha;
#pragma unroll
            for (int c = 0; c < 4; c++)
                Ps[(ty * 4 + r) * PS_PAD + tx + 16 * c] = s[r][c];
        }
        __syncthreads();

        for (int j = 0; j < FBN; j++) {
            float pr[4];
#pragma unroll
            for (int r = 0; r < 4; r++) pr[r] = Ps[(ty * 4 + r) * PS_PAD + j];
            float vv[8];
#pragma unroll
            for (int c = 0; c < 8; c++) vv[c] = Vs[j * HDIM + tx + 16 * c];
#pragma unroll
            for (int r = 0; r < 4; r++)
#pragma unroll
                for (int c = 0; c < 8; c++)
                    o[r][c] += pr[r] * vv[c];
        }
    }

    float* Og = O + ((size_t)(b * SEQ + q0)) * (NQH * HDIM) + h * HDIM;
#pragma unroll
    for (int r = 0; r < 4; r++) {
        float inv = 1.f / l[r];
#pragma unroll
        for (int c = 0; c < 8; c++)
            Og[(size_t)(ty * 4 + r) * (NQH * HDIM) + tx + 16 * c] = o[r][c] * inv;
    }
}

// ---------------- host launcher ---------------------------------------------
extern "C" void kernel_launch(void* const* d_in, const int* in_sizes, int n_in,
                              void* d_out, int out_size)
{
    const float* x   = (const float*)d_in[0];
    const float* w_q = (const float*)d_in[1];
    const float* w_k = (const float*)d_in[2];
    const float* w_v = (const float*)d_in[3];
    const float* w_o = (const float*)d_in[4];
    const float* fc  = (const float*)d_in[5];
    const float* fs  = (const float*)d_in[6];
    float* out = (float*)d_out;

    float *q, *k, *v, *att;
    cudaGetSymbolAddress((void**)&q,   g_q);
    cudaGetSymbolAddress((void**)&k,   g_k);
    cudaGetSymbolAddress((void**)&v,   g_v);
    cudaGetSymbolAddress((void**)&att, g_attn);
    __nv_bfloat16 *xh, *xl, *wqh, *wql, *wkh, *wkl, *wvh, *wvl, *woh, *wol, *ath, *atl;
    cudaGetSymbolAddress((void**)&xh,  g_xh);   cudaGetSymbolAddress((void**)&xl,  g_xl);
    cudaGetSymbolAddress((void**)&wqh, g_wqt_h); cudaGetSymbolAddress((void**)&wql, g_wqt_l);
    cudaGetSymbolAddress((void**)&wkh, g_wkt_h); cudaGetSymbolAddress((void**)&wkl, g_wkt_l);
    cudaGetSymbolAddress((void**)&wvh, g_wvt_h); cudaGetSymbolAddress((void**)&wvl, g_wvt_l);
    cudaGetSymbolAddress((void**)&woh, g_wot_h); cudaGetSymbolAddress((void**)&wol, g_wot_l);
    cudaGetSymbolAddress((void**)&ath, g_atth);  cudaGetSymbolAddress((void**)&atl, g_attl);

    cudaFuncSetAttribute(flash_kernel, cudaFuncAttributeMaxDynamicSharedMemorySize,
                         FLASH_SMEM_BYTES);
    cudaFuncSetAttribute(gemm_mma_kernel, cudaFuncAttributeMaxDynamicSharedMemorySize,
                         GEMM_SMEM);

    const int M = BATCH * SEQ;   // 4096
    const int NKV = NKVH * HDIM; // 1024

    // weight transposes + splits
    transpose_split_kernel<<<dim3(DMODEL / 32, DMODEL / 32), 256>>>(w_q, wqh, wql, DMODEL, DMODEL);
    transpose_split_kernel<<<dim3(NKV / 32,    DMODEL / 32), 256>>>(w_k, wkh, wkl, DMODEL, NKV);
    transpose_split_kernel<<<dim3(NKV / 32,    DMODEL / 32), 256>>>(w_v, wvh, wvl, DMODEL, NKV);
    transpose_split_kernel<<<dim3(DMODEL / 32, DMODEL / 32), 256>>>(w_o, woh, wol, DMODEL, DMODEL);

    // x split
    {
        int n4 = (M * DMODEL) / 4;
        convert_split_kernel<<<(n4 + 255) / 256, 256>>>(x, xh, xl, n4);
    }

    // QKV projections (mma.sync bf16-split)
    gemm_mma_kernel<<<dim3(DMODEL / 128, M / 128), 256, GEMM_SMEM>>>(
        xh, xl, wqh, wql, q, M, DMODEL, DMODEL);
    gemm_mma_kernel<<<dim3(NKV / 128, M / 128), 256, GEMM_SMEM>>>(
        xh, xl, wkh, wkl, k, M, NKV, DMODEL);
    gemm_mma_kernel<<<dim3(NKV / 128, M / 128), 256, GEMM_SMEM>>>(
        xh, xl, wvh, wvl, v, M, NKV, DMODEL);

    // RoPE
    {
        int tq = M * NQH * 64;
        rope_kernel<<<(tq + 255) / 256, 256>>>(q, fc, fs, NQH, tq);
        int tk = M * NKVH * 64;
        rope_kernel<<<(tk + 255) / 256, 256>>>(k, fc, fs, NKVH, tk);
    }

    // attention
    flash_kernel<<<dim3(SEQ / FBM, NQH, BATCH), 256, FLASH_SMEM_BYTES>>>(q, k, v, att);

    // attention output split + O projection
    {
        int n4 = (M * DMODEL) / 4;
        convert_split_kernel<<<(n4 + 255) / 256, 256>>>(att, ath, atl, n4);
    }
    gemm_mma_kernel<<<dim3(DMODEL / 128, M / 128), 256, GEMM_SMEM>>>(
        ath, atl, woh, wol, out, M, DMODEL, DMODEL);
}

// round 4
// speedup vs baseline: 2.5302x; 1.3821x over previous
#include <cuda_runtime.h>
#include <cuda_bf16.h>
#include <math.h>
#include <stdint.h>

#define BATCH 2
#define SEQ 2048
#define DMODEL 4096
#define NQH 32
#define NKVH 8
#define HDIM 128

// ---------------- scratch (device globals; allocation-free) ----------------
__device__ float g_q[(size_t)BATCH * SEQ * NQH * HDIM];
__device__ float g_k[(size_t)BATCH * SEQ * NKVH * HDIM];
__device__ float g_v[(size_t)BATCH * SEQ * NKVH * HDIM];
__device__ float g_attn[(size_t)BATCH * SEQ * NQH * HDIM];

__device__ __nv_bfloat16 g_xh[(size_t)BATCH * SEQ * DMODEL];
__device__ __nv_bfloat16 g_xl[(size_t)BATCH * SEQ * DMODEL];
__device__ __nv_bfloat16 g_wqt_h[(size_t)DMODEL * DMODEL];
__device__ __nv_bfloat16 g_wqt_l[(size_t)DMODEL * DMODEL];
__device__ __nv_bfloat16 g_wkt_h[(size_t)(NKVH*HDIM) * DMODEL];
__device__ __nv_bfloat16 g_wkt_l[(size_t)(NKVH*HDIM) * DMODEL];
__device__ __nv_bfloat16 g_wvt_h[(size_t)(NKVH*HDIM) * DMODEL];
__device__ __nv_bfloat16 g_wvt_l[(size_t)(NKVH*HDIM) * DMODEL];
__device__ __nv_bfloat16 g_wot_h[(size_t)DMODEL * DMODEL];
__device__ __nv_bfloat16 g_wot_l[(size_t)DMODEL * DMODEL];
__device__ __nv_bfloat16 g_atth[(size_t)BATCH * SEQ * DMODEL];
__device__ __nv_bfloat16 g_attl[(size_t)BATCH * SEQ * DMODEL];

// attention bf16 hi/lo operands
__device__ __nv_bfloat16 g_qsh[(size_t)BATCH * SEQ * NQH * HDIM];
__device__ __nv_bfloat16 g_qsl[(size_t)BATCH * SEQ * NQH * HDIM];
__device__ __nv_bfloat16 g_ksh[(size_t)BATCH * SEQ * NKVH * HDIM];
__device__ __nv_bfloat16 g_ksl[(size_t)BATCH * SEQ * NKVH * HDIM];
__device__ __nv_bfloat16 g_vsh[(size_t)BATCH * SEQ * NKVH * HDIM];
__device__ __nv_bfloat16 g_vsl[(size_t)BATCH * SEQ * NKVH * HDIM];

__device__ __forceinline__ uint32_t smem_to_u32(const void* p) {
    uint32_t a;
    asm("{ .reg .u64 t; cvta.to.shared.u64 t, %1; cvt.u32.u64 %0, t; }"
        : "=r"(a) : "l"(p));
    return a;
}

#define CP_ASYNC_16(dst, src) \
    asm volatile("cp.async.cg.shared.global [%0], [%1], 16;" :: "r"(dst), "l"(src) : "memory")
#define CP_COMMIT() asm volatile("cp.async.commit_group;" ::: "memory")
#define CP_WAIT_1()  asm volatile("cp.async.wait_group 1;" ::: "memory")

#define LDMATRIX_X4(r0, r1, r2, r3, addr) \
    asm volatile("ldmatrix.sync.aligned.m8n8.x4.shared.b16 {%0,%1,%2,%3}, [%4];" \
        : "=r"(r0), "=r"(r1), "=r"(r2), "=r"(r3) : "r"(addr))
#define LDMATRIX_X4_T(r0, r1, r2, r3, addr) \
    asm volatile("ldmatrix.sync.aligned.m8n8.x4.trans.shared.b16 {%0,%1,%2,%3}, [%4];" \
        : "=r"(r0), "=r"(r1), "=r"(r2), "=r"(r3) : "r"(addr))

#define MMA_BF16(d, a, b0, b1) \
    asm volatile("mma.sync.aligned.m16n8k16.row.col.f32.bf16.bf16.f32 " \
        "{%0,%1,%2,%3}, {%4,%5,%6,%7}, {%8,%9}, {%0,%1,%2,%3};" \
        : "+f"((d)[0]), "+f"((d)[1]), "+f"((d)[2]), "+f"((d)[3]) \
        : "r"((a)[0]), "r"((a)[1]), "r"((a)[2]), "r"((a)[3]), "r"(b0), "r"(b1))

__device__ __forceinline__ uint32_t pack2bf(float a, float b) {
    __nv_bfloat162 t = __floats2bfloat162_rn(a, b);
    return *reinterpret_cast<uint32_t*>(&t);
}
// pack hi pair and lo pair for split-precision A operand
__device__ __forceinline__ void split_pack(float a, float b, uint32_t& h, uint32_t& l) {
    __nv_bfloat16 ha = __float2bfloat16(a), hb = __float2bfloat16(b);
    h = pack2bf(__bfloat162float(ha), __bfloat162float(hb));
    l = pack2bf(a - __bfloat162float(ha), b - __bfloat162float(hb));
}

// ---------------- split-bf16 GEMM via mma.sync (HMMA) ------------------------
#define TBK 32
#define APITCH 80
#define TILE_B (128 * APITCH)
#define STAGE_B (4 * TILE_B)
#define NSTAGE 3
#define GEMM_SMEM (NSTAGE * STAGE_B)

__global__ __launch_bounds__(256, 1) void gemm_mma_kernel(
    const __nv_bfloat16* __restrict__ Ah, const __nv_bfloat16* __restrict__ Al,
    const __nv_bfloat16* __restrict__ Bh, const __nv_bfloat16* __restrict__ Bl,
    float* __restrict__ C, int M, int N, int K)
{
    extern __shared__ __align__(128) char smem_raw[];
    const uint32_t sbase = smem_to_u32(smem_raw);
    const int tid  = threadIdx.x;
    const int lane = tid & 31;
    const int wid  = tid >> 5;
    const int wm   = wid & 3;
    const int wn   = wid >> 2;
    const int bm = blockIdx.y * 128;
    const int bn = blockIdx.x * 128;

    const __nv_bfloat16* gsrc[4] = {Ah, Al, Bh, Bl};
    const int rbase4[4] = {bm, bm, bn, bn};

    auto issue_stage = [&](int it, int buf) {
        const int k0 = it * TBK;
#pragma unroll
        for (int t = 0; t < 4; t++) {
            const __nv_bfloat16* gp = gsrc[t] + (size_t)rbase4[t] * K + k0;
            const uint32_t db = sbase + buf * STAGE_B + t * TILE_B;
#pragma unroll
            for (int i = 0; i < 2; i++) {
                int c = tid + i * 256;
                int r = c >> 2, ch = c & 3;
                const void* src = gp + (size_t)r * K + ch * 8;
                uint32_t dst = db + r * APITCH + ch * 16;
                CP_ASYNC_16(dst, src);
            }
        }
        CP_COMMIT();
    };

    const int lrow = (lane & 7) + ((lane >> 3) & 1) * 8;
    const int lk   = (lane >> 4) * 8;
    const int nrow = (lane >> 4) * 8 + (lane & 7);
    const int kadd = ((lane >> 3) & 1) * 8;

    float acc[2][8][4];
#pragma unroll
    for (int mt = 0; mt < 2; mt++)
#pragma unroll
        for (int nt = 0; nt < 8; nt++)
#pragma unroll
            for (int j = 0; j < 4; j++) acc[mt][nt][j] = 0.f;

    const int NITER = K / TBK;
    issue_stage(0, 0);
    issue_stage(1, 1);

    for (int it = 0; it < NITER; it++) {
        CP_WAIT_1();
        __syncthreads();
        if (it + 2 < NITER) issue_stage(it + 2, (it + 2) % NSTAGE);
        else CP_COMMIT();

        const uint32_t base = sbase + (it % NSTAGE) * STAGE_B;
#pragma unroll
        for (int kk = 0; kk < 2; kk++) {
            uint32_t bh[8][2], bl[8][2];
#pragma unroll
            for (int p = 0; p < 4; p++) {
                uint32_t ab = base + 2 * TILE_B +
                              (wn * 64 + p * 16 + nrow) * APITCH + (kk * 16 + kadd) * 2;
                LDMATRIX_X4(bh[2*p][0], bh[2*p][1], bh[2*p+1][0], bh[2*p+1][1], ab);
                ab += TILE_B;
                LDMATRIX_X4(bl[2*p][0], bl[2*p][1], bl[2*p+1][0], bl[2*p+1][1], ab);
            }
#pragma unroll
            for (int mt = 0; mt < 2; mt++) {
                uint32_t ah[4], al[4];
                uint32_t aa = base + (wm * 32 + mt * 16 + lrow) * APITCH +
                              (kk * 16 + lk) * 2;
                LDMATRIX_X4(ah[0], ah[1], ah[2], ah[3], aa);
                aa += TILE_B;
                LDMATRIX_X4(al[0], al[1], al[2], al[3], aa);
#pragma unroll
                for (int nt = 0; nt < 8; nt++) {
                    MMA_BF16(acc[mt][nt], ah, bh[nt][0], bh[nt][1]);
                    MMA_BF16(acc[mt][nt], al, bh[nt][0], bh[nt][1]);
                    MMA_BF16(acc[mt][nt], ah, bl[nt][0], bl[nt][1]);
                }
            }
        }
    }

    const int g  = lane >> 2;
    const int t2 = (lane & 3) * 2;
#pragma unroll
    for (int mt = 0; mt < 2; mt++) {
#pragma unroll
        for (int nt = 0; nt < 8; nt++) {
            int row = bm + wm * 32 + mt * 16 + g;
            int col = bn + wn * 64 + nt * 8 + t2;
            *(float2*)&C[(size_t)row * N + col] =
                make_float2(acc[mt][nt][0], acc[mt][nt][1]);
            *(float2*)&C[(size_t)(row + 8) * N + col] =
                make_float2(acc[mt][nt][2], acc[mt][nt][3]);
        }
    }
}

// ---------------- fp32 -> bf16 hi/lo split (elementwise) --------------------
__global__ __launch_bounds__(256) void convert_split_kernel(
    const float* __restrict__ in, __nv_bfloat16* __restrict__ oh,
    __nv_bfloat16* __restrict__ ol, int n4)
{
    int i = blockIdx.x * blockDim.x + threadIdx.x;
    if (i >= n4) return;
    float4 v = ((const float4*)in)[i];
    uint32_t h0, l0, h1, l1;
    split_pack(v.x, v.y, h0, l0);
    split_pack(v.z, v.w, h1, l1);
    ((uint2*)oh)[i] = make_uint2(h0, h1);
    ((uint2*)ol)[i] = make_uint2(l0, l1);
}

// ---------------- fp32 [K,N] -> transposed bf16 hi/lo [N,K] -----------------
__global__ __launch_bounds__(256) void transpose_split_kernel(
    const float* __restrict__ in, __nv_bfloat16* __restrict__ oh,
    __nv_bfloat16* __restrict__ ol, int K, int N)
{
    __shared__ float tile[32][33];
    const int k0 = blockIdx.y * 32, n0 = blockIdx.x * 32;
    const int tx = threadIdx.x & 31, ty = threadIdx.x >> 5;
#pragma unroll
    for (int i = 0; i < 32; i += 8)
        tile[ty + i][tx] = in[(size_t)(k0 + ty + i) * N + n0 + tx];
    __syncthreads();
#pragma unroll
    for (int i = 0; i < 32; i += 8) {
        float v = tile[tx][ty + i];
        __nv_bfloat16 h = __float2bfloat16(v);
        float l = v - __bfloat162float(h);
        size_t o = (size_t)(n0 + ty + i) * K + k0 + tx;
        oh[o] = h;
        ol[o] = __float2bfloat16(l);
    }
}

// ---------------- RoPE + split to bf16 hi/lo ---------------------------------
__global__ __launch_bounds__(256) void rope_split_kernel(
    const float* __restrict__ t, const float* __restrict__ fc,
    const float* __restrict__ fs, __nv_bfloat16* __restrict__ oh,
    __nv_bfloat16* __restrict__ ol, int n_heads, float scale, int total)
{
    int idx = blockIdx.x * blockDim.x + threadIdx.x;
    if (idx >= total) return;
    int i = idx & 63;
    int h = (idx >> 6) % n_heads;
    int row = idx / (n_heads * 64);
    int s = row % SEQ;
    float c  = fc[s * 64 + i];
    float sn = fs[s * 64 + i];
    size_t off = (size_t)row * (n_heads * HDIM) + h * HDIM + 2 * i;
    float a = t[off], b = t[off + 1];
    float ra = (a * c - b * sn) * scale;
    float rb = (a * sn + b * c) * scale;
    uint32_t hp, lp;
    split_pack(ra, rb, hp, lp);
    *(uint32_t*)(oh + off) = hp;
    *(uint32_t*)(ol + off) = lp;
}

// ---------------- flash attention via mma.sync (split bf16) ------------------
// BM=128 q rows / CTA, BN=64 kv per tile, 8 warps x 16 rows.
#define FP 272  // smem pitch bytes for 128-bf16 rows (17*16B, conflict-free)
#define FQH 0
#define FQL 34816
#define FKH 69632
#define FKL 87040
#define FVH 104448
#define FVL 121856
#define FLASH_SMEM 139264

__global__ __launch_bounds__(256, 1) void flash_mma_kernel(
    const __nv_bfloat16* __restrict__ Qh, const __nv_bfloat16* __restrict__ Ql,
    const __nv_bfloat16* __restrict__ Kh, const __nv_bfloat16* __restrict__ Kl,
    const __nv_bfloat16* __restrict__ Vh, const __nv_bfloat16* __restrict__ Vl,
    float* __restrict__ O)
{
    extern __shared__ __align__(128) char sm[];
    const uint32_t sb = smem_to_u32(sm);
    const int qt = blockIdx.x, h = blockIdx.y, b = blockIdx.z;
    const int kvh = h >> 2;
    const int tid = threadIdx.x, lane = tid & 31, w = tid >> 5;
    const int q0 = qt * 128;

    // ldmatrix lane addressing
    const int lrow = (lane & 7) + ((lane >> 3) & 1) * 8;  // A frag
    const int lk   = (lane >> 4) * 8;
    const int nrow = (lane >> 4) * 8 + (lane & 7);        // B frag (non-trans)
    const int kadd = ((lane >> 3) & 1) * 8;
    const int trow = lane & 15;                           // B frag (trans)
    const int tcol = (lane >> 4) * 8;

    // ---- load Q hi/lo tile (128 rows x 128 bf16) ----
    {
        const size_t qoff = ((size_t)(b * SEQ + q0) * NQH + h) * HDIM;
        const uint4* gh = (const uint4*)(Qh + qoff);
        const uint4* gl = (const uint4*)(Ql + qoff);
        for (int i = tid; i < 2048; i += 256) {
            int r = i >> 4, c = i & 15;
            *(uint4*)(sm + FQH + r * FP + c * 16) = gh[(size_t)r * 512 + c];
            *(uint4*)(sm + FQL + r * FP + c * 16) = gl[(size_t)r * 512 + c];
        }
    }

    float m0 = -1e30f, m1 = -1e30f, l0 = 0.f, l1 = 0.f;
    float oacc[16][4];
#pragma unroll
    for (int nt = 0; nt < 16; nt++)
#pragma unroll
        for (int j = 0; j < 4; j++) oacc[nt][j] = 0.f;

    const int row0 = q0 + w * 16 + (lane >> 2);
    const int cb   = 2 * (lane & 3);
    const int ktiles = 2 * qt + 2;

    for (int kt = 0; kt < ktiles; kt++) {
        __syncthreads();
        // ---- load K/V hi/lo tiles (64 rows x 128 bf16 each) ----
        {
            const size_t off = ((size_t)(b * SEQ + kt * 64) * NKVH + kvh) * HDIM;
            const uint4* gkh = (const uint4*)(Kh + off);
            const uint4* gkl = (const uint4*)(Kl + off);
            const uint4* gvh = (const uint4*)(Vh + off);
            const uint4* gvl = (const uint4*)(Vl + off);
            for (int i = tid; i < 1024; i += 256) {
                int r = i >> 4, c = i & 15;
                uint32_t d = r * FP + c * 16;
                size_t g = (size_t)r * 128 + c;
                *(uint4*)(sm + FKH + d) = gkh[g];
                *(uint4*)(sm + FKL + d) = gkl[g];
                *(uint4*)(sm + FVH + d) = gvh[g];
                *(uint4*)(sm + FVL + d) = gvl[g];
            }
        }
        __syncthreads();

        // ---- S = Qh*Kh + Ql*Kh + Qh*Kl  (16 rows x 64 cols per warp) ----
        float s[8][4];
#pragma unroll
        for (int nt = 0; nt < 8; nt++)
#pragma unroll
            for (int j = 0; j < 4; j++) s[nt][j] = 0.f;

#pragma unroll
        for (int ks = 0; ks < 8; ks++) {
            uint32_t ah[4], al[4];
            uint32_t aa = sb + FQH + (w * 16 + lrow) * FP + (ks * 16 + lk) * 2;
            LDMATRIX_X4(ah[0], ah[1], ah[2], ah[3], aa);
            LDMATRIX_X4(al[0], al[1], al[2], al[3], aa + (FQL - FQH));
#pragma unroll
            for (int p = 0; p < 4; p++) {
                uint32_t bh0, bh1, bh2, bh3, bl0, bl1, bl2, bl3;
                uint32_t ba = sb + FKH + (p * 16 + nrow) * FP + (ks * 16 + kadd) * 2;
                LDMATRIX_X4(bh0, bh1, bh2, bh3, ba);
                LDMATRIX_X4(bl0, bl1, bl2, bl3, ba + (FKL - FKH));
                MMA_BF16(s[2*p],   ah, bh0, bh1);
                MMA_BF16(s[2*p],   al, bh0, bh1);
                MMA_BF16(s[2*p],   ah, bl0, bl1);
                MMA_BF16(s[2*p+1], ah, bh2, bh3);
                MMA_BF16(s[2*p+1], al, bh2, bh3);
                MMA_BF16(s[2*p+1], ah, bl2, bl3);
            }
        }

        // ---- causal mask (last two tiles only) ----
        if (kt >= 2 * qt) {
            const int colb = kt * 64 + cb;
#pragma unroll
            for (int nt = 0; nt < 8; nt++) {
                int c0 = colb + 8 * nt;
                if (c0 > row0)     s[nt][0] = -1e30f;
                if (c0 + 1 > row0) s[nt][1] = -1e30f;
                if (c0 > row0 + 8)     s[nt][2] = -1e30f;
                if (c0 + 1 > row0 + 8) s[nt][3] = -1e30f;
            }
        }

        // ---- online softmax (rows row0, row0+8) ----
        float mt0 = -1e30f, mt1 = -1e30f;
#pragma unroll
        for (int nt = 0; nt < 8; nt++) {
            mt0 = fmaxf(mt0, fmaxf(s[nt][0], s[nt][1]));
            mt1 = fmaxf(mt1, fmaxf(s[nt][2], s[nt][3]));
        }
        mt0 = fmaxf(mt0, __shfl_xor_sync(0xffffffffu, mt0, 1));
        mt0 = fmaxf(mt0, __shfl_xor_sync(0xffffffffu, mt0, 2));
        mt1 = fmaxf(mt1, __shfl_xor_sync(0xffffffffu, mt1, 1));
        mt1 = fmaxf(mt1, __shfl_xor_sync(0xffffffffu, mt1, 2));
        float mn0 = fmaxf(m0, mt0), mn1 = fmaxf(m1, mt1);
        float a0 = __expf(m0 - mn0), a1 = __expf(m1 - mn1);
        float ps0 = 0.f, ps1 = 0.f;
#pragma unroll
        for (int nt = 0; nt < 8; nt++) {
            s[nt][0] = __expf(s[nt][0] - mn0);
            s[nt][1] = __expf(s[nt][1] - mn0);
            s[nt][2] = __expf(s[nt][2] - mn1);
            s[nt][3] = __expf(s[nt][3] - mn1);
            ps0 += s[nt][0] + s[nt][1];
            ps1 += s[nt][2] + s[nt][3];
        }
        ps0 += __shfl_xor_sync(0xffffffffu, ps0, 1);
        ps0 += __shfl_xor_sync(0xffffffffu, ps0, 2);
        ps1 += __shfl_xor_sync(0xffffffffu, ps1, 1);
        ps1 += __shfl_xor_sync(0xffffffffu, ps1, 2);
        l0 = l0 * a0 + ps0;  m0 = mn0;
        l1 = l1 * a1 + ps1;  m1 = mn1;
#pragma unroll
        for (int nt = 0; nt < 16; nt++) {
            oacc[nt][0] *= a0; oacc[nt][1] *= a0;
            oacc[nt][2] *= a1; oacc[nt][3] *= a1;
        }

        // ---- O += Ph*Vh + Pl*Vh + Ph*Vl ----
#pragma unroll
        for (int j = 0; j < 4; j++) {
            uint32_t ph[4], pl[4];
            split_pack(s[2*j][0],   s[2*j][1],   ph[0], pl[0]);
            split_pack(s[2*j][2],   s[2*j][3],   ph[1], pl[1]);
            split_pack(s[2*j+1][0], s[2*j+1][1], ph[2], pl[2]);
            split_pack(s[2*j+1][2], s[2*j+1][3], ph[3], pl[3]);
#pragma unroll
            for (int t = 0; t < 8; t++) {
                uint32_t vh0, vh1, vh2, vh3, vl0, vl1, vl2, vl3;
                uint32_t va = sb + FVH + (j * 16 + trow) * FP + (t * 16 + tcol) * 2;
                LDMATRIX_X4_T(vh0, vh1, vh2, vh3, va);
                LDMATRIX_X4_T(vl0, vl1, vl2, vl3, va + (FVL - FVH));
                MMA_BF16(oacc[2*t],   ph, vh0, vh1);
                MMA_BF16(oacc[2*t],   pl, vh0, vh1);
                MMA_BF16(oacc[2*t],   ph, vl0, vl1);
                MMA_BF16(oacc[2*t+1], ph, vh2, vh3);
                MMA_BF16(oacc[2*t+1], pl, vh2, vh3);
                MMA_BF16(oacc[2*t+1], ph, vl2, vl3);
            }
        }
    }

    // ---- epilogue ----
    const float inv0 = 1.f / l0, inv1 = 1.f / l1;
    float* ob0 = O + ((size_t)(b * SEQ + row0)) * DMODEL + h * HDIM + cb;
    float* ob1 = O + ((size_t)(b * SEQ + row0 + 8)) * DMODEL + h * HDIM + cb;
#pragma unroll
    for (int nt = 0; nt < 16; nt++) {
        *(float2*)(ob0 + 8 * nt) = make_float2(oacc[nt][0] * inv0, oacc[nt][1] * inv0);
        *(float2*)(ob1 + 8 * nt) = make_float2(oacc[nt][2] * inv1, oacc[nt][3] * inv1);
    }
}

// ---------------- host launcher ---------------------------------------------
extern "C" void kernel_launch(void* const* d_in, const int* in_sizes, int n_in,
                              void* d_out, int out_size)
{
    const float* x   = (const float*)d_in[0];
    const float* w_q = (const float*)d_in[1];
    const float* w_k = (const float*)d_in[2];
    const float* w_v = (const float*)d_in[3];
    const float* w_o = (const float*)d_in[4];
    const float* fc  = (const float*)d_in[5];
    const float* fs  = (const float*)d_in[6];
    float* out = (float*)d_out;

    float *q, *k, *v, *att;
    cudaGetSymbolAddress((void**)&q,   g_q);
    cudaGetSymbolAddress((void**)&k,   g_k);
    cudaGetSymbolAddress((void**)&v,   g_v);
    cudaGetSymbolAddress((void**)&att, g_attn);
    __nv_bfloat16 *xh, *xl, *wqh, *wql, *wkh, *wkl, *wvh, *wvl, *woh, *wol, *ath, *atl;
    __nv_bfloat16 *qsh, *qsl, *ksh, *ksl, *vsh, *vsl;
    cudaGetSymbolAddress((void**)&xh,  g_xh);    cudaGetSymbolAddress((void**)&xl,  g_xl);
    cudaGetSymbolAddress((void**)&wqh, g_wqt_h); cudaGetSymbolAddress((void**)&wql, g_wqt_l);
    cudaGetSymbolAddress((void**)&wkh, g_wkt_h); cudaGetSymbolAddress((void**)&wkl, g_wkt_l);
    cudaGetSymbolAddress((void**)&wvh, g_wvt_h); cudaGetSymbolAddress((void**)&wvl, g_wvt_l);
    cudaGetSymbolAddress((void**)&woh, g_wot_h); cudaGetSymbolAddress((void**)&wol, g_wot_l);
    cudaGetSymbolAddress((void**)&ath, g_atth);  cudaGetSymbolAddress((void**)&atl, g_attl);
    cudaGetSymbolAddress((void**)&qsh, g_qsh);   cudaGetSymbolAddress((void**)&qsl, g_qsl);
    cudaGetSymbolAddress((void**)&ksh, g_ksh);   cudaGetSymbolAddress((void**)&ksl, g_ksl);
    cudaGetSymbolAddress((void**)&vsh, g_vsh);   cudaGetSymbolAddress((void**)&vsl, g_vsl);

    cudaFuncSetAttribute(gemm_mma_kernel, cudaFuncAttributeMaxDynamicSharedMemorySize,
                         GEMM_SMEM);
    cudaFuncSetAttribute(flash_mma_kernel, cudaFuncAttributeMaxDynamicSharedMemorySize,
                         FLASH_SMEM);

    const int M = BATCH * SEQ;   // 4096
    const int NKV = NKVH * HDIM; // 1024

    // weight transposes + splits
    transpose_split_kernel<<<dim3(DMODEL / 32, DMODEL / 32), 256>>>(w_q, wqh, wql, DMODEL, DMODEL);
    transpose_split_kernel<<<dim3(NKV / 32,    DMODEL / 32), 256>>>(w_k, wkh, wkl, DMODEL, NKV);
    transpose_split_kernel<<<dim3(NKV / 32,    DMODEL / 32), 256>>>(w_v, wvh, wvl, DMODEL, NKV);
    transpose_split_kernel<<<dim3(DMODEL / 32, DMODEL / 32), 256>>>(w_o, woh, wol, DMODEL, DMODEL);

    // x split
    {
        int n4 = (M * DMODEL) / 4;
        convert_split_kernel<<<(n4 + 255) / 256, 256>>>(x, xh, xl, n4);
    }

    // QKV projections (fp32 out)
    gemm_mma_kernel<<<dim3(DMODEL / 128, M / 128), 256, GEMM_SMEM>>>(
        xh, xl, wqh, wql, q, M, DMODEL, DMODEL);
    gemm_mma_kernel<<<dim3(NKV / 128, M / 128), 256, GEMM_SMEM>>>(
        xh, xl, wkh, wkl, k, M, NKV, DMODEL);
    gemm_mma_kernel<<<dim3(NKV / 128, M / 128), 256, GEMM_SMEM>>>(
        xh, xl, wvh, wvl, v, M, NKV, DMODEL);

    // RoPE + split (scale 1/sqrt(d) folded into q); V split
    {
        int tq = M * NQH * 64;
        rope_split_kernel<<<(tq + 255) / 256, 256>>>(q, fc, fs, qsh, qsl, NQH,
                                                     0.0883883476483184f, tq);
        int tk = M * NKVH * 64;
        rope_split_kernel<<<(tk + 255) / 256, 256>>>(k, fc, fs, ksh, ksl, NKVH, 1.0f, tk);
        int n4 = (M * NKV) / 4;
        convert_split_kernel<<<(n4 + 255) / 256, 256>>>(v, vsh, vsl, n4);
    }

    // flash attention (tensor cores)
    flash_mma_kernel<<<dim3(SEQ / 128, NQH, BATCH), 256, FLASH_SMEM>>>(
        qsh, qsl, ksh, ksl, vsh, vsl, att);

    // attention output split + O projection
    {
        int n4 = (M * DMODEL) / 4;
        convert_split_kernel<<<(n4 + 255) / 256, 256>>>(att, ath, atl, n4);
    }
    gemm_mma_kernel<<<dim3(DMODEL / 128, M / 128), 256, GEMM_SMEM>>>(
        ath, atl, woh, wol, out, M, DMODEL, DMODEL);
}

// round 5
// speedup vs baseline: 2.5530x; 1.0090x over previous
#include <cuda_runtime.h>
#include <cuda_bf16.h>
#include <math.h>
#include <stdint.h>

#define BATCH 2
#define SEQ 2048
#define DMODEL 4096
#define NQH 32
#define NKVH 8
#define HDIM 128
#define NKV (NKVH * HDIM)        // 1024
#define NQKV (DMODEL + 2 * NKV)  // 6144

// ---------------- scratch (device globals; allocation-free) ----------------
__device__ __nv_bfloat16 g_xh[(size_t)BATCH * SEQ * DMODEL];
__device__ __nv_bfloat16 g_xl[(size_t)BATCH * SEQ * DMODEL];
__device__ __nv_bfloat16 g_wqkv_h[(size_t)NQKV * DMODEL];   // [6144,4096] rows: q,k,v
__device__ __nv_bfloat16 g_wqkv_l[(size_t)NQKV * DMODEL];
__device__ __nv_bfloat16 g_wot_h[(size_t)DMODEL * DMODEL];
__device__ __nv_bfloat16 g_wot_l[(size_t)DMODEL * DMODEL];
__device__ __nv_bfloat16 g_atth[(size_t)BATCH * SEQ * DMODEL];
__device__ __nv_bfloat16 g_attl[(size_t)BATCH * SEQ * DMODEL];

__device__ __nv_bfloat16 g_qsh[(size_t)BATCH * SEQ * NQH * HDIM];
__device__ __nv_bfloat16 g_qsl[(size_t)BATCH * SEQ * NQH * HDIM];
__device__ __nv_bfloat16 g_ksh[(size_t)BATCH * SEQ * NKV];
__device__ __nv_bfloat16 g_ksl[(size_t)BATCH * SEQ * NKV];
__device__ __nv_bfloat16 g_vsh[(size_t)BATCH * SEQ * NKV];
__device__ __nv_bfloat16 g_vsl[(size_t)BATCH * SEQ * NKV];

__device__ __forceinline__ uint32_t smem_to_u32(const void* p) {
    uint32_t a;
    asm("{ .reg .u64 t; cvta.to.shared.u64 t, %1; cvt.u32.u64 %0, t; }"
        : "=r"(a) : "l"(p));
    return a;
}

#define CP_ASYNC_16(dst, src) \
    asm volatile("cp.async.cg.shared.global [%0], [%1], 16;" :: "r"(dst), "l"(src) : "memory")
#define CP_COMMIT() asm volatile("cp.async.commit_group;" ::: "memory")
#define CP_WAIT_2()  asm volatile("cp.async.wait_group 2;" ::: "memory")

#define LDMATRIX_X4(r0, r1, r2, r3, addr) \
    asm volatile("ldmatrix.sync.aligned.m8n8.x4.shared.b16 {%0,%1,%2,%3}, [%4];" \
        : "=r"(r0), "=r"(r1), "=r"(r2), "=r"(r3) : "r"(addr))
#define LDMATRIX_X4_T(r0, r1, r2, r3, addr) \
    asm volatile("ldmatrix.sync.aligned.m8n8.x4.trans.shared.b16 {%0,%1,%2,%3}, [%4];" \
        : "=r"(r0), "=r"(r1), "=r"(r2), "=r"(r3) : "r"(addr))

#define MMA_BF16(d, a, b0, b1) \
    asm volatile("mma.sync.aligned.m16n8k16.row.col.f32.bf16.bf16.f32 " \
        "{%0,%1,%2,%3}, {%4,%5,%6,%7}, {%8,%9}, {%0,%1,%2,%3};" \
        : "+f"((d)[0]), "+f"((d)[1]), "+f"((d)[2]), "+f"((d)[3]) \
        : "r"((a)[0]), "r"((a)[1]), "r"((a)[2]), "r"((a)[3]), "r"(b0), "r"(b1))

__device__ __forceinline__ uint32_t pack2bf(float a, float b) {
    __nv_bfloat162 t = __floats2bfloat162_rn(a, b);
    return *reinterpret_cast<uint32_t*>(&t);
}
__device__ __forceinline__ void split_pack(float a, float b, uint32_t& h, uint32_t& l) {
    __nv_bfloat16 ha = __float2bfloat16(a), hb = __float2bfloat16(b);
    h = pack2bf(__bfloat162float(ha), __bfloat162float(hb));
    l = pack2bf(a - __bfloat162float(ha), b - __bfloat162float(hb));
}

// ---------------- shared GEMM mainloop (device inline) -----------------------
#define TBK 32
#define APITCH 80
#define TILE_B (128 * APITCH)
#define STAGE_B (4 * TILE_B)
#define NSTAGE 4
#define GEMM_SMEM (NSTAGE * STAGE_B)   // 163840

struct GemmCtx {
    float acc[2][8][4];
    int lane, wid, wm, wn, bm, bn;
};

__device__ __forceinline__ void gemm_mainloop(
    GemmCtx& g, char* smem_raw,
    const __nv_bfloat16* __restrict__ Ah, const __nv_bfloat16* __restrict__ Al,
    const __nv_bfloat16* __restrict__ Bh, const __nv_bfloat16* __restrict__ Bl,
    int K)
{
    const uint32_t sbase = smem_to_u32(smem_raw);
    const int tid = threadIdx.x;
    const int lane = g.lane, wm = g.wm, wn = g.wn, bm = g.bm, bn = g.bn;

    const __nv_bfloat16* gsrc[4] = {Ah, Al, Bh, Bl};
    const int rbase4[4] = {bm, bm, bn, bn};

    auto issue_stage = [&](int it, int buf) {
        const int k0 = it * TBK;
#pragma unroll
        for (int t = 0; t < 4; t++) {
            const __nv_bfloat16* gp = gsrc[t] + (size_t)rbase4[t] * K + k0;
            const uint32_t db = sbase + buf * STAGE_B + t * TILE_B;
#pragma unroll
            for (int i = 0; i < 2; i++) {
                int c = tid + i * 256;
                int r = c >> 2, ch = c & 3;
                const void* src = gp + (size_t)r * K + ch * 8;
                uint32_t dst = db + r * APITCH + ch * 16;
                CP_ASYNC_16(dst, src);
            }
        }
        CP_COMMIT();
    };

    const int lrow = (lane & 7) + ((lane >> 3) & 1) * 8;
    const int lk   = (lane >> 4) * 8;
    const int nrow = (lane >> 4) * 8 + (lane & 7);
    const int kadd = ((lane >> 3) & 1) * 8;

#pragma unroll
    for (int mt = 0; mt < 2; mt++)
#pragma unroll
        for (int nt = 0; nt < 8; nt++)
#pragma unroll
            for (int j = 0; j < 4; j++) g.acc[mt][nt][j] = 0.f;

    const int NITER = K / TBK;
    issue_stage(0, 0);
    issue_stage(1, 1);
    issue_stage(2, 2);

    for (int it = 0; it < NITER; it++) {
        CP_WAIT_2();
        __syncthreads();
        if (it + 3 < NITER) issue_stage(it + 3, (it + 3) % NSTAGE);
        else CP_COMMIT();

        const uint32_t base = sbase + (it % NSTAGE) * STAGE_B;
#pragma unroll
        for (int kk = 0; kk < 2; kk++) {
            uint32_t bh[8][2], bl[8][2];
#pragma unroll
            for (int p = 0; p < 4; p++) {
                uint32_t ab = base + 2 * TILE_B +
                              (wn * 64 + p * 16 + nrow) * APITCH + (kk * 16 + kadd) * 2;
                LDMATRIX_X4(bh[2*p][0], bh[2*p][1], bh[2*p+1][0], bh[2*p+1][1], ab);
                ab += TILE_B;
                LDMATRIX_X4(bl[2*p][0], bl[2*p][1], bl[2*p+1][0], bl[2*p+1][1], ab);
            }
#pragma unroll
            for (int mt = 0; mt < 2; mt++) {
                uint32_t ah[4], al[4];
                uint32_t aa = base + (wm * 32 + mt * 16 + lrow) * APITCH +
                              (kk * 16 + lk) * 2;
                LDMATRIX_X4(ah[0], ah[1], ah[2], ah[3], aa);
                aa += TILE_B;
                LDMATRIX_X4(al[0], al[1], al[2], al[3], aa);
#pragma unroll
                for (int nt = 0; nt < 8; nt++) {
                    MMA_BF16(g.acc[mt][nt], ah, bh[nt][0], bh[nt][1]);
                    MMA_BF16(g.acc[mt][nt], al, bh[nt][0], bh[nt][1]);
                    MMA_BF16(g.acc[mt][nt], ah, bl[nt][0], bl[nt][1]);
                }
            }
        }
    }
}

// ---------------- GEMM -> fp32 C (O projection) ------------------------------
__global__ __launch_bounds__(256, 1) void gemm_mma_kernel(
    const __nv_bfloat16* __restrict__ Ah, const __nv_bfloat16* __restrict__ Al,
    const __nv_bfloat16* __restrict__ Bh, const __nv_bfloat16* __restrict__ Bl,
    float* __restrict__ C, int M, int N, int K)
{
    extern __shared__ __align__(128) char smem_raw[];
    GemmCtx g;
    g.lane = threadIdx.x & 31; g.wid = threadIdx.x >> 5;
    g.wm = g.wid & 3; g.wn = g.wid >> 2;
    g.bm = blockIdx.y * 128; g.bn = blockIdx.x * 128;
    gemm_mainloop(g, smem_raw, Ah, Al, Bh, Bl, K);

    const int gr = g.lane >> 2, t2 = (g.lane & 3) * 2;
#pragma unroll
    for (int mt = 0; mt < 2; mt++) {
#pragma unroll
        for (int nt = 0; nt < 8; nt++) {
            int row = g.bm + g.wm * 32 + mt * 16 + gr;
            int col = g.bn + g.wn * 64 + nt * 8 + t2;
            *(float2*)&C[(size_t)row * N + col] =
                make_float2(g.acc[mt][nt][0], g.acc[mt][nt][1]);
            *(float2*)&C[(size_t)(row + 8) * N + col] =
                make_float2(g.acc[mt][nt][2], g.acc[mt][nt][3]);
        }
    }
}

// ---------------- fused QKV GEMM: rope/scale/split epilogue ------------------
__device__ __forceinline__ void rope_split_store(
    __nv_bfloat16* oh, __nv_bfloat16* ol,
    const float* __restrict__ fc, const float* __restrict__ fs,
    int row, int col, float v0, float v1, int stride, int coloff, float scale)
{
    int s = row & (SEQ - 1);
    int i = (col & 127) >> 1;
    float c  = __ldg(fc + s * 64 + i);
    float sn = __ldg(fs + s * 64 + i);
    float ra = (v0 * c - v1 * sn) * scale;
    float rb = (v0 * sn + v1 * c) * scale;
    uint32_t h, l;
    split_pack(ra, rb, h, l);
    size_t o = (size_t)row * stride + (col - coloff);
    *(uint32_t*)(oh + o) = h;
    *(uint32_t*)(ol + o) = l;
}

__global__ __launch_bounds__(256, 1) void gemm_qkv_kernel(
    const __nv_bfloat16* __restrict__ Ah, const __nv_bfloat16* __restrict__ Al,
    const __nv_bfloat16* __restrict__ Bh, const __nv_bfloat16* __restrict__ Bl,
    const float* __restrict__ fc, const float* __restrict__ fs,
    __nv_bfloat16* __restrict__ qh, __nv_bfloat16* __restrict__ ql,
    __nv_bfloat16* __restrict__ kh, __nv_bfloat16* __restrict__ kl,
    __nv_bfloat16* __restrict__ vh, __nv_bfloat16* __restrict__ vl,
    int K)
{
    extern __shared__ __align__(128) char smem_raw[];
    GemmCtx g;
    g.lane = threadIdx.x & 31; g.wid = threadIdx.x >> 5;
    g.wm = g.wid & 3; g.wn = g.wid >> 2;
    g.bm = blockIdx.y * 128; g.bn = blockIdx.x * 128;
    gemm_mainloop(g, smem_raw, Ah, Al, Bh, Bl, K);

    const int gr = g.lane >> 2, t2 = (g.lane & 3) * 2;
    const float qscale = 0.0883883476483184f;  // 1/sqrt(128)

    if (g.bn < DMODEL) {            // Q region: rope + scale + split
#pragma unroll
        for (int mt = 0; mt < 2; mt++)
#pragma unroll
            for (int nt = 0; nt < 8; nt++) {
                int row = g.bm + g.wm * 32 + mt * 16 + gr;
                int col = g.bn + g.wn * 64 + nt * 8 + t2;
                rope_split_store(qh, ql, fc, fs, row, col,
                                 g.acc[mt][nt][0], g.acc[mt][nt][1], DMODEL, 0, qscale);
                rope_split_store(qh, ql, fc, fs, row + 8, col,
                                 g.acc[mt][nt][2], g.acc[mt][nt][3], DMODEL, 0, qscale);
            }
    } else if (g.bn < DMODEL + NKV) {  // K region: rope + split
#pragma unroll
        for (int mt = 0; mt < 2; mt++)
#pragma unroll
            for (int nt = 0; nt < 8; nt++) {
                int row = g.bm + g.wm * 32 + mt * 16 + gr;
                int col = g.bn + g.wn * 64 + nt * 8 + t2;
                rope_split_store(kh, kl, fc, fs, row, col,
                                 g.acc[mt][nt][0], g.acc[mt][nt][1], NKV, DMODEL, 1.0f);
                rope_split_store(kh, kl, fc, fs, row + 8, col,
                                 g.acc[mt][nt][2], g.acc[mt][nt][3], NKV, DMODEL, 1.0f);
            }
    } else {                            // V region: plain split
#pragma unroll
        for (int mt = 0; mt < 2; mt++)
#pragma unroll
            for (int nt = 0; nt < 8; nt++) {
                int row = g.bm + g.wm * 32 + mt * 16 + gr;
                int col = g.bn + g.wn * 64 + nt * 8 + t2 - (DMODEL + NKV);
                uint32_t h, l;
                size_t o0 = (size_t)row * NKV + col;
                split_pack(g.acc[mt][nt][0], g.acc[mt][nt][1], h, l);
                *(uint32_t*)(vh + o0) = h; *(uint32_t*)(vl + o0) = l;
                size_t o1 = o0 + (size_t)8 * NKV;
                split_pack(g.acc[mt][nt][2], g.acc[mt][nt][3], h, l);
                *(uint32_t*)(vh + o1) = h; *(uint32_t*)(vl + o1) = l;
            }
    }
}

// ---------------- fp32 -> bf16 hi/lo split (x only) --------------------------
__global__ __launch_bounds__(256) void convert_split_kernel(
    const float* __restrict__ in, __nv_bfloat16* __restrict__ oh,
    __nv_bfloat16* __restrict__ ol, int n4)
{
    int i = blockIdx.x * blockDim.x + threadIdx.x;
    if (i >= n4) return;
    float4 v = ((const float4*)in)[i];
    uint32_t h0, l0, h1, l1;
    split_pack(v.x, v.y, h0, l0);
    split_pack(v.z, v.w, h1, l1);
    ((uint2*)oh)[i] = make_uint2(h0, h1);
    ((uint2*)ol)[i] = make_uint2(l0, l1);
}

// ---------------- fp32 [K,N] -> transposed bf16 hi/lo [N,K] ------------------
__global__ __launch_bounds__(256) void transpose_split_kernel(
    const float* __restrict__ in, __nv_bfloat16* __restrict__ oh,
    __nv_bfloat16* __restrict__ ol, int K, int N)
{
    __shared__ float tile[32][33];
    const int k0 = blockIdx.y * 32, n0 = blockIdx.x * 32;
    const int tx = threadIdx.x & 31, ty = threadIdx.x >> 5;
#pragma unroll
    for (int i = 0; i < 32; i += 8)
        tile[ty + i][tx] = in[(size_t)(k0 + ty + i) * N + n0 + tx];
    __syncthreads();
#pragma unroll
    for (int i = 0; i < 32; i += 8) {
        float v = tile[tx][ty + i];
        __nv_bfloat16 h = __float2bfloat16(v);
        float l = v - __bfloat162float(h);
        size_t o = (size_t)(n0 + ty + i) * K + k0 + tx;
        oh[o] = h;
        ol[o] = __float2bfloat16(l);
    }
}

// ---------------- flash attention via mma.sync (split bf16) ------------------
#define FP 272
#define FQH 0
#define FQL 34816
#define FKH 69632
#define FKL 87040
#define FVH 104448
#define FVL 121856
#define FLASH_SMEM 139264

__global__ __launch_bounds__(256, 1) void flash_mma_kernel(
    const __nv_bfloat16* __restrict__ Qh, const __nv_bfloat16* __restrict__ Ql,
    const __nv_bfloat16* __restrict__ Kh, const __nv_bfloat16* __restrict__ Kl,
    const __nv_bfloat16* __restrict__ Vh, const __nv_bfloat16* __restrict__ Vl,
    __nv_bfloat16* __restrict__ Oh, __nv_bfloat16* __restrict__ Ol)
{
    extern __shared__ __align__(128) char sm[];
    const uint32_t sb = smem_to_u32(sm);
    const int qt = blockIdx.x, h = blockIdx.y, b = blockIdx.z;
    const int kvh = h >> 2;
    const int tid = threadIdx.x, lane = tid & 31, w = tid >> 5;
    const int q0 = qt * 128;

    const int lrow = (lane & 7) + ((lane >> 3) & 1) * 8;
    const int lk   = (lane >> 4) * 8;
    const int nrow = (lane >> 4) * 8 + (lane & 7);
    const int kadd = ((lane >> 3) & 1) * 8;
    const int trow = lane & 15;
    const int tcol = (lane >> 4) * 8;

    {
        const size_t qoff = ((size_t)(b * SEQ + q0) * NQH + h) * HDIM;
        const uint4* gh = (const uint4*)(Qh + qoff);
        const uint4* gl = (const uint4*)(Ql + qoff);
        for (int i = tid; i < 2048; i += 256) {
            int r = i >> 4, c = i & 15;
            *(uint4*)(sm + FQH + r * FP + c * 16) = gh[(size_t)r * 512 + c];
            *(uint4*)(sm + FQL + r * FP + c * 16) = gl[(size_t)r * 512 + c];
        }
    }

    float m0 = -1e30f, m1 = -1e30f, l0 = 0.f, l1 = 0.f;
    float oacc[16][4];
#pragma unroll
    for (int nt = 0; nt < 16; nt++)
#pragma unroll
        for (int j = 0; j < 4; j++) oacc[nt][j] = 0.f;

    const int row0 = q0 + w * 16 + (lane >> 2);
    const int cb   = 2 * (lane & 3);
    const int ktiles = 2 * qt + 2;

    for (int kt = 0; kt < ktiles; kt++) {
        __syncthreads();
        {
            const size_t off = ((size_t)(b * SEQ + kt * 64) * NKVH + kvh) * HDIM;
            const uint4* gkh = (const uint4*)(Kh + off);
            const uint4* gkl = (const uint4*)(Kl + off);
            const uint4* gvh = (const uint4*)(Vh + off);
            const uint4* gvl = (const uint4*)(Vl + off);
            for (int i = tid; i < 1024; i += 256) {
                int r = i >> 4, c = i & 15;
                uint32_t d = r * FP + c * 16;
                size_t gg = (size_t)r * 128 + c;
                *(uint4*)(sm + FKH + d) = gkh[gg];
                *(uint4*)(sm + FKL + d) = gkl[gg];
                *(uint4*)(sm + FVH + d) = gvh[gg];
                *(uint4*)(sm + FVL + d) = gvl[gg];
            }
        }
        __syncthreads();

        float s[8][4];
#pragma unroll
        for (int nt = 0; nt < 8; nt++)
#pragma unroll
            for (int j = 0; j < 4; j++) s[nt][j] = 0.f;

#pragma unroll
        for (int ks = 0; ks < 8; ks++) {
            uint32_t ah[4], al[4];
            uint32_t aa = sb + FQH + (w * 16 + lrow) * FP + (ks * 16 + lk) * 2;
            LDMATRIX_X4(ah[0], ah[1], ah[2], ah[3], aa);
            LDMATRIX_X4(al[0], al[1], al[2], al[3], aa + (FQL - FQH));
#pragma unroll
            for (int p = 0; p < 4; p++) {
                uint32_t bh0, bh1, bh2, bh3, bl0, bl1, bl2, bl3;
                uint32_t ba = sb + FKH + (p * 16 + nrow) * FP + (ks * 16 + kadd) * 2;
                LDMATRIX_X4(bh0, bh1, bh2, bh3, ba);
                LDMATRIX_X4(bl0, bl1, bl2, bl3, ba + (FKL - FKH));
                MMA_BF16(s[2*p],   ah, bh0, bh1);
                MMA_BF16(s[2*p],   al, bh0, bh1);
                MMA_BF16(s[2*p],   ah, bl0, bl1);
                MMA_BF16(s[2*p+1], ah, bh2, bh3);
                MMA_BF16(s[2*p+1], al, bh2, bh3);
                MMA_BF16(s[2*p+1], ah, bl2, bl3);
            }
        }

        if (kt >= 2 * qt) {
            const int colb = kt * 64 + cb;
#pragma unroll
            for (int nt = 0; nt < 8; nt++) {
                int c0 = colb + 8 * nt;
                if (c0 > row0)     s[nt][0] = -1e30f;
                if (c0 + 1 > row0) s[nt][1] = -1e30f;
                if (c0 > row0 + 8)     s[nt][2] = -1e30f;
                if (c0 + 1 > row0 + 8) s[nt][3] = -1e30f;
            }
        }

        float mt0 = -1e30f, mt1 = -1e30f;
#pragma unroll
        for (int nt = 0; nt < 8; nt++) {
            mt0 = fmaxf(mt0, fmaxf(s[nt][0], s[nt][1]));
            mt1 = fmaxf(mt1, fmaxf(s[nt][2], s[nt][3]));
        }
        mt0 = fmaxf(mt0, __shfl_xor_sync(0xffffffffu, mt0, 1));
        mt0 = fmaxf(mt0, __shfl_xor_sync(0xffffffffu, mt0, 2));
        mt1 = fmaxf(mt1, __shfl_xor_sync(0xffffffffu, mt1, 1));
        mt1 = fmaxf(mt1, __shfl_xor_sync(0xffffffffu, mt1, 2));
        float mn0 = fmaxf(m0, mt0), mn1 = fmaxf(m1, mt1);
        float a0 = __expf(m0 - mn0), a1 = __expf(m1 - mn1);
        float ps0 = 0.f, ps1 = 0.f;
#pragma unroll
        for (int nt = 0; nt < 8; nt++) {
            s[nt][0] = __expf(s[nt][0] - mn0);
            s[nt][1] = __expf(s[nt][1] - mn0);
            s[nt][2] = __expf(s[nt][2] - mn1);
            s[nt][3] = __expf(s[nt][3] - mn1);
            ps0 += s[nt][0] + s[nt][1];
            ps1 += s[nt][2] + s[nt][3];
        }
        ps0 += __shfl_xor_sync(0xffffffffu, ps0, 1);
        ps0 += __shfl_xor_sync(0xffffffffu, ps0, 2);
        ps1 += __shfl_xor_sync(0xffffffffu, ps1, 1);
        ps1 += __shfl_xor_sync(0xffffffffu, ps1, 2);
        l0 = l0 * a0 + ps0;  m0 = mn0;
        l1 = l1 * a1 + ps1;  m1 = mn1;
#pragma unroll
        for (int nt = 0; nt < 16; nt++) {
            oacc[nt][0] *= a0; oacc[nt][1] *= a0;
            oacc[nt][2] *= a1; oacc[nt][3] *= a1;
        }

#pragma unroll
        for (int j = 0; j < 4; j++) {
            uint32_t ph[4], pl[4];
            split_pack(s[2*j][0],   s[2*j][1],   ph[0], pl[0]);
            split_pack(s[2*j][2],   s[2*j][3],   ph[1], pl[1]);
            split_pack(s[2*j+1][0], s[2*j+1][1], ph[2], pl[2]);
            split_pack(s[2*j+1][2], s[2*j+1][3], ph[3], pl[3]);
#pragma unroll
            for (int t = 0; t < 8; t++) {
                uint32_t vh0, vh1, vh2, vh3, vl0, vl1, vl2, vl3;
                uint32_t va = sb + FVH + (j * 16 + trow) * FP + (t * 16 + tcol) * 2;
                LDMATRIX_X4_T(vh0, vh1, vh2, vh3, va);
                LDMATRIX_X4_T(vl0, vl1, vl2, vl3, va + (FVL - FVH));
                MMA_BF16(oacc[2*t],   ph, vh0, vh1);
                MMA_BF16(oacc[2*t],   pl, vh0, vh1);
                MMA_BF16(oacc[2*t],   ph, vl0, vl1);
                MMA_BF16(oacc[2*t+1], ph, vh2, vh3);
                MMA_BF16(oacc[2*t+1], pl, vh2, vh3);
                MMA_BF16(oacc[2*t+1], ph, vl2, vl3);
            }
        }
    }

    // epilogue: write split bf16 hi/lo directly (feeds O projection)
    const float inv0 = 1.f / l0, inv1 = 1.f / l1;
    const size_t o0 = ((size_t)(b * SEQ + row0)) * DMODEL + h * HDIM + cb;
    const size_t o1 = ((size_t)(b * SEQ + row0 + 8)) * DMODEL + h * HDIM + cb;
#pragma unroll
    for (int nt = 0; nt < 16; nt++) {
        uint32_t hh, ll;
        split_pack(oacc[nt][0] * inv0, oacc[nt][1] * inv0, hh, ll);
        *(uint32_t*)(Oh + o0 + 8 * nt) = hh;
        *(uint32_t*)(Ol + o0 + 8 * nt) = ll;
        split_pack(oacc[nt][2] * inv1, oacc[nt][3] * inv1, hh, ll);
        *(uint32_t*)(Oh + o1 + 8 * nt) = hh;
        *(uint32_t*)(Ol + o1 + 8 * nt) = ll;
    }
}

// ---------------- host launcher ---------------------------------------------
extern "C" void kernel_launch(void* const* d_in, const int* in_sizes, int n_in,
                              void* d_out, int out_size)
{
    const float* x   = (const float*)d_in[0];
    const float* w_q = (const float*)d_in[1];
    const float* w_k = (const float*)d_in[2];
    const float* w_v = (const float*)d_in[3];
    const float* w_o = (const float*)d_in[4];
    const float* fc  = (const float*)d_in[5];
    const float* fs  = (const float*)d_in[6];
    float* out = (float*)d_out;

    __nv_bfloat16 *xh, *xl, *wqkvh, *wqkvl, *woh, *wol, *ath, *atl;
    __nv_bfloat16 *qsh, *qsl, *ksh, *ksl, *vsh, *vsl;
    cudaGetSymbolAddress((void**)&xh,    g_xh);     cudaGetSymbolAddress((void**)&xl,    g_xl);
    cudaGetSymbolAddress((void**)&wqkvh, g_wqkv_h); cudaGetSymbolAddress((void**)&wqkvl, g_wqkv_l);
    cudaGetSymbolAddress((void**)&woh,   g_wot_h);  cudaGetSymbolAddress((void**)&wol,   g_wot_l);
    cudaGetSymbolAddress((void**)&ath,   g_atth);   cudaGetSymbolAddress((void**)&atl,   g_attl);
    cudaGetSymbolAddress((void**)&qsh,   g_qsh);    cudaGetSymbolAddress((void**)&qsl,   g_qsl);
    cudaGetSymbolAddress((void**)&ksh,   g_ksh);    cudaGetSymbolAddress((void**)&ksl,   g_ksl);
    cudaGetSymbolAddress((void**)&vsh,   g_vsh);    cudaGetSymbolAddress((void**)&vsl,   g_vsl);

    cudaFuncSetAttribute(gemm_mma_kernel, cudaFuncAttributeMaxDynamicSharedMemorySize, GEMM_SMEM);
    cudaFuncSetAttribute(gemm_qkv_kernel, cudaFuncAttributeMaxDynamicSharedMemorySize, GEMM_SMEM);
    cudaFuncSetAttribute(flash_mma_kernel, cudaFuncAttributeMaxDynamicSharedMemorySize, FLASH_SMEM);

    const int M = BATCH * SEQ;  // 4096

    // weight transposes + splits into combined [6144,4096] (q,k,v) and wot
    transpose_split_kernel<<<dim3(DMODEL / 32, DMODEL / 32), 256>>>(
        w_q, wqkvh, wqkvl, DMODEL, DMODEL);
    transpose_split_kernel<<<dim3(NKV / 32, DMODEL / 32), 256>>>(
        w_k, wqkvh + (size_t)DMODEL * DMODEL, wqkvl + (size_t)DMODEL * DMODEL, DMODEL, NKV);
    transpose_split_kernel<<<dim3(NKV / 32, DMODEL / 32), 256>>>(
        w_v, wqkvh + (size_t)(DMODEL + NKV) * DMODEL, wqkvl + (size_t)(DMODEL + NKV) * DMODEL,
        DMODEL, NKV);
    transpose_split_kernel<<<dim3(DMODEL / 32, DMODEL / 32), 256>>>(
        w_o, woh, wol, DMODEL, DMODEL);

    // x split
    {
        int n4 = (M * DMODEL) / 4;
        convert_split_kernel<<<(n4 + 255) / 256, 256>>>(x, xh, xl, n4);
    }

    // fused QKV projection + rope + split (one GEMM over N=6144)
    gemm_qkv_kernel<<<dim3(NQKV / 128, M / 128), 256, GEMM_SMEM>>>(
        xh, xl, wqkvh, wqkvl, fc, fs, qsh, qsl, ksh, ksl, vsh, vsl, DMODEL);

    // flash attention (tensor cores), split bf16 output
    flash_mma_kernel<<<dim3(SEQ / 128, NQH, BATCH), 256, FLASH_SMEM>>>(
        qsh, qsl, ksh, ksl, vsh, vsl, ath, atl);

    // O projection
    gemm_mma_kernel<<<dim3(DMODEL / 128, M / 128), 256, GEMM_SMEM>>>(
        ath, atl, woh, wol, out, M, DMODEL, DMODEL);
}

// round 6
// speedup vs baseline: 2.5662x; 1.0052x over previous
#include <cuda_runtime.h>
#include <cuda_bf16.h>
#include <math.h>
#include <stdint.h>

#define BATCH 2
#define SEQ 2048
#define DMODEL 4096
#define NQH 32
#define NKVH 8
#define HDIM 128
#define NKV (NKVH * HDIM)        // 1024
#define NQKV (DMODEL + 2 * NKV)  // 6144

// ---------------- scratch (device globals; allocation-free) ----------------
__device__ __nv_bfloat16 g_xh[(size_t)BATCH * SEQ * DMODEL];
__device__ __nv_bfloat16 g_xl[(size_t)BATCH * SEQ * DMODEL];
__device__ __nv_bfloat16 g_wqkv_h[(size_t)NQKV * DMODEL];   // [6144,4096] rows: q,k,v
__device__ __nv_bfloat16 g_wqkv_l[(size_t)NQKV * DMODEL];
__device__ __nv_bfloat16 g_wot_h[(size_t)DMODEL * DMODEL];
__device__ __nv_bfloat16 g_wot_l[(size_t)DMODEL * DMODEL];
__device__ __nv_bfloat16 g_atth[(size_t)BATCH * SEQ * DMODEL];
__device__ __nv_bfloat16 g_attl[(size_t)BATCH * SEQ * DMODEL];

__device__ __nv_bfloat16 g_qsh[(size_t)BATCH * SEQ * NQH * HDIM];
__device__ __nv_bfloat16 g_qsl[(size_t)BATCH * SEQ * NQH * HDIM];
__device__ __nv_bfloat16 g_ksh[(size_t)BATCH * SEQ * NKV];
__device__ __nv_bfloat16 g_ksl[(size_t)BATCH * SEQ * NKV];
__device__ __nv_bfloat16 g_vsh[(size_t)BATCH * SEQ * NKV];
__device__ __nv_bfloat16 g_vsl[(size_t)BATCH * SEQ * NKV];

__device__ __forceinline__ uint32_t smem_to_u32(const void* p) {
    uint32_t a;
    asm("{ .reg .u64 t; cvta.to.shared.u64 t, %1; cvt.u32.u64 %0, t; }"
        : "=r"(a) : "l"(p));
    return a;
}

#define CP_ASYNC_16(dst, src) \
    asm volatile("cp.async.cg.shared.global [%0], [%1], 16;" :: "r"(dst), "l"(src) : "memory")
#define CP_COMMIT() asm volatile("cp.async.commit_group;" ::: "memory")
#define CP_WAIT_2()  asm volatile("cp.async.wait_group 2;" ::: "memory")

#define LDMATRIX_X4(r0, r1, r2, r3, addr) \
    asm volatile("ldmatrix.sync.aligned.m8n8.x4.shared.b16 {%0,%1,%2,%3}, [%4];" \
        : "=r"(r0), "=r"(r1), "=r"(r2), "=r"(r3) : "r"(addr))
#define LDMATRIX_X4_T(r0, r1, r2, r3, addr) \
    asm volatile("ldmatrix.sync.aligned.m8n8.x4.trans.shared.b16 {%0,%1,%2,%3}, [%4];" \
        : "=r"(r0), "=r"(r1), "=r"(r2), "=r"(r3) : "r"(addr))

// Non-volatile: all data flow is in constraints, so ptxas may schedule freely.
#define MMA_BF16(d, a, b0, b1) \
    asm("mma.sync.aligned.m16n8k16.row.col.f32.bf16.bf16.f32 " \
        "{%0,%1,%2,%3}, {%4,%5,%6,%7}, {%8,%9}, {%0,%1,%2,%3};" \
        : "+f"((d)[0]), "+f"((d)[1]), "+f"((d)[2]), "+f"((d)[3]) \
        : "r"((a)[0]), "r"((a)[1]), "r"((a)[2]), "r"((a)[3]), "r"(b0), "r"(b1))

__device__ __forceinline__ uint32_t pack2bf(float a, float b) {
    __nv_bfloat162 t = __floats2bfloat162_rn(a, b);
    return *reinterpret_cast<uint32_t*>(&t);
}
__device__ __forceinline__ void split_pack(float a, float b, uint32_t& h, uint32_t& l) {
    __nv_bfloat16 ha = __float2bfloat16(a), hb = __float2bfloat16(b);
    h = pack2bf(__bfloat162float(ha), __bfloat162float(hb));
    l = pack2bf(a - __bfloat162float(ha), b - __bfloat162float(hb));
}

// ---------------- shared GEMM mainloop (device inline) -----------------------
#define TBK 32
#define APITCH 80
#define TILE_B (128 * APITCH)
#define STAGE_B (4 * TILE_B)
#define NSTAGE 4
#define GEMM_SMEM (NSTAGE * STAGE_B)   // 163840

struct GemmCtx {
    float acc[2][8][4];
    int lane, wid, wm, wn, bm, bn;
};

__device__ __forceinline__ void gemm_mainloop(
    GemmCtx& g, char* smem_raw,
    const __nv_bfloat16* __restrict__ Ah, const __nv_bfloat16* __restrict__ Al,
    const __nv_bfloat16* __restrict__ Bh, const __nv_bfloat16* __restrict__ Bl,
    int K)
{
    const uint32_t sbase = smem_to_u32(smem_raw);
    const int tid = threadIdx.x;
    const int lane = g.lane, wm = g.wm, wn = g.wn, bm = g.bm, bn = g.bn;

    const __nv_bfloat16* gsrc[4] = {Ah, Al, Bh, Bl};
    const int rbase4[4] = {bm, bm, bn, bn};

    auto issue_stage = [&](int it, int buf) {
        const int k0 = it * TBK;
#pragma unroll
        for (int t = 0; t < 4; t++) {
            const __nv_bfloat16* gp = gsrc[t] + (size_t)rbase4[t] * K + k0;
            const uint32_t db = sbase + buf * STAGE_B + t * TILE_B;
#pragma unroll
            for (int i = 0; i < 2; i++) {
                int c = tid + i * 256;
                int r = c >> 2, ch = c & 3;
                const void* src = gp + (size_t)r * K + ch * 8;
                uint32_t dst = db + r * APITCH + ch * 16;
                CP_ASYNC_16(dst, src);
            }
        }
        CP_COMMIT();
    };

    const int lrow = (lane & 7) + ((lane >> 3) & 1) * 8;
    const int lk   = (lane >> 4) * 8;
    const int nrow = (lane >> 4) * 8 + (lane & 7);
    const int kadd = ((lane >> 3) & 1) * 8;

#pragma unroll
    for (int mt = 0; mt < 2; mt++)
#pragma unroll
        for (int nt = 0; nt < 8; nt++)
#pragma unroll
            for (int j = 0; j < 4; j++) g.acc[mt][nt][j] = 0.f;

    const int NITER = K / TBK;
    issue_stage(0, 0);
    issue_stage(1, 1);
    issue_stage(2, 2);

    for (int it = 0; it < NITER; it++) {
        CP_WAIT_2();
        __syncthreads();
        if (it + 3 < NITER) issue_stage(it + 3, (it + 3) % NSTAGE);
        else CP_COMMIT();

        const uint32_t base = sbase + (it % NSTAGE) * STAGE_B;
#pragma unroll
        for (int kk = 0; kk < 2; kk++) {
            uint32_t bh[8][2], bl[8][2];
#pragma unroll
            for (int p = 0; p < 4; p++) {
                uint32_t ab = base + 2 * TILE_B +
                              (wn * 64 + p * 16 + nrow) * APITCH + (kk * 16 + kadd) * 2;
                LDMATRIX_X4(bh[2*p][0], bh[2*p][1], bh[2*p+1][0], bh[2*p+1][1], ab);
                ab += TILE_B;
                LDMATRIX_X4(bl[2*p][0], bl[2*p][1], bl[2*p+1][0], bl[2*p+1][1], ab);
            }
            uint32_t ah[2][4], al[2][4];
#pragma unroll
            for (int mt = 0; mt < 2; mt++) {
                uint32_t aa = base + (wm * 32 + mt * 16 + lrow) * APITCH +
                              (kk * 16 + lk) * 2;
                LDMATRIX_X4(ah[mt][0], ah[mt][1], ah[mt][2], ah[mt][3], aa);
                aa += TILE_B;
                LDMATRIX_X4(al[mt][0], al[mt][1], al[mt][2], al[mt][3], aa);
            }
            // term-major issue: all accumulators touched once per pass
#pragma unroll
            for (int mt = 0; mt < 2; mt++)
#pragma unroll
                for (int nt = 0; nt < 8; nt++)
                    MMA_BF16(g.acc[mt][nt], ah[mt], bh[nt][0], bh[nt][1]);
#pragma unroll
            for (int mt = 0; mt < 2; mt++)
#pragma unroll
                for (int nt = 0; nt < 8; nt++)
                    MMA_BF16(g.acc[mt][nt], al[mt], bh[nt][0], bh[nt][1]);
#pragma unroll
            for (int mt = 0; mt < 2; mt++)
#pragma unroll
                for (int nt = 0; nt < 8; nt++)
                    MMA_BF16(g.acc[mt][nt], ah[mt], bl[nt][0], bl[nt][1]);
        }
    }
}

// ---------------- GEMM -> fp32 C (O projection) ------------------------------
__global__ __launch_bounds__(256, 1) void gemm_mma_kernel(
    const __nv_bfloat16* __restrict__ Ah, const __nv_bfloat16* __restrict__ Al,
    const __nv_bfloat16* __restrict__ Bh, const __nv_bfloat16* __restrict__ Bl,
    float* __restrict__ C, int M, int N, int K)
{
    extern __shared__ __align__(128) char smem_raw[];
    GemmCtx g;
    g.lane = threadIdx.x & 31; g.wid = threadIdx.x >> 5;
    g.wm = g.wid & 3; g.wn = g.wid >> 2;
    g.bm = blockIdx.y * 128; g.bn = blockIdx.x * 128;
    gemm_mainloop(g, smem_raw, Ah, Al, Bh, Bl, K);

    const int gr = g.lane >> 2, t2 = (g.lane & 3) * 2;
#pragma unroll
    for (int mt = 0; mt < 2; mt++) {
#pragma unroll
        for (int nt = 0; nt < 8; nt++) {
            int row = g.bm + g.wm * 32 + mt * 16 + gr;
            int col = g.bn + g.wn * 64 + nt * 8 + t2;
            *(float2*)&C[(size_t)row * N + col] =
                make_float2(g.acc[mt][nt][0], g.acc[mt][nt][1]);
            *(float2*)&C[(size_t)(row + 8) * N + col] =
                make_float2(g.acc[mt][nt][2], g.acc[mt][nt][3]);
        }
    }
}

// ---------------- fused QKV GEMM: rope/scale/split epilogue ------------------
__device__ __forceinline__ void rope_split_store(
    __nv_bfloat16* oh, __nv_bfloat16* ol,
    const float* __restrict__ fc, const float* __restrict__ fs,
    int row, int col, float v0, float v1, int stride, int coloff, float scale)
{
    int s = row & (SEQ - 1);
    int i = (col & 127) >> 1;
    float c  = __ldg(fc + s * 64 + i);
    float sn = __ldg(fs + s * 64 + i);
    float ra = (v0 * c - v1 * sn) * scale;
    float rb = (v0 * sn + v1 * c) * scale;
    uint32_t h, l;
    split_pack(ra, rb, h, l);
    size_t o = (size_t)row * stride + (col - coloff);
    *(uint32_t*)(oh + o) = h;
    *(uint32_t*)(ol + o) = l;
}

__global__ __launch_bounds__(256, 1) void gemm_qkv_kernel(
    const __nv_bfloat16* __restrict__ Ah, const __nv_bfloat16* __restrict__ Al,
    const __nv_bfloat16* __restrict__ Bh, const __nv_bfloat16* __restrict__ Bl,
    const float* __restrict__ fc, const float* __restrict__ fs,
    __nv_bfloat16* __restrict__ qh, __nv_bfloat16* __restrict__ ql,
    __nv_bfloat16* __restrict__ kh, __nv_bfloat16* __restrict__ kl,
    __nv_bfloat16* __restrict__ vh, __nv_bfloat16* __restrict__ vl,
    int K)
{
    extern __shared__ __align__(128) char smem_raw[];
    GemmCtx g;
    g.lane = threadIdx.x & 31; g.wid = threadIdx.x >> 5;
    g.wm = g.wid & 3; g.wn = g.wid >> 2;
    g.bm = blockIdx.y * 128; g.bn = blockIdx.x * 128;
    gemm_mainloop(g, smem_raw, Ah, Al, Bh, Bl, K);

    const int gr = g.lane >> 2, t2 = (g.lane & 3) * 2;
    const float qscale = 0.0883883476483184f;  // 1/sqrt(128)

    if (g.bn < DMODEL) {            // Q region: rope + scale + split
#pragma unroll
        for (int mt = 0; mt < 2; mt++)
#pragma unroll
            for (int nt = 0; nt < 8; nt++) {
                int row = g.bm + g.wm * 32 + mt * 16 + gr;
                int col = g.bn + g.wn * 64 + nt * 8 + t2;
                rope_split_store(qh, ql, fc, fs, row, col,
                                 g.acc[mt][nt][0], g.acc[mt][nt][1], DMODEL, 0, qscale);
                rope_split_store(qh, ql, fc, fs, row + 8, col,
                                 g.acc[mt][nt][2], g.acc[mt][nt][3], DMODEL, 0, qscale);
            }
    } else if (g.bn < DMODEL + NKV) {  // K region: rope + split
#pragma unroll
        for (int mt = 0; mt < 2; mt++)
#pragma unroll
            for (int nt = 0; nt < 8; nt++) {
                int row = g.bm + g.wm * 32 + mt * 16 + gr;
                int col = g.bn + g.wn * 64 + nt * 8 + t2;
                rope_split_store(kh, kl, fc, fs, row, col,
                                 g.acc[mt][nt][0], g.acc[mt][nt][1], NKV, DMODEL, 1.0f);
                rope_split_store(kh, kl, fc, fs, row + 8, col,
                                 g.acc[mt][nt][2], g.acc[mt][nt][3], NKV, DMODEL, 1.0f);
            }
    } else {                            // V region: plain split
#pragma unroll
        for (int mt = 0; mt < 2; mt++)
#pragma unroll
            for (int nt = 0; nt < 8; nt++) {
                int row = g.bm + g.wm * 32 + mt * 16 + gr;
                int col = g.bn + g.wn * 64 + nt * 8 + t2 - (DMODEL + NKV);
                uint32_t h, l;
                size_t o0 = (size_t)row * NKV + col;
                split_pack(g.acc[mt][nt][0], g.acc[mt][nt][1], h, l);
                *(uint32_t*)(vh + o0) = h; *(uint32_t*)(vl + o0) = l;
                size_t o1 = o0 + (size_t)8 * NKV;
                split_pack(g.acc[mt][nt][2], g.acc[mt][nt][3], h, l);
                *(uint32_t*)(vh + o1) = h; *(uint32_t*)(vl + o1) = l;
            }
    }
}

// ---------------- fp32 -> bf16 hi/lo split (x only) --------------------------
__global__ __launch_bounds__(256) void convert_split_kernel(
    const float* __restrict__ in, __nv_bfloat16* __restrict__ oh,
    __nv_bfloat16* __restrict__ ol, int n4)
{
    int i = blockIdx.x * blockDim.x + threadIdx.x;
    if (i >= n4) return;
    float4 v = ((const float4*)in)[i];
    uint32_t h0, l0, h1, l1;
    split_pack(v.x, v.y, h0, l0);
    split_pack(v.z, v.w, h1, l1);
    ((uint2*)oh)[i] = make_uint2(h0, h1);
    ((uint2*)ol)[i] = make_uint2(l0, l1);
}

// ---------------- fp32 [K,N] -> transposed bf16 hi/lo [N,K] ------------------
__global__ __launch_bounds__(256) void transpose_split_kernel(
    const float* __restrict__ in, __nv_bfloat16* __restrict__ oh,
    __nv_bfloat16* __restrict__ ol, int K, int N)
{
    __shared__ float tile[32][33];
    const int k0 = blockIdx.y * 32, n0 = blockIdx.x * 32;
    const int tx = threadIdx.x & 31, ty = threadIdx.x >> 5;
#pragma unroll
    for (int i = 0; i < 32; i += 8)
        tile[ty + i][tx] = in[(size_t)(k0 + ty + i) * N + n0 + tx];
    __syncthreads();
#pragma unroll
    for (int i = 0; i < 32; i += 8) {
        float v = tile[tx][ty + i];
        __nv_bfloat16 h = __float2bfloat16(v);
        float l = v - __bfloat162float(h);
        size_t o = (size_t)(n0 + ty + i) * K + k0 + tx;
        oh[o] = h;
        ol[o] = __float2bfloat16(l);
    }
}

// ---------------- flash attention via mma.sync (split bf16) ------------------
#define FP 272
#define FQH 0
#define FQL 34816
#define FKH 69632
#define FKL 87040
#define FVH 104448
#define FVL 121856
#define FLASH_SMEM 139264

__global__ __launch_bounds__(256, 1) void flash_mma_kernel(
    const __nv_bfloat16* __restrict__ Qh, const __nv_bfloat16* __restrict__ Ql,
    const __nv_bfloat16* __restrict__ Kh, const __nv_bfloat16* __restrict__ Kl,
    const __nv_bfloat16* __restrict__ Vh, const __nv_bfloat16* __restrict__ Vl,
    __nv_bfloat16* __restrict__ Oh, __nv_bfloat16* __restrict__ Ol)
{
    extern __shared__ __align__(128) char sm[];
    const uint32_t sb = smem_to_u32(sm);
    const int qt = blockIdx.x, h = blockIdx.y, b = blockIdx.z;
    const int kvh = h >> 2;
    const int tid = threadIdx.x, lane = tid & 31, w = tid >> 5;
    const int q0 = qt * 128;

    const int lrow = (lane & 7) + ((lane >> 3) & 1) * 8;
    const int lk   = (lane >> 4) * 8;
    const int nrow = (lane >> 4) * 8 + (lane & 7);
    const int kadd = ((lane >> 3) & 1) * 8;
    const int trow = lane & 15;
    const int tcol = (lane >> 4) * 8;

    {
        const size_t qoff = ((size_t)(b * SEQ + q0) * NQH + h) * HDIM;
        const uint4* gh = (const uint4*)(Qh + qoff);
        const uint4* gl = (const uint4*)(Ql + qoff);
        for (int i = tid; i < 2048; i += 256) {
            int r = i >> 4, c = i & 15;
            *(uint4*)(sm + FQH + r * FP + c * 16) = gh[(size_t)r * 512 + c];
            *(uint4*)(sm + FQL + r * FP + c * 16) = gl[(size_t)r * 512 + c];
        }
    }

    float m0 = -1e30f, m1 = -1e30f, l0 = 0.f, l1 = 0.f;
    float oacc[16][4];
#pragma unroll
    for (int nt = 0; nt < 16; nt++)
#pragma unroll
        for (int j = 0; j < 4; j++) oacc[nt][j] = 0.f;

    const int row0 = q0 + w * 16 + (lane >> 2);
    const int cb   = 2 * (lane & 3);
    const int ktiles = 2 * qt + 2;

    for (int kt = 0; kt < ktiles; kt++) {
        __syncthreads();
        {
            const size_t off = ((size_t)(b * SEQ + kt * 64) * NKVH + kvh) * HDIM;
            const uint4* gkh = (const uint4*)(Kh + off);
            const uint4* gkl = (const uint4*)(Kl + off);
            const uint4* gvh = (const uint4*)(Vh + off);
            const uint4* gvl = (const uint4*)(Vl + off);
            for (int i = tid; i < 1024; i += 256) {
                int r = i >> 4, c = i & 15;
                uint32_t d = r * FP + c * 16;
                size_t gg = (size_t)r * 128 + c;
                *(uint4*)(sm + FKH + d) = gkh[gg];
                *(uint4*)(sm + FKL + d) = gkl[gg];
                *(uint4*)(sm + FVH + d) = gvh[gg];
                *(uint4*)(sm + FVL + d) = gvl[gg];
            }
        }
        __syncthreads();

        float s[8][4];
#pragma unroll
        for (int nt = 0; nt < 8; nt++)
#pragma unroll
            for (int j = 0; j < 4; j++) s[nt][j] = 0.f;

#pragma unroll
        for (int ks = 0; ks < 8; ks++) {
            uint32_t ah[4], al[4];
            uint32_t aa = sb + FQH + (w * 16 + lrow) * FP + (ks * 16 + lk) * 2;
            LDMATRIX_X4(ah[0], ah[1], ah[2], ah[3], aa);
            LDMATRIX_X4(al[0], al[1], al[2], al[3], aa + (FQL - FQH));
            uint32_t bh[8][2], bl[8][2];
#pragma unroll
            for (int p = 0; p < 4; p++) {
                uint32_t ba = sb + FKH + (p * 16 + nrow) * FP + (ks * 16 + kadd) * 2;
                LDMATRIX_X4(bh[2*p][0], bh[2*p][1], bh[2*p+1][0], bh[2*p+1][1], ba);
                LDMATRIX_X4(bl[2*p][0], bl[2*p][1], bl[2*p+1][0], bl[2*p+1][1],
                            ba + (FKL - FKH));
            }
            // term-major issue
#pragma unroll
            for (int nt = 0; nt < 8; nt++) MMA_BF16(s[nt], ah, bh[nt][0], bh[nt][1]);
#pragma unroll
            for (int nt = 0; nt < 8; nt++) MMA_BF16(s[nt], al, bh[nt][0], bh[nt][1]);
#pragma unroll
            for (int nt = 0; nt < 8; nt++) MMA_BF16(s[nt], ah, bl[nt][0], bl[nt][1]);
        }

        if (kt >= 2 * qt) {
            const int colb = kt * 64 + cb;
#pragma unroll
            for (int nt = 0; nt < 8; nt++) {
                int c0 = colb + 8 * nt;
                if (c0 > row0)     s[nt][0] = -1e30f;
                if (c0 + 1 > row0) s[nt][1] = -1e30f;
                if (c0 > row0 + 8)     s[nt][2] = -1e30f;
                if (c0 + 1 > row0 + 8) s[nt][3] = -1e30f;
            }
        }

        float mt0 = -1e30f, mt1 = -1e30f;
#pragma unroll
        for (int nt = 0; nt < 8; nt++) {
            mt0 = fmaxf(mt0, fmaxf(s[nt][0], s[nt][1]));
            mt1 = fmaxf(mt1, fmaxf(s[nt][2], s[nt][3]));
        }
        mt0 = fmaxf(mt0, __shfl_xor_sync(0xffffffffu, mt0, 1));
        mt0 = fmaxf(mt0, __shfl_xor_sync(0xffffffffu, mt0, 2));
        mt1 = fmaxf(mt1, __shfl_xor_sync(0xffffffffu, mt1, 1));
        mt1 = fmaxf(mt1, __shfl_xor_sync(0xffffffffu, mt1, 2));
        float mn0 = fmaxf(m0, mt0), mn1 = fmaxf(m1, mt1);
        float a0 = __expf(m0 - mn0), a1 = __expf(m1 - mn1);
        float ps0 = 0.f, ps1 = 0.f;
#pragma unroll
        for (int nt = 0; nt < 8; nt++) {
            s[nt][0] = __expf(s[nt][0] - mn0);
            s[nt][1] = __expf(s[nt][1] - mn0);
            s[nt][2] = __expf(s[nt][2] - mn1);
            s[nt][3] = __expf(s[nt][3] - mn1);
            ps0 += s[nt][0] + s[nt][1];
            ps1 += s[nt][2] + s[nt][3];
        }
        ps0 += __shfl_xor_sync(0xffffffffu, ps0, 1);
        ps0 += __shfl_xor_sync(0xffffffffu, ps0, 2);
        ps1 += __shfl_xor_sync(0xffffffffu, ps1, 1);
        ps1 += __shfl_xor_sync(0xffffffffu, ps1, 2);
        l0 = l0 * a0 + ps0;  m0 = mn0;
        l1 = l1 * a1 + ps1;  m1 = mn1;
#pragma unroll
        for (int nt = 0; nt < 16; nt++) {
            oacc[nt][0] *= a0; oacc[nt][1] *= a0;
            oacc[nt][2] *= a1; oacc[nt][3] *= a1;
        }

        // O += Ph*Vh + Pl*Vh + Ph*Vl  (term-major)
#pragma unroll
        for (int j = 0; j < 4; j++) {
            uint32_t ph[4], pl[4];
            split_pack(s[2*j][0],   s[2*j][1],   ph[0], pl[0]);
            split_pack(s[2*j][2],   s[2*j][3],   ph[1], pl[1]);
            split_pack(s[2*j+1][0], s[2*j+1][1], ph[2], pl[2]);
            split_pack(s[2*j+1][2], s[2*j+1][3], ph[3], pl[3]);
            uint32_t vfh[8][4], vfl[8][4];
#pragma unroll
            for (int t = 0; t < 8; t++) {
                uint32_t va = sb + FVH + (j * 16 + trow) * FP + (t * 16 + tcol) * 2;
                LDMATRIX_X4_T(vfh[t][0], vfh[t][1], vfh[t][2], vfh[t][3], va);
                LDMATRIX_X4_T(vfl[t][0], vfl[t][1], vfl[t][2], vfl[t][3],
                              va + (FVL - FVH));
            }
#pragma unroll
            for (int t = 0; t < 8; t++) {
                MMA_BF16(oacc[2*t],   ph, vfh[t][0], vfh[t][1]);
                MMA_BF16(oacc[2*t+1], ph, vfh[t][2], vfh[t][3]);
            }
#pragma unroll
            for (int t = 0; t < 8; t++) {
                MMA_BF16(oacc[2*t],   pl, vfh[t][0], vfh[t][1]);
                MMA_BF16(oacc[2*t+1], pl, vfh[t][2], vfh[t][3]);
            }
#pragma unroll
            for (int t = 0; t < 8; t++) {
                MMA_BF16(oacc[2*t],   ph, vfl[t][0], vfl[t][1]);
                MMA_BF16(oacc[2*t+1], ph, vfl[t][2], vfl[t][3]);
            }
        }
    }

    // epilogue: write split bf16 hi/lo directly (feeds O projection)
    const float inv0 = 1.f / l0, inv1 = 1.f / l1;
    const size_t o0 = ((size_t)(b * SEQ + row0)) * DMODEL + h * HDIM + cb;
    const size_t o1 = ((size_t)(b * SEQ + row0 + 8)) * DMODEL + h * HDIM + cb;
#pragma unroll
    for (int nt = 0; nt < 16; nt++) {
        uint32_t hh, ll;
        split_pack(oacc[nt][0] * inv0, oacc[nt][1] * inv0, hh, ll);
        *(uint32_t*)(Oh + o0 + 8 * nt) = hh;
        *(uint32_t*)(Ol + o0 + 8 * nt) = ll;
        split_pack(oacc[nt][2] * inv1, oacc[nt][3] * inv1, hh, ll);
        *(uint32_t*)(Oh + o1 + 8 * nt) = hh;
        *(uint32_t*)(Ol + o1 + 8 * nt) = ll;
    }
}

// ---------------- host launcher ---------------------------------------------
extern "C" void kernel_launch(void* const* d_in, const int* in_sizes, int n_in,
                              void* d_out, int out_size)
{
    const float* x   = (const float*)d_in[0];
    const float* w_q = (const float*)d_in[1];
    const float* w_k = (const float*)d_in[2];
    const float* w_v = (const float*)d_in[3];
    const float* w_o = (const float*)d_in[4];
    const float* fc  = (const float*)d_in[5];
    const float* fs  = (const float*)d_in[6];
    float* out = (float*)d_out;

    __nv_bfloat16 *xh, *xl, *wqkvh, *wqkvl, *woh, *wol, *ath, *atl;
    __nv_bfloat16 *qsh, *qsl, *ksh, *ksl, *vsh, *vsl;
    cudaGetSymbolAddress((void**)&xh,    g_xh);     cudaGetSymbolAddress((void**)&xl,    g_xl);
    cudaGetSymbolAddress((void**)&wqkvh, g_wqkv_h); cudaGetSymbolAddress((void**)&wqkvl, g_wqkv_l);
    cudaGetSymbolAddress((void**)&woh,   g_wot_h);  cudaGetSymbolAddress((void**)&wol,   g_wot_l);
    cudaGetSymbolAddress((void**)&ath,   g_atth);   cudaGetSymbolAddress((void**)&atl,   g_attl);
    cudaGetSymbolAddress((void**)&qsh,   g_qsh);    cudaGetSymbolAddress((void**)&qsl,   g_qsl);
    cudaGetSymbolAddress((void**)&ksh,   g_ksh);    cudaGetSymbolAddress((void**)&ksl,   g_ksl);
    cudaGetSymbolAddress((void**)&vsh,   g_vsh);    cudaGetSymbolAddress((void**)&vsl,   g_vsl);

    cudaFuncSetAttribute(gemm_mma_kernel, cudaFuncAttributeMaxDynamicSharedMemorySize, GEMM_SMEM);
    cudaFuncSetAttribute(gemm_qkv_kernel, cudaFuncAttributeMaxDynamicSharedMemorySize, GEMM_SMEM);
    cudaFuncSetAttribute(flash_mma_kernel, cudaFuncAttributeMaxDynamicSharedMemorySize, FLASH_SMEM);

    const int M = BATCH * SEQ;  // 4096

    // weight transposes + splits into combined [6144,4096] (q,k,v) and wot
    transpose_split_kernel<<<dim3(DMODEL / 32, DMODEL / 32), 256>>>(
        w_q, wqkvh, wqkvl, DMODEL, DMODEL);
    transpose_split_kernel<<<dim3(NKV / 32, DMODEL / 32), 256>>>(
        w_k, wqkvh + (size_t)DMODEL * DMODEL, wqkvl + (size_t)DMODEL * DMODEL, DMODEL, NKV);
    transpose_split_kernel<<<dim3(NKV / 32, DMODEL / 32), 256>>>(
        w_v, wqkvh + (size_t)(DMODEL + NKV) * DMODEL, wqkvl + (size_t)(DMODEL + NKV) * DMODEL,
        DMODEL, NKV);
    transpose_split_kernel<<<dim3(DMODEL / 32, DMODEL / 32), 256>>>(
        w_o, woh, wol, DMODEL, DMODEL);

    // x split
    {
        int n4 = (M * DMODEL) / 4;
        convert_split_kernel<<<(n4 + 255) / 256, 256>>>(x, xh, xl, n4);
    }

    // fused QKV projection + rope + split (one GEMM over N=6144)
    gemm_qkv_kernel<<<dim3(NQKV / 128, M / 128), 256, GEMM_SMEM>>>(
        xh, xl, wqkvh, wqkvl, fc, fs, qsh, qsl, ksh, ksl, vsh, vsl, DMODEL);

    // flash attention (tensor cores), split bf16 output
    flash_mma_kernel<<<dim3(SEQ / 128, NQH, BATCH), 256, FLASH_SMEM>>>(
        qsh, qsl, ksh, ksl, vsh, vsl, ath, atl);

    // O projection
    gemm_mma_kernel<<<dim3(DMODEL / 128, M / 128), 256, GEMM_SMEM>>>(
        ath, atl, woh, wol, out, M, DMODEL, DMODEL);
}

// round 7
// speedup vs baseline: 2.9141x; 1.1356x over previous
#include <cuda_runtime.h>
#include <cuda_bf16.h>
#include <math.h>
#include <stdint.h>

#define BATCH 2
#define SEQ 2048
#define DMODEL 4096
#define NQH 32
#define NKVH 8
#define HDIM 128
#define NKV (NKVH * HDIM)        // 1024
#define NQKV (DMODEL + 2 * NKV)  // 6144

// ---------------- scratch (device globals; allocation-free) ----------------
__device__ __nv_bfloat16 g_xh[(size_t)BATCH * SEQ * DMODEL];
__device__ __nv_bfloat16 g_xl[(size_t)BATCH * SEQ * DMODEL];
__device__ __nv_bfloat16 g_wqkv_h[(size_t)NQKV * DMODEL];   // [6144,4096] rows: q,k,v
__device__ __nv_bfloat16 g_wqkv_l[(size_t)NQKV * DMODEL];
__device__ __nv_bfloat16 g_wot_h[(size_t)DMODEL * DMODEL];
__device__ __nv_bfloat16 g_wot_l[(size_t)DMODEL * DMODEL];
__device__ __nv_bfloat16 g_atth[(size_t)BATCH * SEQ * DMODEL];
__device__ __nv_bfloat16 g_attl[(size_t)BATCH * SEQ * DMODEL];

__device__ __nv_bfloat16 g_qsh[(size_t)BATCH * SEQ * NQH * HDIM];
__device__ __nv_bfloat16 g_qsl[(size_t)BATCH * SEQ * NQH * HDIM];
__device__ __nv_bfloat16 g_ksh[(size_t)BATCH * SEQ * NKV];
__device__ __nv_bfloat16 g_ksl[(size_t)BATCH * SEQ * NKV];
__device__ __nv_bfloat16 g_vsh[(size_t)BATCH * SEQ * NKV];
__device__ __nv_bfloat16 g_vsl[(size_t)BATCH * SEQ * NKV];

__device__ __forceinline__ uint32_t smem_to_u32(const void* p) {
    uint32_t a;
    asm("{ .reg .u64 t; cvta.to.shared.u64 t, %1; cvt.u32.u64 %0, t; }"
        : "=r"(a) : "l"(p));
    return a;
}

#define CP_ASYNC_16(dst, src) \
    asm volatile("cp.async.cg.shared.global [%0], [%1], 16;" :: "r"(dst), "l"(src) : "memory")
#define CP_COMMIT() asm volatile("cp.async.commit_group;" ::: "memory")
#define CP_WAIT_0()  asm volatile("cp.async.wait_group 0;" ::: "memory")

#define LDMATRIX_X4(r0, r1, r2, r3, addr) \
    asm volatile("ldmatrix.sync.aligned.m8n8.x4.shared.b16 {%0,%1,%2,%3}, [%4];" \
        : "=r"(r0), "=r"(r1), "=r"(r2), "=r"(r3) : "r"(addr))
#define LDMATRIX_X4_T(r0, r1, r2, r3, addr) \
    asm volatile("ldmatrix.sync.aligned.m8n8.x4.trans.shared.b16 {%0,%1,%2,%3}, [%4];" \
        : "=r"(r0), "=r"(r1), "=r"(r2), "=r"(r3) : "r"(addr))

#define MMA_BF16(d, a, b0, b1) \
    asm("mma.sync.aligned.m16n8k16.row.col.f32.bf16.bf16.f32 " \
        "{%0,%1,%2,%3}, {%4,%5,%6,%7}, {%8,%9}, {%0,%1,%2,%3};" \
        : "+f"((d)[0]), "+f"((d)[1]), "+f"((d)[2]), "+f"((d)[3]) \
        : "r"((a)[0]), "r"((a)[1]), "r"((a)[2]), "r"((a)[3]), "r"(b0), "r"(b1))

__device__ __forceinline__ uint32_t pack2bf(float a, float b) {
    __nv_bfloat162 t = __floats2bfloat162_rn(a, b);
    return *reinterpret_cast<uint32_t*>(&t);
}
__device__ __forceinline__ void split_pack(float a, float b, uint32_t& h, uint32_t& l) {
    __nv_bfloat16 ha = __float2bfloat16(a), hb = __float2bfloat16(b);
    h = pack2bf(__bfloat162float(ha), __bfloat162float(hb));
    l = pack2bf(a - __bfloat162float(ha), b - __bfloat162float(hb));
}

// ---------------- shared GEMM mainloop (device inline) -----------------------
// TBK=64, 2 stages, padded pitch 144B (9x16B, ldmatrix conflict-free).
#define TBK 64
#define APITCH 144
#define TILE_B (128 * APITCH)          // 18432
#define STAGE_B (4 * TILE_B)           // 73728
#define GEMM_SMEM (2 * STAGE_B)        // 147456

struct GemmCtx {
    float acc[2][8][4];
    int lane, wid, wm, wn, bm, bn;
};

__device__ __forceinline__ void gemm_mainloop(
    GemmCtx& g, char* smem_raw,
    const __nv_bfloat16* __restrict__ Ah, const __nv_bfloat16* __restrict__ Al,
    const __nv_bfloat16* __restrict__ Bh, const __nv_bfloat16* __restrict__ Bl,
    int K)
{
    const uint32_t sbase = smem_to_u32(smem_raw);
    const int tid = threadIdx.x;
    const int lane = g.lane, wm = g.wm, wn = g.wn, bm = g.bm, bn = g.bn;

    const __nv_bfloat16* gsrc[4] = {Ah, Al, Bh, Bl};
    const int rbase4[4] = {bm, bm, bn, bn};

    auto issue_stage = [&](int it, int buf) {
        const int k0 = it * TBK;
#pragma unroll
        for (int t = 0; t < 4; t++) {
            const __nv_bfloat16* gp = gsrc[t] + (size_t)rbase4[t] * K + k0;
            const uint32_t db = sbase + buf * STAGE_B + t * TILE_B;
#pragma unroll
            for (int i = 0; i < 4; i++) {
                int c = i * 256 + tid;          // 1024 chunks of 16B per tile
                int r = c >> 3, ch = c & 7;
                const void* src = gp + (size_t)r * K + ch * 8;
                uint32_t dst = db + r * APITCH + ch * 16;
                CP_ASYNC_16(dst, src);
            }
        }
        CP_COMMIT();
    };

    const int lrow = (lane & 7) + ((lane >> 3) & 1) * 8;
    const int lk   = (lane >> 4) * 8;
    const int nrow = (lane >> 4) * 8 + (lane & 7);
    const int kadd = ((lane >> 3) & 1) * 8;

    // frag loader for one k16 quarter
    auto load_q = [&](uint32_t base, int kk,
                      uint32_t a_h[2][4], uint32_t a_l[2][4],
                      uint32_t b_h[8][2], uint32_t b_l[8][2]) {
#pragma unroll
        for (int p = 0; p < 4; p++) {
            uint32_t ab = base + 2 * TILE_B +
                          (wn * 64 + p * 16 + nrow) * APITCH + (kk * 16 + kadd) * 2;
            LDMATRIX_X4(b_h[2*p][0], b_h[2*p][1], b_h[2*p+1][0], b_h[2*p+1][1], ab);
            LDMATRIX_X4(b_l[2*p][0], b_l[2*p][1], b_l[2*p+1][0], b_l[2*p+1][1],
                        ab + TILE_B);
        }
#pragma unroll
        for (int mt = 0; mt < 2; mt++) {
            uint32_t aa = base + (wm * 32 + mt * 16 + lrow) * APITCH +
                          (kk * 16 + lk) * 2;
            LDMATRIX_X4(a_h[mt][0], a_h[mt][1], a_h[mt][2], a_h[mt][3], aa);
            LDMATRIX_X4(a_l[mt][0], a_l[mt][1], a_l[mt][2], a_l[mt][3],
                        aa + TILE_B);
        }
    };

#pragma unroll
    for (int mt = 0; mt < 2; mt++)
#pragma unroll
        for (int nt = 0; nt < 8; nt++)
#pragma unroll
            for (int j = 0; j < 4; j++) g.acc[mt][nt][j] = 0.f;

    const int NITER = K / TBK;
    issue_stage(0, 0);

    for (int it = 0; it < NITER; it++) {
        CP_WAIT_0();
        __syncthreads();
        if (it + 1 < NITER) issue_stage(it + 1, (it + 1) & 1);
        const uint32_t base = sbase + (it & 1) * STAGE_B;

        uint32_t ah[2][2][4], al[2][2][4], bh[2][8][2], bl[2][8][2];
        load_q(base, 0, ah[0], al[0], bh[0], bl[0]);
#pragma unroll
        for (int kk = 0; kk < 4; kk++) {
            const int cur = kk & 1, nxt = cur ^ 1;
            if (kk < 3) load_q(base, kk + 1, ah[nxt], al[nxt], bh[nxt], bl[nxt]);
            // term-major passes over buffer `cur`
#pragma unroll
            for (int mt = 0; mt < 2; mt++)
#pragma unroll
                for (int nt = 0; nt < 8; nt++)
                    MMA_BF16(g.acc[mt][nt], ah[cur][mt], bh[cur][nt][0], bh[cur][nt][1]);
#pragma unroll
            for (int mt = 0; mt < 2; mt++)
#pragma unroll
                for (int nt = 0; nt < 8; nt++)
                    MMA_BF16(g.acc[mt][nt], al[cur][mt], bh[cur][nt][0], bh[cur][nt][1]);
#pragma unroll
            for (int mt = 0; mt < 2; mt++)
#pragma unroll
                for (int nt = 0; nt < 8; nt++)
                    MMA_BF16(g.acc[mt][nt], ah[cur][mt], bl[cur][nt][0], bl[cur][nt][1]);
        }
        __syncthreads();  // protect stage buffer before next overwrite
    }
}

// ---------------- GEMM -> fp32 C (O projection) ------------------------------
__global__ __launch_bounds__(256, 1) void gemm_mma_kernel(
    const __nv_bfloat16* __restrict__ Ah, const __nv_bfloat16* __restrict__ Al,
    const __nv_bfloat16* __restrict__ Bh, const __nv_bfloat16* __restrict__ Bl,
    float* __restrict__ C, int M, int N, int K)
{
    extern __shared__ __align__(128) char smem_raw[];
    GemmCtx g;
    g.lane = threadIdx.x & 31; g.wid = threadIdx.x >> 5;
    g.wm = g.wid & 3; g.wn = g.wid >> 2;
    g.bm = blockIdx.y * 128; g.bn = blockIdx.x * 128;
    gemm_mainloop(g, smem_raw, Ah, Al, Bh, Bl, K);

    const int gr = g.lane >> 2, t2 = (g.lane & 3) * 2;
#pragma unroll
    for (int mt = 0; mt < 2; mt++) {
#pragma unroll
        for (int nt = 0; nt < 8; nt++) {
            int row = g.bm + g.wm * 32 + mt * 16 + gr;
            int col = g.bn + g.wn * 64 + nt * 8 + t2;
            *(float2*)&C[(size_t)row * N + col] =
                make_float2(g.acc[mt][nt][0], g.acc[mt][nt][1]);
            *(float2*)&C[(size_t)(row + 8) * N + col] =
                make_float2(g.acc[mt][nt][2], g.acc[mt][nt][3]);
        }
    }
}

// ---------------- fused QKV GEMM: rope/scale/split epilogue ------------------
__device__ __forceinline__ void rope_split_store(
    __nv_bfloat16* oh, __nv_bfloat16* ol,
    const float* __restrict__ fc, const float* __restrict__ fs,
    int row, int col, float v0, float v1, int stride, int coloff, float scale)
{
    int s = row & (SEQ - 1);
    int i = (col & 127) >> 1;
    float c  = __ldg(fc + s * 64 + i);
    float sn = __ldg(fs + s * 64 + i);
    float ra = (v0 * c - v1 * sn) * scale;
    float rb = (v0 * sn + v1 * c) * scale;
    uint32_t h, l;
    split_pack(ra, rb, h, l);
    size_t o = (size_t)row * stride + (col - coloff);
    *(uint32_t*)(oh + o) = h;
    *(uint32_t*)(ol + o) = l;
}

__global__ __launch_bounds__(256, 1) void gemm_qkv_kernel(
    const __nv_bfloat16* __restrict__ Ah, const __nv_bfloat16* __restrict__ Al,
    const __nv_bfloat16* __restrict__ Bh, const __nv_bfloat16* __restrict__ Bl,
    const float* __restrict__ fc, const float* __restrict__ fs,
    __nv_bfloat16* __restrict__ qh, __nv_bfloat16* __restrict__ ql,
    __nv_bfloat16* __restrict__ kh, __nv_bfloat16* __restrict__ kl,
    __nv_bfloat16* __restrict__ vh, __nv_bfloat16* __restrict__ vl,
    int K)
{
    extern __shared__ __align__(128) char smem_raw[];
    GemmCtx g;
    g.lane = threadIdx.x & 31; g.wid = threadIdx.x >> 5;
    g.wm = g.wid & 3; g.wn = g.wid >> 2;
    g.bm = blockIdx.y * 128; g.bn = blockIdx.x * 128;
    gemm_mainloop(g, smem_raw, Ah, Al, Bh, Bl, K);

    const int gr = g.lane >> 2, t2 = (g.lane & 3) * 2;
    const float qscale = 0.0883883476483184f;  // 1/sqrt(128)

    if (g.bn < DMODEL) {
#pragma unroll
        for (int mt = 0; mt < 2; mt++)
#pragma unroll
            for (int nt = 0; nt < 8; nt++) {
                int row = g.bm + g.wm * 32 + mt * 16 + gr;
                int col = g.bn + g.wn * 64 + nt * 8 + t2;
                rope_split_store(qh, ql, fc, fs, row, col,
                                 g.acc[mt][nt][0], g.acc[mt][nt][1], DMODEL, 0, qscale);
                rope_split_store(qh, ql, fc, fs, row + 8, col,
                                 g.acc[mt][nt][2], g.acc[mt][nt][3], DMODEL, 0, qscale);
            }
    } else if (g.bn < DMODEL + NKV) {
#pragma unroll
        for (int mt = 0; mt < 2; mt++)
#pragma unroll
            for (int nt = 0; nt < 8; nt++) {
                int row = g.bm + g.wm * 32 + mt * 16 + gr;
                int col = g.bn + g.wn * 64 + nt * 8 + t2;
                rope_split_store(kh, kl, fc, fs, row, col,
                                 g.acc[mt][nt][0], g.acc[mt][nt][1], NKV, DMODEL, 1.0f);
                rope_split_store(kh, kl, fc, fs, row + 8, col,
                                 g.acc[mt][nt][2], g.acc[mt][nt][3], NKV, DMODEL, 1.0f);
            }
    } else {
#pragma unroll
        for (int mt = 0; mt < 2; mt++)
#pragma unroll
            for (int nt = 0; nt < 8; nt++) {
                int row = g.bm + g.wm * 32 + mt * 16 + gr;
                int col = g.bn + g.wn * 64 + nt * 8 + t2 - (DMODEL + NKV);
                uint32_t h, l;
                size_t o0 = (size_t)row * NKV + col;
                split_pack(g.acc[mt][nt][0], g.acc[mt][nt][1], h, l);
                *(uint32_t*)(vh + o0) = h; *(uint32_t*)(vl + o0) = l;
                size_t o1 = o0 + (size_t)8 * NKV;
                split_pack(g.acc[mt][nt][2], g.acc[mt][nt][3], h, l);
                *(uint32_t*)(vh + o1) = h; *(uint32_t*)(vl + o1) = l;
            }
    }
}

// ---------------- fp32 -> bf16 hi/lo split (x only) --------------------------
__global__ __launch_bounds__(256) void convert_split_kernel(
    const float* __restrict__ in, __nv_bfloat16* __restrict__ oh,
    __nv_bfloat16* __restrict__ ol, int n4)
{
    int i = blockIdx.x * blockDim.x + threadIdx.x;
    if (i >= n4) return;
    float4 v = ((const float4*)in)[i];
    uint32_t h0, l0, h1, l1;
    split_pack(v.x, v.y, h0, l0);
    split_pack(v.z, v.w, h1, l1);
    ((uint2*)oh)[i] = make_uint2(h0, h1);
    ((uint2*)ol)[i] = make_uint2(l0, l1);
}

// ---------------- fp32 [K,N] -> transposed bf16 hi/lo [N,K] ------------------
__global__ __launch_bounds__(256) void transpose_split_kernel(
    const float* __restrict__ in, __nv_bfloat16* __restrict__ oh,
    __nv_bfloat16* __restrict__ ol, int K, int N)
{
    __shared__ float tile[32][33];
    const int k0 = blockIdx.y * 32, n0 = blockIdx.x * 32;
    const int tx = threadIdx.x & 31, ty = threadIdx.x >> 5;
#pragma unroll
    for (int i = 0; i < 32; i += 8)
        tile[ty + i][tx] = in[(size_t)(k0 + ty + i) * N + n0 + tx];
    __syncthreads();
#pragma unroll
    for (int i = 0; i < 32; i += 8) {
        float v = tile[tx][ty + i];
        __nv_bfloat16 h = __float2bfloat16(v);
        float l = v - __bfloat162float(h);
        size_t o = (size_t)(n0 + ty + i) * K + k0 + tx;
        oh[o] = h;
        ol[o] = __float2bfloat16(l);
    }
}

// ---------------- flash attention via mma.sync (split bf16) ------------------
// BM=64 q rows / CTA, 4 warps x 16 rows, 2 CTAs per SM.
#define FP 272
#define FQH 0
#define FQL 17408
#define FKH 34816
#define FKL 52224
#define FVH 69632
#define FVL 87040
#define FLASH_SMEM 104448

__global__ __launch_bounds__(128, 2) void flash_mma_kernel(
    const __nv_bfloat16* __restrict__ Qh, const __nv_bfloat16* __restrict__ Ql,
    const __nv_bfloat16* __restrict__ Kh, const __nv_bfloat16* __restrict__ Kl,
    const __nv_bfloat16* __restrict__ Vh, const __nv_bfloat16* __restrict__ Vl,
    __nv_bfloat16* __restrict__ Oh, __nv_bfloat16* __restrict__ Ol)
{
    extern __shared__ __align__(128) char sm[];
    const uint32_t sb = smem_to_u32(sm);
    const int qt = blockIdx.x, h = blockIdx.y, b = blockIdx.z;
    const int kvh = h >> 2;
    const int tid = threadIdx.x, lane = tid & 31, w = tid >> 5;  // w in 0..3
    const int q0 = qt * 64;

    const int lrow = (lane & 7) + ((lane >> 3) & 1) * 8;
    const int lk   = (lane >> 4) * 8;
    const int nrow = (lane >> 4) * 8 + (lane & 7);
    const int kadd = ((lane >> 3) & 1) * 8;
    const int trow = lane & 15;
    const int tcol = (lane >> 4) * 8;

    // ---- load Q hi/lo tile (64 rows x 128 bf16) ----
    {
        const size_t qoff = ((size_t)(b * SEQ + q0) * NQH + h) * HDIM;
        const uint4* gh = (const uint4*)(Qh + qoff);
        const uint4* gl = (const uint4*)(Ql + qoff);
        for (int i = tid; i < 1024; i += 128) {
            int r = i >> 4, c = i & 15;
            *(uint4*)(sm + FQH + r * FP + c * 16) = gh[(size_t)r * 512 + c];
            *(uint4*)(sm + FQL + r * FP + c * 16) = gl[(size_t)r * 512 + c];
        }
    }

    float m0 = -1e30f, m1 = -1e30f, l0 = 0.f, l1 = 0.f;
    float oacc[16][4];
#pragma unroll
    for (int nt = 0; nt < 16; nt++)
#pragma unroll
        for (int j = 0; j < 4; j++) oacc[nt][j] = 0.f;

    const int row0 = q0 + w * 16 + (lane >> 2);
    const int cb   = 2 * (lane & 3);
    const int ktiles = qt + 1;

    for (int kt = 0; kt < ktiles; kt++) {
        __syncthreads();
        {
            const size_t off = ((size_t)(b * SEQ + kt * 64) * NKVH + kvh) * HDIM;
            const uint4* gkh = (const uint4*)(Kh + off);
            const uint4* gkl = (const uint4*)(Kl + off);
            const uint4* gvh = (const uint4*)(Vh + off);
            const uint4* gvl = (const uint4*)(Vl + off);
            for (int i = tid; i < 1024; i += 128) {
                int r = i >> 4, c = i & 15;
                uint32_t d = r * FP + c * 16;
                size_t gg = (size_t)r * 128 + c;
                *(uint4*)(sm + FKH + d) = gkh[gg];
                *(uint4*)(sm + FKL + d) = gkl[gg];
                *(uint4*)(sm + FVH + d) = gvh[gg];
                *(uint4*)(sm + FVL + d) = gvl[gg];
            }
        }
        __syncthreads();

        float s[8][4];
#pragma unroll
        for (int nt = 0; nt < 8; nt++)
#pragma unroll
            for (int j = 0; j < 4; j++) s[nt][j] = 0.f;

#pragma unroll
        for (int ks = 0; ks < 8; ks++) {
            uint32_t ah[4], al[4];
            uint32_t aa = sb + FQH + (w * 16 + lrow) * FP + (ks * 16 + lk) * 2;
            LDMATRIX_X4(ah[0], ah[1], ah[2], ah[3], aa);
            LDMATRIX_X4(al[0], al[1], al[2], al[3], aa + (FQL - FQH));
            uint32_t bh[8][2], bl[8][2];
#pragma unroll
            for (int p = 0; p < 4; p++) {
                uint32_t ba = sb + FKH + (p * 16 + nrow) * FP + (ks * 16 + kadd) * 2;
                LDMATRIX_X4(bh[2*p][0], bh[2*p][1], bh[2*p+1][0], bh[2*p+1][1], ba);
                LDMATRIX_X4(bl[2*p][0], bl[2*p][1], bl[2*p+1][0], bl[2*p+1][1],
                            ba + (FKL - FKH));
            }
#pragma unroll
            for (int nt = 0; nt < 8; nt++) MMA_BF16(s[nt], ah, bh[nt][0], bh[nt][1]);
#pragma unroll
            for (int nt = 0; nt < 8; nt++) MMA_BF16(s[nt], al, bh[nt][0], bh[nt][1]);
#pragma unroll
            for (int nt = 0; nt < 8; nt++) MMA_BF16(s[nt], ah, bl[nt][0], bl[nt][1]);
        }

        if (kt == qt) {  // diagonal tile masking
            const int colb = kt * 64 + cb;
#pragma unroll
            for (int nt = 0; nt < 8; nt++) {
                int c0 = colb + 8 * nt;
                if (c0 > row0)     s[nt][0] = -1e30f;
                if (c0 + 1 > row0) s[nt][1] = -1e30f;
                if (c0 > row0 + 8)     s[nt][2] = -1e30f;
                if (c0 + 1 > row0 + 8) s[nt][3] = -1e30f;
            }
        }

        float mt0 = -1e30f, mt1 = -1e30f;
#pragma unroll
        for (int nt = 0; nt < 8; nt++) {
            mt0 = fmaxf(mt0, fmaxf(s[nt][0], s[nt][1]));
            mt1 = fmaxf(mt1, fmaxf(s[nt][2], s[nt][3]));
        }
        mt0 = fmaxf(mt0, __shfl_xor_sync(0xffffffffu, mt0, 1));
        mt0 = fmaxf(mt0, __shfl_xor_sync(0xffffffffu, mt0, 2));
        mt1 = fmaxf(mt1, __shfl_xor_sync(0xffffffffu, mt1, 1));
        mt1 = fmaxf(mt1, __shfl_xor_sync(0xffffffffu, mt1, 2));
        float mn0 = fmaxf(m0, mt0), mn1 = fmaxf(m1, mt1);
        float a0 = __expf(m0 - mn0), a1 = __expf(m1 - mn1);
        float ps0 = 0.f, ps1 = 0.f;
#pragma unroll
        for (int nt = 0; nt < 8; nt++) {
            s[nt][0] = __expf(s[nt][0] - mn0);
            s[nt][1] = __expf(s[nt][1] - mn0);
            s[nt][2] = __expf(s[nt][2] - mn1);
            s[nt][3] = __expf(s[nt][3] - mn1);
            ps0 += s[nt][0] + s[nt][1];
            ps1 += s[nt][2] + s[nt][3];
        }
        ps0 += __shfl_xor_sync(0xffffffffu, ps0, 1);
        ps0 += __shfl_xor_sync(0xffffffffu, ps0, 2);
        ps1 += __shfl_xor_sync(0xffffffffu, ps1, 1);
        ps1 += __shfl_xor_sync(0xffffffffu, ps1, 2);
        l0 = l0 * a0 + ps0;  m0 = mn0;
        l1 = l1 * a1 + ps1;  m1 = mn1;
#pragma unroll
        for (int nt = 0; nt < 16; nt++) {
            oacc[nt][0] *= a0; oacc[nt][1] *= a0;
            oacc[nt][2] *= a1; oacc[nt][3] *= a1;
        }

#pragma unroll
        for (int j = 0; j < 4; j++) {
            uint32_t ph[4], pl[4];
            split_pack(s[2*j][0],   s[2*j][1],   ph[0], pl[0]);
            split_pack(s[2*j][2],   s[2*j][3],   ph[1], pl[1]);
            split_pack(s[2*j+1][0], s[2*j+1][1], ph[2], pl[2]);
            split_pack(s[2*j+1][2], s[2*j+1][3], ph[3], pl[3]);
            uint32_t vfh[8][4], vfl[8][4];
#pragma unroll
            for (int t = 0; t < 8; t++) {
                uint32_t va = sb + FVH + (j * 16 + trow) * FP + (t * 16 + tcol) * 2;
                LDMATRIX_X4_T(vfh[t][0], vfh[t][1], vfh[t][2], vfh[t][3], va);
                LDMATRIX_X4_T(vfl[t][0], vfl[t][1], vfl[t][2], vfl[t][3],
                              va + (FVL - FVH));
            }
#pragma unroll
            for (int t = 0; t < 8; t++) {
                MMA_BF16(oacc[2*t],   ph, vfh[t][0], vfh[t][1]);
                MMA_BF16(oacc[2*t+1], ph, vfh[t][2], vfh[t][3]);
            }
#pragma unroll
            for (int t = 0; t < 8; t++) {
                MMA_BF16(oacc[2*t],   pl, vfh[t][0], vfh[t][1]);
                MMA_BF16(oacc[2*t+1], pl, vfh[t][2], vfh[t][3]);
            }
#pragma unroll
            for (int t = 0; t < 8; t++) {
                MMA_BF16(oacc[2*t],   ph, vfl[t][0], vfl[t][1]);
                MMA_BF16(oacc[2*t+1], ph, vfl[t][2], vfl[t][3]);
            }
        }
    }

    const float inv0 = 1.f / l0, inv1 = 1.f / l1;
    const size_t o0 = ((size_t)(b * SEQ + row0)) * DMODEL + h * HDIM + cb;
    const size_t o1 = ((size_t)(b * SEQ + row0 + 8)) * DMODEL + h * HDIM + cb;
#pragma unroll
    for (int nt = 0; nt < 16; nt++) {
        uint32_t hh, ll;
        split_pack(oacc[nt][0] * inv0, oacc[nt][1] * inv0, hh, ll);
        *(uint32_t*)(Oh + o0 + 8 * nt) = hh;
        *(uint32_t*)(Ol + o0 + 8 * nt) = ll;
        split_pack(oacc[nt][2] * inv1, oacc[nt][3] * inv1, hh, ll);
        *(uint32_t*)(Oh + o1 + 8 * nt) = hh;
        *(uint32_t*)(Ol + o1 + 8 * nt) = ll;
    }
}

// ---------------- host launcher ---------------------------------------------
extern "C" void kernel_launch(void* const* d_in, const int* in_sizes, int n_in,
                              void* d_out, int out_size)
{
    const float* x   = (const float*)d_in[0];
    const float* w_q = (const float*)d_in[1];
    const float* w_k = (const float*)d_in[2];
    const float* w_v = (const float*)d_in[3];
    const float* w_o = (const float*)d_in[4];
    const float* fc  = (const float*)d_in[5];
    const float* fs  = (const float*)d_in[6];
    float* out = (float*)d_out;

    __nv_bfloat16 *xh, *xl, *wqkvh, *wqkvl, *woh, *wol, *ath, *atl;
    __nv_bfloat16 *qsh, *qsl, *ksh, *ksl, *vsh, *vsl;
    cudaGetSymbolAddress((void**)&xh,    g_xh);     cudaGetSymbolAddress((void**)&xl,    g_xl);
    cudaGetSymbolAddress((void**)&wqkvh, g_wqkv_h); cudaGetSymbolAddress((void**)&wqkvl, g_wqkv_l);
    cudaGetSymbolAddress((void**)&woh,   g_wot_h);  cudaGetSymbolAddress((void**)&wol,   g_wot_l);
    cudaGetSymbolAddress((void**)&ath,   g_atth);   cudaGetSymbolAddress((void**)&atl,   g_attl);
    cudaGetSymbolAddress((void**)&qsh,   g_qsh);    cudaGetSymbolAddress((void**)&qsl,   g_qsl);
    cudaGetSymbolAddress((void**)&ksh,   g_ksh);    cudaGetSymbolAddress((void**)&ksl,   g_ksl);
    cudaGetSymbolAddress((void**)&vsh,   g_vsh);    cudaGetSymbolAddress((void**)&vsl,   g_vsl);

    cudaFuncSetAttribute(gemm_mma_kernel, cudaFuncAttributeMaxDynamicSharedMemorySize, GEMM_SMEM);
    cudaFuncSetAttribute(gemm_qkv_kernel, cudaFuncAttributeMaxDynamicSharedMemorySize, GEMM_SMEM);
    cudaFuncSetAttribute(flash_mma_kernel, cudaFuncAttributeMaxDynamicSharedMemorySize, FLASH_SMEM);

    const int M = BATCH * SEQ;  // 4096

    // weight transposes + splits into combined [6144,4096] (q,k,v) and wot
    transpose_split_kernel<<<dim3(DMODEL / 32, DMODEL / 32), 256>>>(
        w_q, wqkvh, wqkvl, DMODEL, DMODEL);
    transpose_split_kernel<<<dim3(NKV / 32, DMODEL / 32), 256>>>(
        w_k, wqkvh + (size_t)DMODEL * DMODEL, wqkvl + (size_t)DMODEL * DMODEL, DMODEL, NKV);
    transpose_split_kernel<<<dim3(NKV / 32, DMODEL / 32), 256>>>(
        w_v, wqkvh + (size_t)(DMODEL + NKV) * DMODEL, wqkvl + (size_t)(DMODEL + NKV) * DMODEL,
        DMODEL, NKV);
    transpose_split_kernel<<<dim3(DMODEL / 32, DMODEL / 32), 256>>>(
        w_o, woh, wol, DMODEL, DMODEL);

    // x split
    {
        int n4 = (M * DMODEL) / 4;
        convert_split_kernel<<<(n4 + 255) / 256, 256>>>(x, xh, xl, n4);
    }

    // fused QKV projection + rope + split (one GEMM over N=6144)
    gemm_qkv_kernel<<<dim3(NQKV / 128, M / 128), 256, GEMM_SMEM>>>(
        xh, xl, wqkvh, wqkvl, fc, fs, qsh, qsl, ksh, ksl, vsh, vsl, DMODEL);

    // flash attention (tensor cores), BM=64, 2 CTAs/SM
    flash_mma_kernel<<<dim3(SEQ / 64, NQH, BATCH), 128, FLASH_SMEM>>>(
        qsh, qsl, ksh, ksl, vsh, vsl, ath, atl);

    // O projection
    gemm_mma_kernel<<<dim3(DMODEL / 128, M / 128), 256, GEMM_SMEM>>>(
        ath, atl, woh, wol, out, M, DMODEL, DMODEL);
}

// round 8
// speedup vs baseline: 3.9818x; 1.3664x over previous
#include <cuda_runtime.h>
#include <cuda_fp16.h>
#include <math.h>
#include <stdint.h>

#define BATCH 2
#define SEQ 2048
#define DMODEL 4096
#define NQH 32
#define NKVH 8
#define HDIM 128
#define NKV (NKVH * HDIM)        // 1024
#define NQKV (DMODEL + 2 * NKV)  // 6144

// ---------------- scratch (device globals; allocation-free) ----------------
__device__ __half g_xh[(size_t)BATCH * SEQ * DMODEL];
__device__ __half g_xl[(size_t)BATCH * SEQ * DMODEL];
__device__ __half g_wqkv_h[(size_t)NQKV * DMODEL];   // [6144,4096] rows: q,k,v (hi only)
__device__ __half g_wot_h[(size_t)DMODEL * DMODEL];
__device__ __half g_atth[(size_t)BATCH * SEQ * DMODEL];
__device__ __half g_attl[(size_t)BATCH * SEQ * DMODEL];

__device__ __half g_qsh[(size_t)BATCH * SEQ * NQH * HDIM];
__device__ __half g_qsl[(size_t)BATCH * SEQ * NQH * HDIM];
__device__ __half g_ksh[(size_t)BATCH * SEQ * NKV];   // hi only
__device__ __half g_vsh[(size_t)BATCH * SEQ * NKV];   // hi only

__device__ __forceinline__ uint32_t smem_to_u32(const void* p) {
    uint32_t a;
    asm("{ .reg .u64 t; cvta.to.shared.u64 t, %1; cvt.u32.u64 %0, t; }"
        : "=r"(a) : "l"(p));
    return a;
}

#define CP_ASYNC_16(dst, src) \
    asm volatile("cp.async.cg.shared.global [%0], [%1], 16;" :: "r"(dst), "l"(src) : "memory")
#define CP_COMMIT() asm volatile("cp.async.commit_group;" ::: "memory")
#define CP_WAIT_1()  asm volatile("cp.async.wait_group 1;" ::: "memory")

#define LDMATRIX_X4(r0, r1, r2, r3, addr) \
    asm volatile("ldmatrix.sync.aligned.m8n8.x4.shared.b16 {%0,%1,%2,%3}, [%4];" \
        : "=r"(r0), "=r"(r1), "=r"(r2), "=r"(r3) : "r"(addr))
#define LDMATRIX_X4_T(r0, r1, r2, r3, addr) \
    asm volatile("ldmatrix.sync.aligned.m8n8.x4.trans.shared.b16 {%0,%1,%2,%3}, [%4];" \
        : "=r"(r0), "=r"(r1), "=r"(r2), "=r"(r3) : "r"(addr))

#define MMA_F16(d, a, b0, b1) \
    asm("mma.sync.aligned.m16n8k16.row.col.f32.f16.f16.f32 " \
        "{%0,%1,%2,%3}, {%4,%5,%6,%7}, {%8,%9}, {%0,%1,%2,%3};" \
        : "+f"((d)[0]), "+f"((d)[1]), "+f"((d)[2]), "+f"((d)[3]) \
        : "r"((a)[0]), "r"((a)[1]), "r"((a)[2]), "r"((a)[3]), "r"(b0), "r"(b1))

__device__ __forceinline__ uint32_t pack2h(float a, float b) {
    __half2 t = __floats2half2_rn(a, b);
    return *reinterpret_cast<uint32_t*>(&t);
}
__device__ __forceinline__ void split_pack_h(float a, float b, uint32_t& h, uint32_t& l) {
    __half ha = __float2half_rn(a), hb = __float2half_rn(b);
    h = pack2h(__half2float(ha), __half2float(hb));
    l = pack2h(a - __half2float(ha), b - __half2float(hb));
}

// ---------------- shared GEMM mainloop (device inline) -----------------------
// TBK=64, 3 stages of 3 tiles (Ah, Al, Bh), pitch 144B.
#define TBK 64
#define APITCH 144
#define TILE_B (128 * APITCH)          // 18432
#define STAGE_B (3 * TILE_B)           // 55296
#define NSTAGE 3
#define GEMM_SMEM (NSTAGE * STAGE_B)   // 165888

struct GemmCtx {
    float acc[2][8][4];
    int lane, wid, wm, wn, bm, bn;
};

__device__ __forceinline__ void gemm_mainloop(
    GemmCtx& g, char* smem_raw,
    const __half* __restrict__ Ah, const __half* __restrict__ Al,
    const __half* __restrict__ Bh, int K)
{
    const uint32_t sbase = smem_to_u32(smem_raw);
    const int tid = threadIdx.x;
    const int lane = g.lane, wm = g.wm, wn = g.wn, bm = g.bm, bn = g.bn;

    const __half* gsrc[3] = {Ah, Al, Bh};
    const int rbase3[3] = {bm, bm, bn};

    auto issue_stage = [&](int it, int buf) {
        const int k0 = it * TBK;
#pragma unroll
        for (int t = 0; t < 3; t++) {
            const __half* gp = gsrc[t] + (size_t)rbase3[t] * K + k0;
            const uint32_t db = sbase + buf * STAGE_B + t * TILE_B;
#pragma unroll
            for (int i = 0; i < 4; i++) {
                int c = i * 256 + tid;          // 1024 chunks of 16B per tile
                int r = c >> 3, ch = c & 7;
                const void* src = gp + (size_t)r * K + ch * 8;
                uint32_t dst = db + r * APITCH + ch * 16;
                CP_ASYNC_16(dst, src);
            }
        }
        CP_COMMIT();
    };

    const int lrow = (lane & 7) + ((lane >> 3) & 1) * 8;
    const int lk   = (lane >> 4) * 8;
    const int nrow = (lane >> 4) * 8 + (lane & 7);
    const int kadd = ((lane >> 3) & 1) * 8;

    // frag loader for one k16 quarter (A hi+lo, B hi)
    auto load_q = [&](uint32_t base, int kk,
                      uint32_t a_h[2][4], uint32_t a_l[2][4], uint32_t b_h[8][2]) {
#pragma unroll
        for (int p = 0; p < 4; p++) {
            uint32_t ab = base + 2 * TILE_B +
                          (wn * 64 + p * 16 + nrow) * APITCH + (kk * 16 + kadd) * 2;
            LDMATRIX_X4(b_h[2*p][0], b_h[2*p][1], b_h[2*p+1][0], b_h[2*p+1][1], ab);
        }
#pragma unroll
        for (int mt = 0; mt < 2; mt++) {
            uint32_t aa = base + (wm * 32 + mt * 16 + lrow) * APITCH +
                          (kk * 16 + lk) * 2;
            LDMATRIX_X4(a_h[mt][0], a_h[mt][1], a_h[mt][2], a_h[mt][3], aa);
            LDMATRIX_X4(a_l[mt][0], a_l[mt][1], a_l[mt][2], a_l[mt][3],
                        aa + TILE_B);
        }
    };

#pragma unroll
    for (int mt = 0; mt < 2; mt++)
#pragma unroll
        for (int nt = 0; nt < 8; nt++)
#pragma unroll
            for (int j = 0; j < 4; j++) g.acc[mt][nt][j] = 0.f;

    const int NITER = K / TBK;
    issue_stage(0, 0);
    issue_stage(1, 1);

    for (int it = 0; it < NITER; it++) {
        CP_WAIT_1();
        __syncthreads();
        if (it + 2 < NITER) issue_stage(it + 2, (it + 2) % NSTAGE);
        else CP_COMMIT();
        const uint32_t base = sbase + (it % NSTAGE) * STAGE_B;

        uint32_t ah[2][2][4], al[2][2][4], bh[2][8][2];
        load_q(base, 0, ah[0], al[0], bh[0]);
#pragma unroll
        for (int kk = 0; kk < 4; kk++) {
            const int cur = kk & 1, nxt = cur ^ 1;
            if (kk < 3) load_q(base, kk + 1, ah[nxt], al[nxt], bh[nxt]);
            // term-major: pass 1 Ah*Bh, pass 2 Al*Bh
#pragma unroll
            for (int mt = 0; mt < 2; mt++)
#pragma unroll
                for (int nt = 0; nt < 8; nt++)
                    MMA_F16(g.acc[mt][nt], ah[cur][mt], bh[cur][nt][0], bh[cur][nt][1]);
#pragma unroll
            for (int mt = 0; mt < 2; mt++)
#pragma unroll
                for (int nt = 0; nt < 8; nt++)
                    MMA_F16(g.acc[mt][nt], al[cur][mt], bh[cur][nt][0], bh[cur][nt][1]);
        }
        __syncthreads();
    }
}

// ---------------- GEMM -> fp32 C (O projection) ------------------------------
__global__ __launch_bounds__(256, 1) void gemm_mma_kernel(
    const __half* __restrict__ Ah, const __half* __restrict__ Al,
    const __half* __restrict__ Bh, float* __restrict__ C, int M, int N, int K)
{
    extern __shared__ __align__(128) char smem_raw[];
    GemmCtx g;
    g.lane = threadIdx.x & 31; g.wid = threadIdx.x >> 5;
    g.wm = g.wid & 3; g.wn = g.wid >> 2;
    g.bm = blockIdx.y * 128; g.bn = blockIdx.x * 128;
    gemm_mainloop(g, smem_raw, Ah, Al, Bh, K);

    const int gr = g.lane >> 2, t2 = (g.lane & 3) * 2;
#pragma unroll
    for (int mt = 0; mt < 2; mt++) {
#pragma unroll
        for (int nt = 0; nt < 8; nt++) {
            int row = g.bm + g.wm * 32 + mt * 16 + gr;
            int col = g.bn + g.wn * 64 + nt * 8 + t2;
            *(float2*)&C[(size_t)row * N + col] =
                make_float2(g.acc[mt][nt][0], g.acc[mt][nt][1]);
            *(float2*)&C[(size_t)(row + 8) * N + col] =
                make_float2(g.acc[mt][nt][2], g.acc[mt][nt][3]);
        }
    }
}

// ---------------- fused QKV GEMM: rope/scale/split epilogue ------------------
__device__ __forceinline__ void rope_split_store_h(
    __half* oh, __half* ol,
    const float* __restrict__ fc, const float* __restrict__ fs,
    int row, int col, float v0, float v1, int stride, int coloff, float scale,
    bool want_lo)
{
    int s = row & (SEQ - 1);
    int i = (col & 127) >> 1;
    float c  = __ldg(fc + s * 64 + i);
    float sn = __ldg(fs + s * 64 + i);
    float ra = (v0 * c - v1 * sn) * scale;
    float rb = (v0 * sn + v1 * c) * scale;
    uint32_t h, l;
    split_pack_h(ra, rb, h, l);
    size_t o = (size_t)row * stride + (col - coloff);
    *(uint32_t*)(oh + o) = h;
    if (want_lo) *(uint32_t*)(ol + o) = l;
}

__global__ __launch_bounds__(256, 1) void gemm_qkv_kernel(
    const __half* __restrict__ Ah, const __half* __restrict__ Al,
    const __half* __restrict__ Bh,
    const float* __restrict__ fc, const float* __restrict__ fs,
    __half* __restrict__ qh, __half* __restrict__ ql,
    __half* __restrict__ kh, __half* __restrict__ vh, int K)
{
    extern __shared__ __align__(128) char smem_raw[];
    GemmCtx g;
    g.lane = threadIdx.x & 31; g.wid = threadIdx.x >> 5;
    g.wm = g.wid & 3; g.wn = g.wid >> 2;
    g.bm = blockIdx.y * 128; g.bn = blockIdx.x * 128;
    gemm_mainloop(g, smem_raw, Ah, Al, Bh, K);

    const int gr = g.lane >> 2, t2 = (g.lane & 3) * 2;
    const float qscale = 0.0883883476483184f;  // 1/sqrt(128)

    if (g.bn < DMODEL) {            // Q: rope + scale + split (hi+lo)
#pragma unroll
        for (int mt = 0; mt < 2; mt++)
#pragma unroll
            for (int nt = 0; nt < 8; nt++) {
                int row = g.bm + g.wm * 32 + mt * 16 + gr;
                int col = g.bn + g.wn * 64 + nt * 8 + t2;
                rope_split_store_h(qh, ql, fc, fs, row, col,
                                   g.acc[mt][nt][0], g.acc[mt][nt][1], DMODEL, 0,
                                   qscale, true);
                rope_split_store_h(qh, ql, fc, fs, row + 8, col,
                                   g.acc[mt][nt][2], g.acc[mt][nt][3], DMODEL, 0,
                                   qscale, true);
            }
    } else if (g.bn < DMODEL + NKV) {  // K: rope, hi only
#pragma unroll
        for (int mt = 0; mt < 2; mt++)
#pragma unroll
            for (int nt = 0; nt < 8; nt++) {
                int row = g.bm + g.wm * 32 + mt * 16 + gr;
                int col = g.bn + g.wn * 64 + nt * 8 + t2;
                rope_split_store_h(kh, nullptr, fc, fs, row, col,
                                   g.acc[mt][nt][0], g.acc[mt][nt][1], NKV, DMODEL,
                                   1.0f, false);
                rope_split_store_h(kh, nullptr, fc, fs, row + 8, col,
                                   g.acc[mt][nt][2], g.acc[mt][nt][3], NKV, DMODEL,
                                   1.0f, false);
            }
    } else {                            // V: hi only
#pragma unroll
        for (int mt = 0; mt < 2; mt++)
#pragma unroll
            for (int nt = 0; nt < 8; nt++) {
                int row = g.bm + g.wm * 32 + mt * 16 + gr;
                int col = g.bn + g.wn * 64 + nt * 8 + t2 - (DMODEL + NKV);
                size_t o0 = (size_t)row * NKV + col;
                *(uint32_t*)(vh + o0) = pack2h(g.acc[mt][nt][0], g.acc[mt][nt][1]);
                size_t o1 = o0 + (size_t)8 * NKV;
                *(uint32_t*)(vh + o1) = pack2h(g.acc[mt][nt][2], g.acc[mt][nt][3]);
            }
    }
}

// ---------------- fp32 -> fp16 hi/lo split (x) --------------------------------
__global__ __launch_bounds__(256) void convert_split_kernel(
    const float* __restrict__ in, __half* __restrict__ oh,
    __half* __restrict__ ol, int n4)
{
    int i = blockIdx.x * blockDim.x + threadIdx.x;
    if (i >= n4) return;
    float4 v = ((const float4*)in)[i];
    uint32_t h0, l0, h1, l1;
    split_pack_h(v.x, v.y, h0, l0);
    split_pack_h(v.z, v.w, h1, l1);
    ((uint2*)oh)[i] = make_uint2(h0, h1);
    ((uint2*)ol)[i] = make_uint2(l0, l1);
}

// ---------------- fp32 [K,N] -> transposed fp16 [N,K] (hi only) --------------
__global__ __launch_bounds__(256) void transpose_h_kernel(
    const float* __restrict__ in, __half* __restrict__ oh, int K, int N)
{
    __shared__ float tile[32][33];
    const int k0 = blockIdx.y * 32, n0 = blockIdx.x * 32;
    const int tx = threadIdx.x & 31, ty = threadIdx.x >> 5;
#pragma unroll
    for (int i = 0; i < 32; i += 8)
        tile[ty + i][tx] = in[(size_t)(k0 + ty + i) * N + n0 + tx];
    __syncthreads();
#pragma unroll
    for (int i = 0; i < 32; i += 8) {
        float v = tile[tx][ty + i];
        oh[(size_t)(n0 + ty + i) * K + k0 + tx] = __float2half_rn(v);
    }
}

// ---------------- flash attention via mma.sync (fp16, A-side split) ----------
// BM=64, 4 warps x 16 rows, 2 CTAs/SM. Q hi+lo; K,V hi only.
#define FP 272
#define FQH 0
#define FQL 17408
#define FKH 34816
#define FVH 52224
#define FLASH_SMEM 69632

__global__ __launch_bounds__(128, 2) void flash_mma_kernel(
    const __half* __restrict__ Qh, const __half* __restrict__ Ql,
    const __half* __restrict__ Kh, const __half* __restrict__ Vh,
    __half* __restrict__ Oh, __half* __restrict__ Ol)
{
    extern __shared__ __align__(128) char sm[];
    const uint32_t sb = smem_to_u32(sm);
    const int qt = blockIdx.x, h = blockIdx.y, b = blockIdx.z;
    const int kvh = h >> 2;
    const int tid = threadIdx.x, lane = tid & 31, w = tid >> 5;
    const int q0 = qt * 64;

    const int lrow = (lane & 7) + ((lane >> 3) & 1) * 8;
    const int lk   = (lane >> 4) * 8;
    const int nrow = (lane >> 4) * 8 + (lane & 7);
    const int kadd = ((lane >> 3) & 1) * 8;
    const int trow = lane & 15;
    const int tcol = (lane >> 4) * 8;

    {
        const size_t qoff = ((size_t)(b * SEQ + q0) * NQH + h) * HDIM;
        const uint4* gh = (const uint4*)(Qh + qoff);
        const uint4* gl = (const uint4*)(Ql + qoff);
        for (int i = tid; i < 1024; i += 128) {
            int r = i >> 4, c = i & 15;
            *(uint4*)(sm + FQH + r * FP + c * 16) = gh[(size_t)r * 512 + c];
            *(uint4*)(sm + FQL + r * FP + c * 16) = gl[(size_t)r * 512 + c];
        }
    }

    float m0 = -1e30f, m1 = -1e30f, l0 = 0.f, l1 = 0.f;
    float oacc[16][4];
#pragma unroll
    for (int nt = 0; nt < 16; nt++)
#pragma unroll
        for (int j = 0; j < 4; j++) oacc[nt][j] = 0.f;

    const int row0 = q0 + w * 16 + (lane >> 2);
    const int cb   = 2 * (lane & 3);
    const int ktiles = qt + 1;

    for (int kt = 0; kt < ktiles; kt++) {
        __syncthreads();
        {
            const size_t off = ((size_t)(b * SEQ + kt * 64) * NKVH + kvh) * HDIM;
            const uint4* gkh = (const uint4*)(Kh + off);
            const uint4* gvh = (const uint4*)(Vh + off);
            for (int i = tid; i < 1024; i += 128) {
                int r = i >> 4, c = i & 15;
                uint32_t d = r * FP + c * 16;
                size_t gg = (size_t)r * 128 + c;
                *(uint4*)(sm + FKH + d) = gkh[gg];
                *(uint4*)(sm + FVH + d) = gvh[gg];
            }
        }
        __syncthreads();

        float s[8][4];
#pragma unroll
        for (int nt = 0; nt < 8; nt++)
#pragma unroll
            for (int j = 0; j < 4; j++) s[nt][j] = 0.f;

#pragma unroll
        for (int ks = 0; ks < 8; ks++) {
            uint32_t ah[4], al[4];
            uint32_t aa = sb + FQH + (w * 16 + lrow) * FP + (ks * 16 + lk) * 2;
            LDMATRIX_X4(ah[0], ah[1], ah[2], ah[3], aa);
            LDMATRIX_X4(al[0], al[1], al[2], al[3], aa + (FQL - FQH));
            uint32_t bh[8][2];
#pragma unroll
            for (int p = 0; p < 4; p++) {
                uint32_t ba = sb + FKH + (p * 16 + nrow) * FP + (ks * 16 + kadd) * 2;
                LDMATRIX_X4(bh[2*p][0], bh[2*p][1], bh[2*p+1][0], bh[2*p+1][1], ba);
            }
#pragma unroll
            for (int nt = 0; nt < 8; nt++) MMA_F16(s[nt], ah, bh[nt][0], bh[nt][1]);
#pragma unroll
            for (int nt = 0; nt < 8; nt++) MMA_F16(s[nt], al, bh[nt][0], bh[nt][1]);
        }

        if (kt == qt) {
            const int colb = kt * 64 + cb;
#pragma unroll
            for (int nt = 0; nt < 8; nt++) {
                int c0 = colb + 8 * nt;
                if (c0 > row0)     s[nt][0] = -1e30f;
                if (c0 + 1 > row0) s[nt][1] = -1e30f;
                if (c0 > row0 + 8)     s[nt][2] = -1e30f;
                if (c0 + 1 > row0 + 8) s[nt][3] = -1e30f;
            }
        }

        float mt0 = -1e30f, mt1 = -1e30f;
#pragma unroll
        for (int nt = 0; nt < 8; nt++) {
            mt0 = fmaxf(mt0, fmaxf(s[nt][0], s[nt][1]));
            mt1 = fmaxf(mt1, fmaxf(s[nt][2], s[nt][3]));
        }
        mt0 = fmaxf(mt0, __shfl_xor_sync(0xffffffffu, mt0, 1));
        mt0 = fmaxf(mt0, __shfl_xor_sync(0xffffffffu, mt0, 2));
        mt1 = fmaxf(mt1, __shfl_xor_sync(0xffffffffu, mt1, 1));
        mt1 = fmaxf(mt1, __shfl_xor_sync(0xffffffffu, mt1, 2));
        float mn0 = fmaxf(m0, mt0), mn1 = fmaxf(m1, mt1);
        float a0 = __expf(m0 - mn0), a1 = __expf(m1 - mn1);
        float ps0 = 0.f, ps1 = 0.f;
#pragma unroll
        for (int nt = 0; nt < 8; nt++) {
            s[nt][0] = __expf(s[nt][0] - mn0);
            s[nt][1] = __expf(s[nt][1] - mn0);
            s[nt][2] = __expf(s[nt][2] - mn1);
            s[nt][3] = __expf(s[nt][3] - mn1);
            ps0 += s[nt][0] + s[nt][1];
            ps1 += s[nt][2] + s[nt][3];
        }
        ps0 += __shfl_xor_sync(0xffffffffu, ps0, 1);
        ps0 += __shfl_xor_sync(0xffffffffu, ps0, 2);
        ps1 += __shfl_xor_sync(0xffffffffu, ps1, 1);
        ps1 += __shfl_xor_sync(0xffffffffu, ps1, 2);
        l0 = l0 * a0 + ps0;  m0 = mn0;
        l1 = l1 * a1 + ps1;  m1 = mn1;
#pragma unroll
        for (int nt = 0; nt < 16; nt++) {
            oacc[nt][0] *= a0; oacc[nt][1] *= a0;
            oacc[nt][2] *= a1; oacc[nt][3] *= a1;
        }

        // O += Ph*Vh + Pl*Vh (P residual corrected; V hi only)
#pragma unroll
        for (int j = 0; j < 4; j++) {
            uint32_t ph[4], pl[4];
            split_pack_h(s[2*j][0],   s[2*j][1],   ph[0], pl[0]);
            split_pack_h(s[2*j][2],   s[2*j][3],   ph[1], pl[1]);
            split_pack_h(s[2*j+1][0], s[2*j+1][1], ph[2], pl[2]);
            split_pack_h(s[2*j+1][2], s[2*j+1][3], ph[3], pl[3]);
            uint32_t vfh[8][4];
#pragma unroll
            for (int t = 0; t < 8; t++) {
                uint32_t va = sb + FVH + (j * 16 + trow) * FP + (t * 16 + tcol) * 2;
                LDMATRIX_X4_T(vfh[t][0], vfh[t][1], vfh[t][2], vfh[t][3], va);
            }
#pragma unroll
            for (int t = 0; t < 8; t++) {
                MMA_F16(oacc[2*t],   ph, vfh[t][0], vfh[t][1]);
                MMA_F16(oacc[2*t+1], ph, vfh[t][2], vfh[t][3]);
            }
#pragma unroll
            for (int t = 0; t < 8; t++) {
                MMA_F16(oacc[2*t],   pl, vfh[t][0], vfh[t][1]);
                MMA_F16(oacc[2*t+1], pl, vfh[t][2], vfh[t][3]);
            }
        }
    }

    const float inv0 = 1.f / l0, inv1 = 1.f / l1;
    const size_t o0 = ((size_t)(b * SEQ + row0)) * DMODEL + h * HDIM + cb;
    const size_t o1 = ((size_t)(b * SEQ + row0 + 8)) * DMODEL + h * HDIM + cb;
#pragma unroll
    for (int nt = 0; nt < 16; nt++) {
        uint32_t hh, ll;
        split_pack_h(oacc[nt][0] * inv0, oacc[nt][1] * inv0, hh, ll);
        *(uint32_t*)(Oh + o0 + 8 * nt) = hh;
        *(uint32_t*)(Ol + o0 + 8 * nt) = ll;
        split_pack_h(oacc[nt][2] * inv1, oacc[nt][3] * inv1, hh, ll);
        *(uint32_t*)(Oh + o1 + 8 * nt) = hh;
        *(uint32_t*)(Ol + o1 + 8 * nt) = ll;
    }
}

// ---------------- host launcher ---------------------------------------------
extern "C" void kernel_launch(void* const* d_in, const int* in_sizes, int n_in,
                              void* d_out, int out_size)
{
    const float* x   = (const float*)d_in[0];
    const float* w_q = (const float*)d_in[1];
    const float* w_k = (const float*)d_in[2];
    const float* w_v = (const float*)d_in[3];
    const float* w_o = (const float*)d_in[4];
    const float* fc  = (const float*)d_in[5];
    const float* fs  = (const float*)d_in[6];
    float* out = (float*)d_out;

    __half *xh, *xl, *wqkvh, *woh, *ath, *atl, *qsh, *qsl, *ksh, *vsh;
    cudaGetSymbolAddress((void**)&xh,    g_xh);     cudaGetSymbolAddress((void**)&xl,  g_xl);
    cudaGetSymbolAddress((void**)&wqkvh, g_wqkv_h);
    cudaGetSymbolAddress((void**)&woh,   g_wot_h);
    cudaGetSymbolAddress((void**)&ath,   g_atth);   cudaGetSymbolAddress((void**)&atl, g_attl);
    cudaGetSymbolAddress((void**)&qsh,   g_qsh);    cudaGetSymbolAddress((void**)&qsl, g_qsl);
    cudaGetSymbolAddress((void**)&ksh,   g_ksh);    cudaGetSymbolAddress((void**)&vsh, g_vsh);

    cudaFuncSetAttribute(gemm_mma_kernel, cudaFuncAttributeMaxDynamicSharedMemorySize, GEMM_SMEM);
    cudaFuncSetAttribute(gemm_qkv_kernel, cudaFuncAttributeMaxDynamicSharedMemorySize, GEMM_SMEM);
    cudaFuncSetAttribute(flash_mma_kernel, cudaFuncAttributeMaxDynamicSharedMemorySize, FLASH_SMEM);

    const int M = BATCH * SEQ;  // 4096

    // weight transposes (hi only) into combined [6144,4096] and wot
    transpose_h_kernel<<<dim3(DMODEL / 32, DMODEL / 32), 256>>>(w_q, wqkvh, DMODEL, DMODEL);
    transpose_h_kernel<<<dim3(NKV / 32, DMODEL / 32), 256>>>(
        w_k, wqkvh + (size_t)DMODEL * DMODEL, DMODEL, NKV);
    transpose_h_kernel<<<dim3(NKV / 32, DMODEL / 32), 256>>>(
        w_v, wqkvh + (size_t)(DMODEL + NKV) * DMODEL, DMODEL, NKV);
    transpose_h_kernel<<<dim3(DMODEL / 32, DMODEL / 32), 256>>>(w_o, woh, DMODEL, DMODEL);

    // x split (hi + lo)
    {
        int n4 = (M * DMODEL) / 4;
        convert_split_kernel<<<(n4 + 255) / 256, 256>>>(x, xh, xl, n4);
    }

    // fused QKV projection + rope + split (one GEMM over N=6144)
    gemm_qkv_kernel<<<dim3(NQKV / 128, M / 128), 256, GEMM_SMEM>>>(
        xh, xl, wqkvh, fc, fs, qsh, qsl, ksh, vsh, DMODEL);

    // flash attention
    flash_mma_kernel<<<dim3(SEQ / 64, NQH, BATCH), 128, FLASH_SMEM>>>(
        qsh, qsl, ksh, vsh, ath, atl);

    // O projection
    gemm_mma_kernel<<<dim3(DMODEL / 128, M / 128), 256, GEMM_SMEM>>>(
        ath, atl, woh, out, M, DMODEL, DMODEL);
}

// round 9
// speedup vs baseline: 4.1178x; 1.0341x over previous
#include <cuda_runtime.h>
#include <cuda_fp16.h>
#include <math.h>
#include <stdint.h>

#define BATCH 2
#define SEQ 2048
#define DMODEL 4096
#define NQH 32
#define NKVH 8
#define HDIM 128
#define NKV (NKVH * HDIM)        // 1024
#define NQKV (DMODEL + 2 * NKV)  // 6144

// ---------------- scratch (device globals; allocation-free) ----------------
__device__ __half g_xh[(size_t)BATCH * SEQ * DMODEL];
__device__ __half g_xl[(size_t)BATCH * SEQ * DMODEL];
__device__ __half g_wqkv_h[(size_t)NQKV * DMODEL];   // [6144,4096] rows: q,k,v (hi only)
__device__ __half g_wot_h[(size_t)DMODEL * DMODEL];
__device__ __half g_atth[(size_t)BATCH * SEQ * DMODEL];
__device__ __half g_attl[(size_t)BATCH * SEQ * DMODEL];

__device__ __half g_qsh[(size_t)BATCH * SEQ * NQH * HDIM];
__device__ __half g_qsl[(size_t)BATCH * SEQ * NQH * HDIM];
__device__ __half g_ksh[(size_t)BATCH * SEQ * NKV];   // hi only
__device__ __half g_vsh[(size_t)BATCH * SEQ * NKV];   // hi only

__device__ __forceinline__ uint32_t smem_to_u32(const void* p) {
    uint32_t a;
    asm("{ .reg .u64 t; cvta.to.shared.u64 t, %1; cvt.u32.u64 %0, t; }"
        : "=r"(a) : "l"(p));
    return a;
}

#define CP_ASYNC_16(dst, src) \
    asm volatile("cp.async.cg.shared.global [%0], [%1], 16;" :: "r"(dst), "l"(src) : "memory")
#define CP_COMMIT() asm volatile("cp.async.commit_group;" ::: "memory")
#define CP_WAIT_1()  asm volatile("cp.async.wait_group 1;" ::: "memory")

#define LDMATRIX_X4(r0, r1, r2, r3, addr) \
    asm volatile("ldmatrix.sync.aligned.m8n8.x4.shared.b16 {%0,%1,%2,%3}, [%4];" \
        : "=r"(r0), "=r"(r1), "=r"(r2), "=r"(r3) : "r"(addr))
#define LDMATRIX_X4_T(r0, r1, r2, r3, addr) \
    asm volatile("ldmatrix.sync.aligned.m8n8.x4.trans.shared.b16 {%0,%1,%2,%3}, [%4];" \
        : "=r"(r0), "=r"(r1), "=r"(r2), "=r"(r3) : "r"(addr))

#define MMA_F16(d, a, b0, b1) \
    asm("mma.sync.aligned.m16n8k16.row.col.f32.f16.f16.f32 " \
        "{%0,%1,%2,%3}, {%4,%5,%6,%7}, {%8,%9}, {%0,%1,%2,%3};" \
        : "+f"((d)[0]), "+f"((d)[1]), "+f"((d)[2]), "+f"((d)[3]) \
        : "r"((a)[0]), "r"((a)[1]), "r"((a)[2]), "r"((a)[3]), "r"(b0), "r"(b1))

__device__ __forceinline__ uint32_t pack2h(float a, float b) {
    __half2 t = __floats2half2_rn(a, b);
    return *reinterpret_cast<uint32_t*>(&t);
}
__device__ __forceinline__ void split_pack_h(float a, float b, uint32_t& h, uint32_t& l) {
    __half ha = __float2half_rn(a), hb = __float2half_rn(b);
    h = pack2h(__half2float(ha), __half2float(hb));
    l = pack2h(a - __half2float(ha), b - __half2float(hb));
}

// ---------------- shared GEMM mainloop (device inline) -----------------------
// TBK=128, 2 stages of 3 tiles (Ah, Al, Bh), pitch 272B (17x16B, conflict-free).
#define TBK 128
#define APITCH 272
#define TILE_B (128 * APITCH)          // 34816
#define STAGE_B (3 * TILE_B)           // 104448
#define GEMM_SMEM (2 * STAGE_B)        // 208896

struct GemmCtx {
    float acc[2][8][4];
    int lane, wid, wm, wn, bm, bn;
};

__device__ __forceinline__ void gemm_mainloop(
    GemmCtx& g, char* smem_raw,
    const __half* __restrict__ Ah, const __half* __restrict__ Al,
    const __half* __restrict__ Bh, int K)
{
    const uint32_t sbase = smem_to_u32(smem_raw);
    const int tid = threadIdx.x;
    const int lane = g.lane, wm = g.wm, wn = g.wn, bm = g.bm, bn = g.bn;

    const __half* gsrc[3] = {Ah, Al, Bh};
    const int rbase3[3] = {bm, bm, bn};

    auto issue_stage = [&](int it, int buf) {
        const int k0 = it * TBK;
#pragma unroll
        for (int t = 0; t < 3; t++) {
            const __half* gp = gsrc[t] + (size_t)rbase3[t] * K + k0;
            const uint32_t db = sbase + buf * STAGE_B + t * TILE_B;
#pragma unroll
            for (int i = 0; i < 8; i++) {
                int c = i * 256 + tid;          // 2048 chunks of 16B per tile
                int r = c >> 4, ch = c & 15;
                const void* src = gp + (size_t)r * K + ch * 8;
                uint32_t dst = db + r * APITCH + ch * 16;
                CP_ASYNC_16(dst, src);
            }
        }
        CP_COMMIT();
    };

    const int lrow = (lane & 7) + ((lane >> 3) & 1) * 8;
    const int lk   = (lane >> 4) * 8;
    const int nrow = (lane >> 4) * 8 + (lane & 7);
    const int kadd = ((lane >> 3) & 1) * 8;

    // frag loader for one k16 quarter (A hi+lo, B hi)
    auto load_q = [&](uint32_t base, int kk,
                      uint32_t a_h[2][4], uint32_t a_l[2][4], uint32_t b_h[8][2]) {
#pragma unroll
        for (int p = 0; p < 4; p++) {
            uint32_t ab = base + 2 * TILE_B +
                          (wn * 64 + p * 16 + nrow) * APITCH + (kk * 16 + kadd) * 2;
            LDMATRIX_X4(b_h[2*p][0], b_h[2*p][1], b_h[2*p+1][0], b_h[2*p+1][1], ab);
        }
#pragma unroll
        for (int mt = 0; mt < 2; mt++) {
            uint32_t aa = base + (wm * 32 + mt * 16 + lrow) * APITCH +
                          (kk * 16 + lk) * 2;
            LDMATRIX_X4(a_h[mt][0], a_h[mt][1], a_h[mt][2], a_h[mt][3], aa);
            LDMATRIX_X4(a_l[mt][0], a_l[mt][1], a_l[mt][2], a_l[mt][3],
                        aa + TILE_B);
        }
    };

#pragma unroll
    for (int mt = 0; mt < 2; mt++)
#pragma unroll
        for (int nt = 0; nt < 8; nt++)
#pragma unroll
            for (int j = 0; j < 4; j++) g.acc[mt][nt][j] = 0.f;

    const int NITER = K / TBK;   // 32
    issue_stage(0, 0);
    issue_stage(1, 1);

    for (int it = 0; it < NITER; it++) {
        CP_WAIT_1();
        __syncthreads();
        const uint32_t base = sbase + (it & 1) * STAGE_B;

        uint32_t ah[2][2][4], al[2][2][4], bh[2][8][2];
        load_q(base, 0, ah[0], al[0], bh[0]);
#pragma unroll
        for (int kk = 0; kk < 8; kk++) {
            const int cur = kk & 1, nxt = cur ^ 1;
            if (kk < 7) load_q(base, kk + 1, ah[nxt], al[nxt], bh[nxt]);
            // term-major: pass 1 Ah*Bh, pass 2 Al*Bh
#pragma unroll
            for (int mt = 0; mt < 2; mt++)
#pragma unroll
                for (int nt = 0; nt < 8; nt++)
                    MMA_F16(g.acc[mt][nt], ah[cur][mt], bh[cur][nt][0], bh[cur][nt][1]);
#pragma unroll
            for (int mt = 0; mt < 2; mt++)
#pragma unroll
                for (int nt = 0; nt < 8; nt++)
                    MMA_F16(g.acc[mt][nt], al[cur][mt], bh[cur][nt][0], bh[cur][nt][1]);
        }
        __syncthreads();
        if (it + 2 < NITER) issue_stage(it + 2, it & 1);
        else CP_COMMIT();   // keep group accounting aligned
    }
}

// ---------------- GEMM -> fp32 C (O projection) ------------------------------
__global__ __launch_bounds__(256, 1) void gemm_mma_kernel(
    const __half* __restrict__ Ah, const __half* __restrict__ Al,
    const __half* __restrict__ Bh, float* __restrict__ C, int M, int N, int K)
{
    extern __shared__ __align__(128) char smem_raw[];
    GemmCtx g;
    g.lane = threadIdx.x & 31; g.wid = threadIdx.x >> 5;
    g.wm = g.wid & 3; g.wn = g.wid >> 2;
    g.bm = blockIdx.y * 128; g.bn = blockIdx.x * 128;
    gemm_mainloop(g, smem_raw, Ah, Al, Bh, K);

    const int gr = g.lane >> 2, t2 = (g.lane & 3) * 2;
#pragma unroll
    for (int mt = 0; mt < 2; mt++) {
#pragma unroll
        for (int nt = 0; nt < 8; nt++) {
            int row = g.bm + g.wm * 32 + mt * 16 + gr;
            int col = g.bn + g.wn * 64 + nt * 8 + t2;
            *(float2*)&C[(size_t)row * N + col] =
                make_float2(g.acc[mt][nt][0], g.acc[mt][nt][1]);
            *(float2*)&C[(size_t)(row + 8) * N + col] =
                make_float2(g.acc[mt][nt][2], g.acc[mt][nt][3]);
        }
    }
}

// ---------------- fused QKV GEMM: rope/scale/split epilogue ------------------
__device__ __forceinline__ void rope_split_store_h(
    __half* oh, __half* ol,
    const float* __restrict__ fc, const float* __restrict__ fs,
    int row, int col, float v0, float v1, int stride, int coloff, float scale,
    bool want_lo)
{
    int s = row & (SEQ - 1);
    int i = (col & 127) >> 1;
    float c  = __ldg(fc + s * 64 + i);
    float sn = __ldg(fs + s * 64 + i);
    float ra = (v0 * c - v1 * sn) * scale;
    float rb = (v0 * sn + v1 * c) * scale;
    uint32_t h, l;
    split_pack_h(ra, rb, h, l);
    size_t o = (size_t)row * stride + (col - coloff);
    *(uint32_t*)(oh + o) = h;
    if (want_lo) *(uint32_t*)(ol + o) = l;
}

__global__ __launch_bounds__(256, 1) void gemm_qkv_kernel(
    const __half* __restrict__ Ah, const __half* __restrict__ Al,
    const __half* __restrict__ Bh,
    const float* __restrict__ fc, const float* __restrict__ fs,
    __half* __restrict__ qh, __half* __restrict__ ql,
    __half* __restrict__ kh, __half* __restrict__ vh, int K)
{
    extern __shared__ __align__(128) char smem_raw[];
    GemmCtx g;
    g.lane = threadIdx.x & 31; g.wid = threadIdx.x >> 5;
    g.wm = g.wid & 3; g.wn = g.wid >> 2;
    g.bm = blockIdx.y * 128; g.bn = blockIdx.x * 128;
    gemm_mainloop(g, smem_raw, Ah, Al, Bh, K);

    const int gr = g.lane >> 2, t2 = (g.lane & 3) * 2;
    const float qscale = 0.0883883476483184f;  // 1/sqrt(128)

    if (g.bn < DMODEL) {            // Q: rope + scale + split (hi+lo)
#pragma unroll
        for (int mt = 0; mt < 2; mt++)
#pragma unroll
            for (int nt = 0; nt < 8; nt++) {
                int row = g.bm + g.wm * 32 + mt * 16 + gr;
                int col = g.bn + g.wn * 64 + nt * 8 + t2;
                rope_split_store_h(qh, ql, fc, fs, row, col,
                                   g.acc[mt][nt][0], g.acc[mt][nt][1], DMODEL, 0,
                                   qscale, true);
                rope_split_store_h(qh, ql, fc, fs, row + 8, col,
                                   g.acc[mt][nt][2], g.acc[mt][nt][3], DMODEL, 0,
                                   qscale, true);
            }
    } else if (g.bn < DMODEL + NKV) {  // K: rope, hi only
#pragma unroll
        for (int mt = 0; mt < 2; mt++)
#pragma unroll
            for (int nt = 0; nt < 8; nt++) {
                int row = g.bm + g.wm * 32 + mt * 16 + gr;
                int col = g.bn + g.wn * 64 + nt * 8 + t2;
                rope_split_store_h(kh, nullptr, fc, fs, row, col,
                                   g.acc[mt][nt][0], g.acc[mt][nt][1], NKV, DMODEL,
                                   1.0f, false);
                rope_split_store_h(kh, nullptr, fc, fs, row + 8, col,
                                   g.acc[mt][nt][2], g.acc[mt][nt][3], NKV, DMODEL,
                                   1.0f, false);
            }
    } else {                            // V: hi only
#pragma unroll
        for (int mt = 0; mt < 2; mt++)
#pragma unroll
            for (int nt = 0; nt < 8; nt++) {
                int row = g.bm + g.wm * 32 + mt * 16 + gr;
                int col = g.bn + g.wn * 64 + nt * 8 + t2 - (DMODEL + NKV);
                size_t o0 = (size_t)row * NKV + col;
                *(uint32_t*)(vh + o0) = pack2h(g.acc[mt][nt][0], g.acc[mt][nt][1]);
                size_t o1 = o0 + (size_t)8 * NKV;
                *(uint32_t*)(vh + o1) = pack2h(g.acc[mt][nt][2], g.acc[mt][nt][3]);
            }
    }
}

// ---------------- fp32 -> fp16 hi/lo split (x) --------------------------------
__global__ __launch_bounds__(256) void convert_split_kernel(
    const float* __restrict__ in, __half* __restrict__ oh,
    __half* __restrict__ ol, int n4)
{
    int i = blockIdx.x * blockDim.x + threadIdx.x;
    if (i >= n4) return;
    float4 v = ((const float4*)in)[i];
    uint32_t h0, l0, h1, l1;
    split_pack_h(v.x, v.y, h0, l0);
    split_pack_h(v.z, v.w, h1, l1);
    ((uint2*)oh)[i] = make_uint2(h0, h1);
    ((uint2*)ol)[i] = make_uint2(l0, l1);
}

// ---------------- fp32 [K,N] -> transposed fp16 [N,K] (hi only) --------------
__global__ __launch_bounds__(256) void transpose_h_kernel(
    const float* __restrict__ in, __half* __restrict__ oh, int K, int N)
{
    __shared__ float tile[32][33];
    const int k0 = blockIdx.y * 32, n0 = blockIdx.x * 32;
    const int tx = threadIdx.x & 31, ty = threadIdx.x >> 5;
#pragma unroll
    for (int i = 0; i < 32; i += 8)
        tile[ty + i][tx] = in[(size_t)(k0 + ty + i) * N + n0 + tx];
    __syncthreads();
#pragma unroll
    for (int i = 0; i < 32; i += 8) {
        float v = tile[tx][ty + i];
        oh[(size_t)(n0 + ty + i) * K + k0 + tx] = __float2half_rn(v);
    }
}

// ---------------- flash attention via mma.sync (fp16, A-side split) ----------
// BM=64, 4 warps x 16 rows, 2 CTAs/SM. Q hi+lo; K,V hi only.
// blockIdx.x reversed so heavy (large-qt) causal tiles launch first.
#define FP 272
#define FQH 0
#define FQL 17408
#define FKH 34816
#define FVH 52224
#define FLASH_SMEM 69632

__global__ __launch_bounds__(128, 2) void flash_mma_kernel(
    const __half* __restrict__ Qh, const __half* __restrict__ Ql,
    const __half* __restrict__ Kh, const __half* __restrict__ Vh,
    __half* __restrict__ Oh, __half* __restrict__ Ol)
{
    extern __shared__ __align__(128) char sm[];
    const uint32_t sb = smem_to_u32(sm);
    const int qt = gridDim.x - 1 - blockIdx.x;   // heavy tiles first
    const int h = blockIdx.y, b = blockIdx.z;
    const int kvh = h >> 2;
    const int tid = threadIdx.x, lane = tid & 31, w = tid >> 5;
    const int q0 = qt * 64;

    const int lrow = (lane & 7) + ((lane >> 3) & 1) * 8;
    const int lk   = (lane >> 4) * 8;
    const int nrow = (lane >> 4) * 8 + (lane & 7);
    const int kadd = ((lane >> 3) & 1) * 8;
    const int trow = lane & 15;
    const int tcol = (lane >> 4) * 8;

    {
        const size_t qoff = ((size_t)(b * SEQ + q0) * NQH + h) * HDIM;
        const uint4* gh = (const uint4*)(Qh + qoff);
        const uint4* gl = (const uint4*)(Ql + qoff);
        for (int i = tid; i < 1024; i += 128) {
            int r = i >> 4, c = i & 15;
            *(uint4*)(sm + FQH + r * FP + c * 16) = gh[(size_t)r * 512 + c];
            *(uint4*)(sm + FQL + r * FP + c * 16) = gl[(size_t)r * 512 + c];
        }
    }

    float m0 = -1e30f, m1 = -1e30f, l0 = 0.f, l1 = 0.f;
    float oacc[16][4];
#pragma unroll
    for (int nt = 0; nt < 16; nt++)
#pragma unroll
        for (int j = 0; j < 4; j++) oacc[nt][j] = 0.f;

    const int row0 = q0 + w * 16 + (lane >> 2);
    const int cb   = 2 * (lane & 3);
    const int ktiles = qt + 1;

    for (int kt = 0; kt < ktiles; kt++) {
        __syncthreads();
        {
            const size_t off = ((size_t)(b * SEQ + kt * 64) * NKVH + kvh) * HDIM;
            const uint4* gkh = (const uint4*)(Kh + off);
            const uint4* gvh = (const uint4*)(Vh + off);
            for (int i = tid; i < 1024; i += 128) {
                int r = i >> 4, c = i & 15;
                uint32_t d = r * FP + c * 16;
                size_t gg = (size_t)r * 128 + c;
                *(uint4*)(sm + FKH + d) = gkh[gg];
                *(uint4*)(sm + FVH + d) = gvh[gg];
            }
        }
        __syncthreads();

        float s[8][4];
#pragma unroll
        for (int nt = 0; nt < 8; nt++)
#pragma unroll
            for (int j = 0; j < 4; j++) s[nt][j] = 0.f;

#pragma unroll
        for (int ks = 0; ks < 8; ks++) {
            uint32_t ah[4], al[4];
            uint32_t aa = sb + FQH + (w * 16 + lrow) * FP + (ks * 16 + lk) * 2;
            LDMATRIX_X4(ah[0], ah[1], ah[2], ah[3], aa);
            LDMATRIX_X4(al[0], al[1], al[2], al[3], aa + (FQL - FQH));
            uint32_t bh[8][2];
#pragma unroll
            for (int p = 0; p < 4; p++) {
                uint32_t ba = sb + FKH + (p * 16 + nrow) * FP + (ks * 16 + kadd) * 2;
                LDMATRIX_X4(bh[2*p][0], bh[2*p][1], bh[2*p+1][0], bh[2*p+1][1], ba);
            }
#pragma unroll
            for (int nt = 0; nt < 8; nt++) MMA_F16(s[nt], ah, bh[nt][0], bh[nt][1]);
#pragma unroll
            for (int nt = 0; nt < 8; nt++) MMA_F16(s[nt], al, bh[nt][0], bh[nt][1]);
        }

        if (kt == qt) {
            const int colb = kt * 64 + cb;
#pragma unroll
            for (int nt = 0; nt < 8; nt++) {
                int c0 = colb + 8 * nt;
                if (c0 > row0)     s[nt][0] = -1e30f;
                if (c0 + 1 > row0) s[nt][1] = -1e30f;
                if (c0 > row0 + 8)     s[nt][2] = -1e30f;
                if (c0 + 1 > row0 + 8) s[nt][3] = -1e30f;
            }
        }

        float mt0 = -1e30f, mt1 = -1e30f;
#pragma unroll
        for (int nt = 0; nt < 8; nt++) {
            mt0 = fmaxf(mt0, fmaxf(s[nt][0], s[nt][1]));
            mt1 = fmaxf(mt1, fmaxf(s[nt][2], s[nt][3]));
        }
        mt0 = fmaxf(mt0, __shfl_xor_sync(0xffffffffu, mt0, 1));
        mt0 = fmaxf(mt0, __shfl_xor_sync(0xffffffffu, mt0, 2));
        mt1 = fmaxf(mt1, __shfl_xor_sync(0xffffffffu, mt1, 1));
        mt1 = fmaxf(mt1, __shfl_xor_sync(0xffffffffu, mt1, 2));
        float mn0 = fmaxf(m0, mt0), mn1 = fmaxf(m1, mt1);
        float a0 = __expf(m0 - mn0), a1 = __expf(m1 - mn1);
        float ps0 = 0.f, ps1 = 0.f;
#pragma unroll
        for (int nt = 0; nt < 8; nt++) {
            s[nt][0] = __expf(s[nt][0] - mn0);
            s[nt][1] = __expf(s[nt][1] - mn0);
            s[nt][2] = __expf(s[nt][2] - mn1);
            s[nt][3] = __expf(s[nt][3] - mn1);
            ps0 += s[nt][0] + s[nt][1];
            ps1 += s[nt][2] + s[nt][3];
        }
        ps0 += __shfl_xor_sync(0xffffffffu, ps0, 1);
        ps0 += __shfl_xor_sync(0xffffffffu, ps0, 2);
        ps1 += __shfl_xor_sync(0xffffffffu, ps1, 1);
        ps1 += __shfl_xor_sync(0xffffffffu, ps1, 2);
        l0 = l0 * a0 + ps0;  m0 = mn0;
        l1 = l1 * a1 + ps1;  m1 = mn1;
#pragma unroll
        for (int nt = 0; nt < 16; nt++) {
            oacc[nt][0] *= a0; oacc[nt][1] *= a0;
            oacc[nt][2] *= a1; oacc[nt][3] *= a1;
        }

        // O += Ph*Vh + Pl*Vh (P residual corrected; V hi only)
#pragma unroll
        for (int j = 0; j < 4; j++) {
            uint32_t ph[4], pl[4];
            split_pack_h(s[2*j][0],   s[2*j][1],   ph[0], pl[0]);
            split_pack_h(s[2*j][2],   s[2*j][3],   ph[1], pl[1]);
            split_pack_h(s[2*j+1][0], s[2*j+1][1], ph[2], pl[2]);
            split_pack_h(s[2*j+1][2], s[2*j+1][3], ph[3], pl[3]);
            uint32_t vfh[8][4];
#pragma unroll
            for (int t = 0; t < 8; t++) {
                uint32_t va = sb + FVH + (j * 16 + trow) * FP + (t * 16 + tcol) * 2;
                LDMATRIX_X4_T(vfh[t][0], vfh[t][1], vfh[t][2], vfh[t][3], va);
            }
#pragma unroll
            for (int t = 0; t < 8; t++) {
                MMA_F16(oacc[2*t],   ph, vfh[t][0], vfh[t][1]);
                MMA_F16(oacc[2*t+1], ph, vfh[t][2], vfh[t][3]);
            }
#pragma unroll
            for (int t = 0; t < 8; t++) {
                MMA_F16(oacc[2*t],   pl, vfh[t][0], vfh[t][1]);
                MMA_F16(oacc[2*t+1], pl, vfh[t][2], vfh[t][3]);
            }
        }
    }

    const float inv0 = 1.f / l0, inv1 = 1.f / l1;
    const size_t o0 = ((size_t)(b * SEQ + row0)) * DMODEL + h * HDIM + cb;
    const size_t o1 = ((size_t)(b * SEQ + row0 + 8)) * DMODEL + h * HDIM + cb;
#pragma unroll
    for (int nt = 0; nt < 16; nt++) {
        uint32_t hh, ll;
        split_pack_h(oacc[nt][0] * inv0, oacc[nt][1] * inv0, hh, ll);
        *(uint32_t*)(Oh + o0 + 8 * nt) = hh;
        *(uint32_t*)(Ol + o0 + 8 * nt) = ll;
        split_pack_h(oacc[nt][2] * inv1, oacc[nt][3] * inv1, hh, ll);
        *(uint32_t*)(Oh + o1 + 8 * nt) = hh;
        *(uint32_t*)(Ol + o1 + 8 * nt) = ll;
    }
}

// ---------------- host launcher ---------------------------------------------
extern "C" void kernel_launch(void* const* d_in, const int* in_sizes, int n_in,
                              void* d_out, int out_size)
{
    const float* x   = (const float*)d_in[0];
    const float* w_q = (const float*)d_in[1];
    const float* w_k = (const float*)d_in[2];
    const float* w_v = (const float*)d_in[3];
    const float* w_o = (const float*)d_in[4];
    const float* fc  = (const float*)d_in[5];
    const float* fs  = (const float*)d_in[6];
    float* out = (float*)d_out;

    __half *xh, *xl, *wqkvh, *woh, *ath, *atl, *qsh, *qsl, *ksh, *vsh;
    cudaGetSymbolAddress((void**)&xh,    g_xh);     cudaGetSymbolAddress((void**)&xl,  g_xl);
    cudaGetSymbolAddress((void**)&wqkvh, g_wqkv_h);
    cudaGetSymbolAddress((void**)&woh,   g_wot_h);
    cudaGetSymbolAddress((void**)&ath,   g_atth);   cudaGetSymbolAddress((void**)&atl, g_attl);
    cudaGetSymbolAddress((void**)&qsh,   g_qsh);    cudaGetSymbolAddress((void**)&qsl, g_qsl);
    cudaGetSymbolAddress((void**)&ksh,   g_ksh);    cudaGetSymbolAddress((void**)&vsh, g_vsh);

    cudaFuncSetAttribute(gemm_mma_kernel, cudaFuncAttributeMaxDynamicSharedMemorySize, GEMM_SMEM);
    cudaFuncSetAttribute(gemm_qkv_kernel, cudaFuncAttributeMaxDynamicSharedMemorySize, GEMM_SMEM);
    cudaFuncSetAttribute(flash_mma_kernel, cudaFuncAttributeMaxDynamicSharedMemorySize, FLASH_SMEM);

    const int M = BATCH * SEQ;  // 4096

    // weight transposes (hi only) into combined [6144,4096] and wot
    transpose_h_kernel<<<dim3(DMODEL / 32, DMODEL / 32), 256>>>(w_q, wqkvh, DMODEL, DMODEL);
    transpose_h_kernel<<<dim3(NKV / 32, DMODEL / 32), 256>>>(
        w_k, wqkvh + (size_t)DMODEL * DMODEL, DMODEL, NKV);
    transpose_h_kernel<<<dim3(NKV / 32, DMODEL / 32), 256>>>(
        w_v, wqkvh + (size_t)(DMODEL + NKV) * DMODEL, DMODEL, NKV);
    transpose_h_kernel<<<dim3(DMODEL / 32, DMODEL / 32), 256>>>(w_o, woh, DMODEL, DMODEL);

    // x split (hi + lo)
    {
        int n4 = (M * DMODEL) / 4;
        convert_split_kernel<<<(n4 + 255) / 256, 256>>>(x, xh, xl, n4);
    }

    // fused QKV projection + rope + split (one GEMM over N=6144)
    gemm_qkv_kernel<<<dim3(NQKV / 128, M / 128), 256, GEMM_SMEM>>>(
        xh, xl, wqkvh, fc, fs, qsh, qsl, ksh, vsh, DMODEL);

    // flash attention (heavy tiles first)
    flash_mma_kernel<<<dim3(SEQ / 64, NQH, BATCH), 128, FLASH_SMEM>>>(
        qsh, qsl, ksh, vsh, ath, atl);

    // O projection
    gemm_mma_kernel<<<dim3(DMODEL / 128, M / 128), 256, GEMM_SMEM>>>(
        ath, atl, woh, out, M, DMODEL, DMODEL);
}

// round 11
// speedup vs baseline: 4.1734x; 1.0135x over previous
#include <cuda_runtime.h>
#include <cuda_fp16.h>
#include <math.h>
#include <stdint.h>

#define BATCH 2
#define SEQ 2048
#define DMODEL 4096
#define NQH 32
#define NKVH 8
#define HDIM 128
#define NKV (NKVH * HDIM)        // 1024
#define NQKV (DMODEL + 2 * NKV)  // 6144

// ---------------- scratch (device globals; allocation-free) ----------------
__device__ __half g_xh[(size_t)BATCH * SEQ * DMODEL];
__device__ __half g_xl[(size_t)BATCH * SEQ * DMODEL];
__device__ __half g_wqkv_h[(size_t)NQKV * DMODEL];   // [6144,4096] rows: q,k,v (hi only)
__device__ __half g_wot_h[(size_t)DMODEL * DMODEL];
__device__ __half g_atth[(size_t)BATCH * SEQ * DMODEL];
__device__ __half g_attl[(size_t)BATCH * SEQ * DMODEL];

__device__ __half g_qsh[(size_t)BATCH * SEQ * NQH * HDIM];
__device__ __half g_qsl[(size_t)BATCH * SEQ * NQH * HDIM];
__device__ __half g_ksh[(size_t)BATCH * SEQ * NKV];   // hi only
__device__ __half g_vsh[(size_t)BATCH * SEQ * NKV];   // hi only

__device__ __forceinline__ uint32_t smem_to_u32(const void* p) {
    uint32_t a;
    asm("{ .reg .u64 t; cvta.to.shared.u64 t, %1; cvt.u32.u64 %0, t; }"
        : "=r"(a) : "l"(p));
    return a;
}

#define CP_ASYNC_16(dst, src) \
    asm volatile("cp.async.cg.shared.global [%0], [%1], 16;" :: "r"(dst), "l"(src) : "memory")
#define CP_COMMIT() asm volatile("cp.async.commit_group;" ::: "memory")
#define CP_WAIT_1()  asm volatile("cp.async.wait_group 1;" ::: "memory")

#define LDMATRIX_X4(r0, r1, r2, r3, addr) \
    asm volatile("ldmatrix.sync.aligned.m8n8.x4.shared.b16 {%0,%1,%2,%3}, [%4];" \
        : "=r"(r0), "=r"(r1), "=r"(r2), "=r"(r3) : "r"(addr))
#define LDMATRIX_X4_T(r0, r1, r2, r3, addr) \
    asm volatile("ldmatrix.sync.aligned.m8n8.x4.trans.shared.b16 {%0,%1,%2,%3}, [%4];" \
        : "=r"(r0), "=r"(r1), "=r"(r2), "=r"(r3) : "r"(addr))

#define MMA_F16(d, a, b0, b1) \
    asm("mma.sync.aligned.m16n8k16.row.col.f32.f16.f16.f32 " \
        "{%0,%1,%2,%3}, {%4,%5,%6,%7}, {%8,%9}, {%0,%1,%2,%3};" \
        : "+f"((d)[0]), "+f"((d)[1]), "+f"((d)[2]), "+f"((d)[3]) \
        : "r"((a)[0]), "r"((a)[1]), "r"((a)[2]), "r"((a)[3]), "r"(b0), "r"(b1))

__device__ __forceinline__ uint32_t pack2h(float a, float b) {
    __half2 t = __floats2half2_rn(a, b);
    return *reinterpret_cast<uint32_t*>(&t);
}
__device__ __forceinline__ void split_pack_h(float a, float b, uint32_t& h, uint32_t& l) {
    __half ha = __float2half_rn(a), hb = __float2half_rn(b);
    h = pack2h(__half2float(ha), __half2float(hb));
    l = pack2h(a - __half2float(ha), b - __half2float(hb));
}

// ---------------- shared GEMM mainloop (device inline) -----------------------
// TBK=128, 2 stages of 3 tiles (Ah, Al, Bh), pitch 272B (17x16B, conflict-free).
#define TBK 128
#define APITCH 272
#define TILE_B (128 * APITCH)          // 34816
#define STAGE_B (3 * TILE_B)           // 104448
#define GEMM_SMEM (2 * STAGE_B)        // 208896

struct GemmCtx {
    float acc[2][8][4];
    int lane, wid, wm, wn, bm, bn;
};

__device__ __forceinline__ void gemm_mainloop(
    GemmCtx& g, char* smem_raw,
    const __half* __restrict__ Ah, const __half* __restrict__ Al,
    const __half* __restrict__ Bh, int K)
{
    const uint32_t sbase = smem_to_u32(smem_raw);
    const int tid = threadIdx.x;
    const int lane = g.lane, wm = g.wm, wn = g.wn, bm = g.bm, bn = g.bn;

    const __half* gsrc[3] = {Ah, Al, Bh};
    const int rbase3[3] = {bm, bm, bn};

    auto issue_stage = [&](int it, int buf) {
        const int k0 = it * TBK;
#pragma unroll
        for (int t = 0; t < 3; t++) {
            const __half* gp = gsrc[t] + (size_t)rbase3[t] * K + k0;
            const uint32_t db = sbase + buf * STAGE_B + t * TILE_B;
#pragma unroll
            for (int i = 0; i < 8; i++) {
                int c = i * 256 + tid;          // 2048 chunks of 16B per tile
                int r = c >> 4, ch = c & 15;
                const void* src = gp + (size_t)r * K + ch * 8;
                uint32_t dst = db + r * APITCH + ch * 16;
                CP_ASYNC_16(dst, src);
            }
        }
        CP_COMMIT();
    };

    const int lrow = (lane & 7) + ((lane >> 3) & 1) * 8;
    const int lk   = (lane >> 4) * 8;
    const int nrow = (lane >> 4) * 8 + (lane & 7);
    const int kadd = ((lane >> 3) & 1) * 8;

    // frag loader for one k16 quarter (A hi+lo, B hi)
    auto load_q = [&](uint32_t base, int kk,
                      uint32_t a_h[2][4], uint32_t a_l[2][4], uint32_t b_h[8][2]) {
#pragma unroll
        for (int p = 0; p < 4; p++) {
            uint32_t ab = base + 2 * TILE_B +
                          (wn * 64 + p * 16 + nrow) * APITCH + (kk * 16 + kadd) * 2;
            LDMATRIX_X4(b_h[2*p][0], b_h[2*p][1], b_h[2*p+1][0], b_h[2*p+1][1], ab);
        }
#pragma unroll
        for (int mt = 0; mt < 2; mt++) {
            uint32_t aa = base + (wm * 32 + mt * 16 + lrow) * APITCH +
                          (kk * 16 + lk) * 2;
            LDMATRIX_X4(a_h[mt][0], a_h[mt][1], a_h[mt][2], a_h[mt][3], aa);
            LDMATRIX_X4(a_l[mt][0], a_l[mt][1], a_l[mt][2], a_l[mt][3],
                        aa + TILE_B);
        }
    };

#pragma unroll
    for (int mt = 0; mt < 2; mt++)
#pragma unroll
        for (int nt = 0; nt < 8; nt++)
#pragma unroll
            for (int j = 0; j < 4; j++) g.acc[mt][nt][j] = 0.f;

    const int NITER = K / TBK;   // 32
    issue_stage(0, 0);
    issue_stage(1, 1);

    for (int it = 0; it < NITER; it++) {
        CP_WAIT_1();
        __syncthreads();
        const uint32_t base = sbase + (it & 1) * STAGE_B;

        uint32_t ah[2][2][4], al[2][2][4], bh[2][8][2];
        load_q(base, 0, ah[0], al[0], bh[0]);
#pragma unroll
        for (int kk = 0; kk < 8; kk++) {
            const int cur = kk & 1, nxt = cur ^ 1;
            if (kk < 7) load_q(base, kk + 1, ah[nxt], al[nxt], bh[nxt]);
            // term-major: pass 1 Ah*Bh, pass 2 Al*Bh
#pragma unroll
            for (int mt = 0; mt < 2; mt++)
#pragma unroll
                for (int nt = 0; nt < 8; nt++)
                    MMA_F16(g.acc[mt][nt], ah[cur][mt], bh[cur][nt][0], bh[cur][nt][1]);
#pragma unroll
            for (int mt = 0; mt < 2; mt++)
#pragma unroll
                for (int nt = 0; nt < 8; nt++)
                    MMA_F16(g.acc[mt][nt], al[cur][mt], bh[cur][nt][0], bh[cur][nt][1]);
        }
        __syncthreads();
        if (it + 2 < NITER) issue_stage(it + 2, it & 1);
        else CP_COMMIT();   // keep group accounting aligned
    }
}

// ---------------- GEMM -> fp32 C (O projection) ------------------------------
__global__ __launch_bounds__(256, 1) void gemm_mma_kernel(
    const __half* __restrict__ Ah, const __half* __restrict__ Al,
    const __half* __restrict__ Bh, float* __restrict__ C, int M, int N, int K)
{
    extern __shared__ __align__(128) char smem_raw[];
    GemmCtx g;
    g.lane = threadIdx.x & 31; g.wid = threadIdx.x >> 5;
    g.wm = g.wid & 3; g.wn = g.wid >> 2;
    g.bm = blockIdx.y * 128; g.bn = blockIdx.x * 128;
    gemm_mainloop(g, smem_raw, Ah, Al, Bh, K);

    const int gr = g.lane >> 2, t2 = (g.lane & 3) * 2;
#pragma unroll
    for (int mt = 0; mt < 2; mt++) {
#pragma unroll
        for (int nt = 0; nt < 8; nt++) {
            int row = g.bm + g.wm * 32 + mt * 16 + gr;
            int col = g.bn + g.wn * 64 + nt * 8 + t2;
            *(float2*)&C[(size_t)row * N + col] =
                make_float2(g.acc[mt][nt][0], g.acc[mt][nt][1]);
            *(float2*)&C[(size_t)(row + 8) * N + col] =
                make_float2(g.acc[mt][nt][2], g.acc[mt][nt][3]);
        }
    }
}

// ---------------- fused QKV GEMM: rope/scale/split epilogue ------------------
__device__ __forceinline__ void rope_split_store_h(
    __half* oh, __half* ol,
    const float* __restrict__ fc, const float* __restrict__ fs,
    int row, int col, float v0, float v1, int stride, int coloff, float scale,
    bool want_lo)
{
    int s = row & (SEQ - 1);
    int i = (col & 127) >> 1;
    float c  = __ldg(fc + s * 64 + i);
    float sn = __ldg(fs + s * 64 + i);
    float ra = (v0 * c - v1 * sn) * scale;
    float rb = (v0 * sn + v1 * c) * scale;
    uint32_t h, l;
    split_pack_h(ra, rb, h, l);
    size_t o = (size_t)row * stride + (col - coloff);
    *(uint32_t*)(oh + o) = h;
    if (want_lo) *(uint32_t*)(ol + o) = l;
}

__global__ __launch_bounds__(256, 1) void gemm_qkv_kernel(
    const __half* __restrict__ Ah, const __half* __restrict__ Al,
    const __half* __restrict__ Bh,
    const float* __restrict__ fc, const float* __restrict__ fs,
    __half* __restrict__ qh, __half* __restrict__ ql,
    __half* __restrict__ kh, __half* __restrict__ vh, int K)
{
    extern __shared__ __align__(128) char smem_raw[];
    GemmCtx g;
    g.lane = threadIdx.x & 31; g.wid = threadIdx.x >> 5;
    g.wm = g.wid & 3; g.wn = g.wid >> 2;
    g.bm = blockIdx.y * 128; g.bn = blockIdx.x * 128;
    gemm_mainloop(g, smem_raw, Ah, Al, Bh, K);

    const int gr = g.lane >> 2, t2 = (g.lane & 3) * 2;
    const float qscale = 0.0883883476483184f;  // 1/sqrt(128)

    if (g.bn < DMODEL) {            // Q: rope + scale + split (hi+lo)
#pragma unroll
        for (int mt = 0; mt < 2; mt++)
#pragma unroll
            for (int nt = 0; nt < 8; nt++) {
                int row = g.bm + g.wm * 32 + mt * 16 + gr;
                int col = g.bn + g.wn * 64 + nt * 8 + t2;
                rope_split_store_h(qh, ql, fc, fs, row, col,
                                   g.acc[mt][nt][0], g.acc[mt][nt][1], DMODEL, 0,
                                   qscale, true);
                rope_split_store_h(qh, ql, fc, fs, row + 8, col,
                                   g.acc[mt][nt][2], g.acc[mt][nt][3], DMODEL, 0,
                                   qscale, true);
            }
    } else if (g.bn < DMODEL + NKV) {  // K: rope, hi only
#pragma unroll
        for (int mt = 0; mt < 2; mt++)
#pragma unroll
            for (int nt = 0; nt < 8; nt++) {
                int row = g.bm + g.wm * 32 + mt * 16 + gr;
                int col = g.bn + g.wn * 64 + nt * 8 + t2;
                rope_split_store_h(kh, nullptr, fc, fs, row, col,
                                   g.acc[mt][nt][0], g.acc[mt][nt][1], NKV, DMODEL,
                                   1.0f, false);
                rope_split_store_h(kh, nullptr, fc, fs, row + 8, col,
                                   g.acc[mt][nt][2], g.acc[mt][nt][3], NKV, DMODEL,
                                   1.0f, false);
            }
    } else {                            // V: hi only
#pragma unroll
        for (int mt = 0; mt < 2; mt++)
#pragma unroll
            for (int nt = 0; nt < 8; nt++) {
                int row = g.bm + g.wm * 32 + mt * 16 + gr;
                int col = g.bn + g.wn * 64 + nt * 8 + t2 - (DMODEL + NKV);
                size_t o0 = (size_t)row * NKV + col;
                *(uint32_t*)(vh + o0) = pack2h(g.acc[mt][nt][0], g.acc[mt][nt][1]);
                size_t o1 = o0 + (size_t)8 * NKV;
                *(uint32_t*)(vh + o1) = pack2h(g.acc[mt][nt][2], g.acc[mt][nt][3]);
            }
    }
}

// ---------------- fp32 -> fp16 hi/lo split (x) --------------------------------
__global__ __launch_bounds__(256) void convert_split_kernel(
    const float* __restrict__ in, __half* __restrict__ oh,
    __half* __restrict__ ol, int n4)
{
    int i = blockIdx.x * blockDim.x + threadIdx.x;
    if (i >= n4) return;
    float4 v = ((const float4*)in)[i];
    uint32_t h0, l0, h1, l1;
    split_pack_h(v.x, v.y, h0, l0);
    split_pack_h(v.z, v.w, h1, l1);
    ((uint2*)oh)[i] = make_uint2(h0, h1);
    ((uint2*)ol)[i] = make_uint2(l0, l1);
}

// ---------------- fp32 [K,N] -> transposed fp16 [N,K] (hi only) --------------
__global__ __launch_bounds__(256) void transpose_h_kernel(
    const float* __restrict__ in, __half* __restrict__ oh, int K, int N)
{
    __shared__ float tile[32][33];
    const int k0 = blockIdx.y * 32, n0 = blockIdx.x * 32;
    const int tx = threadIdx.x & 31, ty = threadIdx.x >> 5;
#pragma unroll
    for (int i = 0; i < 32; i += 8)
        tile[ty + i][tx] = in[(size_t)(k0 + ty + i) * N + n0 + tx];
    __syncthreads();
#pragma unroll
    for (int i = 0; i < 32; i += 8) {
        float v = tile[tx][ty + i];
        oh[(size_t)(n0 + ty + i) * K + k0 + tx] = __float2half_rn(v);
    }
}

// ---------------- flash attention via mma.sync (fp16, A-side split) ----------
// BM=64, 4 warps x 16 rows, 2 CTAs/SM. Q hi+lo; K,V hi only.
// K/V loads via cp.async double buffering; heavy causal tiles launch first.
#define FP 272
#define FQH 0
#define FQL 17408
#define FKV0 34816            // buf0: K at +0, V at +17408
#define KVBUF_B 34816         // one K+V buffer
#define FLASH_SMEM 104448     // Q(2) + 2 x (K+V)

__global__ __launch_bounds__(128, 2) void flash_mma_kernel(
    const __half* __restrict__ Qh, const __half* __restrict__ Ql,
    const __half* __restrict__ Kh, const __half* __restrict__ Vh,
    __half* __restrict__ Oh, __half* __restrict__ Ol)
{
    extern __shared__ __align__(128) char sm[];
    const uint32_t sb = smem_to_u32(sm);
    const int qt = gridDim.x - 1 - blockIdx.x;   // heavy tiles first
    const int h = blockIdx.y, b = blockIdx.z;
    const int kvh = h >> 2;
    const int tid = threadIdx.x, lane = tid & 31, w = tid >> 5;
    const int q0 = qt * 64;

    const int lrow = (lane & 7) + ((lane >> 3) & 1) * 8;
    const int lk   = (lane >> 4) * 8;
    const int nrow = (lane >> 4) * 8 + (lane & 7);
    const int kadd = ((lane >> 3) & 1) * 8;
    const int trow = lane & 15;
    const int tcol = (lane >> 4) * 8;

    // cp.async K+V tile issue into buffer `buf`.
    // Token row stride is NKV halfs (off already includes kvh*HDIM).
    auto issue_kv = [&](int kt, int buf) {
        const size_t off = ((size_t)(b * SEQ + kt * 64) * NKVH + kvh) * HDIM;
        const __half* gk = Kh + off;
        const __half* gv = Vh + off;
        const uint32_t kb = sb + FKV0 + buf * KVBUF_B;
#pragma unroll
        for (int i = 0; i < 8; i++) {
            int c = i * 128 + tid;          // 1024 chunks per tile
            int r = c >> 4, ch = c & 15;
            uint32_t d = r * FP + ch * 16;
            CP_ASYNC_16(kb + d,         gk + (size_t)r * NKV + ch * 8);
            CP_ASYNC_16(kb + 17408 + d, gv + (size_t)r * NKV + ch * 8);
        }
        CP_COMMIT();
    };

    // Q hi/lo tile load (plain, one-time)
    {
        const size_t qoff = ((size_t)(b * SEQ + q0) * NQH + h) * HDIM;
        const uint4* gh = (const uint4*)(Qh + qoff);
        const uint4* gl = (const uint4*)(Ql + qoff);
        for (int i = tid; i < 1024; i += 128) {
            int r = i >> 4, c = i & 15;
            *(uint4*)(sm + FQH + r * FP + c * 16) = gh[(size_t)r * 512 + c];
            *(uint4*)(sm + FQL + r * FP + c * 16) = gl[(size_t)r * 512 + c];
        }
    }

    float m0 = -1e30f, m1 = -1e30f, l0 = 0.f, l1 = 0.f;
    float oacc[16][4];
#pragma unroll
    for (int nt = 0; nt < 16; nt++)
#pragma unroll
        for (int j = 0; j < 4; j++) oacc[nt][j] = 0.f;

    const int row0 = q0 + w * 16 + (lane >> 2);
    const int cb   = 2 * (lane & 3);
    const int ktiles = qt + 1;

    issue_kv(0, 0);

    for (int kt = 0; kt < ktiles; kt++) {
        if (kt + 1 < ktiles) issue_kv(kt + 1, (kt + 1) & 1);
        else CP_COMMIT();               // empty group keeps wait_1 semantics
        CP_WAIT_1();                    // tile kt resident
        __syncthreads();
        const uint32_t FKHb = FKV0 + (kt & 1) * KVBUF_B;
        const uint32_t FVHb = FKHb + 17408;

        float s[8][4];
#pragma unroll
        for (int nt = 0; nt < 8; nt++)
#pragma unroll
            for (int j = 0; j < 4; j++) s[nt][j] = 0.f;

#pragma unroll
        for (int ks = 0; ks < 8; ks++) {
            uint32_t ah[4], al[4];
            uint32_t aa = sb + FQH + (w * 16 + lrow) * FP + (ks * 16 + lk) * 2;
            LDMATRIX_X4(ah[0], ah[1], ah[2], ah[3], aa);
            LDMATRIX_X4(al[0], al[1], al[2], al[3], aa + (FQL - FQH));
            uint32_t bh[8][2];
#pragma unroll
            for (int p = 0; p < 4; p++) {
                uint32_t ba = sb + FKHb + (p * 16 + nrow) * FP + (ks * 16 + kadd) * 2;
                LDMATRIX_X4(bh[2*p][0], bh[2*p][1], bh[2*p+1][0], bh[2*p+1][1], ba);
            }
#pragma unroll
            for (int nt = 0; nt < 8; nt++) MMA_F16(s[nt], ah, bh[nt][0], bh[nt][1]);
#pragma unroll
            for (int nt = 0; nt < 8; nt++) MMA_F16(s[nt], al, bh[nt][0], bh[nt][1]);
        }

        if (kt == qt) {
            const int colb = kt * 64 + cb;
#pragma unroll
            for (int nt = 0; nt < 8; nt++) {
                int c0 = colb + 8 * nt;
                if (c0 > row0)     s[nt][0] = -1e30f;
                if (c0 + 1 > row0) s[nt][1] = -1e30f;
                if (c0 > row0 + 8)     s[nt][2] = -1e30f;
                if (c0 + 1 > row0 + 8) s[nt][3] = -1e30f;
            }
        }

        float mt0 = -1e30f, mt1 = -1e30f;
#pragma unroll
        for (int nt = 0; nt < 8; nt++) {
            mt0 = fmaxf(mt0, fmaxf(s[nt][0], s[nt][1]));
            mt1 = fmaxf(mt1, fmaxf(s[nt][2], s[nt][3]));
        }
        mt0 = fmaxf(mt0, __shfl_xor_sync(0xffffffffu, mt0, 1));
        mt0 = fmaxf(mt0, __shfl_xor_sync(0xffffffffu, mt0, 2));
        mt1 = fmaxf(mt1, __shfl_xor_sync(0xffffffffu, mt1, 1));
        mt1 = fmaxf(mt1, __shfl_xor_sync(0xffffffffu, mt1, 2));
        float mn0 = fmaxf(m0, mt0), mn1 = fmaxf(m1, mt1);
        float a0 = __expf(m0 - mn0), a1 = __expf(m1 - mn1);
        float ps0 = 0.f, ps1 = 0.f;
#pragma unroll
        for (int nt = 0; nt < 8; nt++) {
            s[nt][0] = __expf(s[nt][0] - mn0);
            s[nt][1] = __expf(s[nt][1] - mn0);
            s[nt][2] = __expf(s[nt][2] - mn1);
            s[nt][3] = __expf(s[nt][3] - mn1);
            ps0 += s[nt][0] + s[nt][1];
            ps1 += s[nt][2] + s[nt][3];
        }
        ps0 += __shfl_xor_sync(0xffffffffu, ps0, 1);
        ps0 += __shfl_xor_sync(0xffffffffu, ps0, 2);
        ps1 += __shfl_xor_sync(0xffffffffu, ps1, 1);
        ps1 += __shfl_xor_sync(0xffffffffu, ps1, 2);
        l0 = l0 * a0 + ps0;  m0 = mn0;
        l1 = l1 * a1 + ps1;  m1 = mn1;
#pragma unroll
        for (int nt = 0; nt < 16; nt++) {
            oacc[nt][0] *= a0; oacc[nt][1] *= a0;
            oacc[nt][2] *= a1; oacc[nt][3] *= a1;
        }

        // O += Ph*Vh + Pl*Vh (P residual corrected; V hi only)
#pragma unroll
        for (int j = 0; j < 4; j++) {
            uint32_t ph[4], pl[4];
            split_pack_h(s[2*j][0],   s[2*j][1],   ph[0], pl[0]);
            split_pack_h(s[2*j][2],   s[2*j][3],   ph[1], pl[1]);
            split_pack_h(s[2*j+1][0], s[2*j+1][1], ph[2], pl[2]);
            split_pack_h(s[2*j+1][2], s[2*j+1][3], ph[3], pl[3]);
            uint32_t vfh[8][4];
#pragma unroll
            for (int t = 0; t < 8; t++) {
                uint32_t va = sb + FVHb + (j * 16 + trow) * FP + (t * 16 + tcol) * 2;
                LDMATRIX_X4_T(vfh[t][0], vfh[t][1], vfh[t][2], vfh[t][3], va);
            }
#pragma unroll
            for (int t = 0; t < 8; t++) {
                MMA_F16(oacc[2*t],   ph, vfh[t][0], vfh[t][1]);
                MMA_F16(oacc[2*t+1], ph, vfh[t][2], vfh[t][3]);
            }
#pragma unroll
            for (int t = 0; t < 8; t++) {
                MMA_F16(oacc[2*t],   pl, vfh[t][0], vfh[t][1]);
                MMA_F16(oacc[2*t+1], pl, vfh[t][2], vfh[t][3]);
            }
        }
        __syncthreads();   // all smem reads of this buffer done before reuse
    }

    const float inv0 = 1.f / l0, inv1 = 1.f / l1;
    const size_t o0 = ((size_t)(b * SEQ + row0)) * DMODEL + h * HDIM + cb;
    const size_t o1 = ((size_t)(b * SEQ + row0 + 8)) * DMODEL + h * HDIM + cb;
#pragma unroll
    for (int nt = 0; nt < 16; nt++) {
        uint32_t hh, ll;
        split_pack_h(oacc[nt][0] * inv0, oacc[nt][1] * inv0, hh, ll);
        *(uint32_t*)(Oh + o0 + 8 * nt) = hh;
        *(uint32_t*)(Ol + o0 + 8 * nt) = ll;
        split_pack_h(oacc[nt][2] * inv1, oacc[nt][3] * inv1, hh, ll);
        *(uint32_t*)(Oh + o1 + 8 * nt) = hh;
        *(uint32_t*)(Ol + o1 + 8 * nt) = ll;
    }
}

// ---------------- host launcher ---------------------------------------------
extern "C" void kernel_launch(void* const* d_in, const int* in_sizes, int n_in,
                              void* d_out, int out_size)
{
    const float* x   = (const float*)d_in[0];
    const float* w_q = (const float*)d_in[1];
    const float* w_k = (const float*)d_in[2];
    const float* w_v = (const float*)d_in[3];
    const float* w_o = (const float*)d_in[4];
    const float* fc  = (const float*)d_in[5];
    const float* fs  = (const float*)d_in[6];
    float* out = (float*)d_out;

    __half *xh, *xl, *wqkvh, *woh, *ath, *atl, *qsh, *qsl, *ksh, *vsh;
    cudaGetSymbolAddress((void**)&xh,    g_xh);     cudaGetSymbolAddress((void**)&xl,  g_xl);
    cudaGetSymbolAddress((void**)&wqkvh, g_wqkv_h);
    cudaGetSymbolAddress((void**)&woh,   g_wot_h);
    cudaGetSymbolAddress((void**)&ath,   g_atth);   cudaGetSymbolAddress((void**)&atl, g_attl);
    cudaGetSymbolAddress((void**)&qsh,   g_qsh);    cudaGetSymbolAddress((void**)&qsl, g_qsl);
    cudaGetSymbolAddress((void**)&ksh,   g_ksh);    cudaGetSymbolAddress((void**)&vsh, g_vsh);

    cudaFuncSetAttribute(gemm_mma_kernel, cudaFuncAttributeMaxDynamicSharedMemorySize, GEMM_SMEM);
    cudaFuncSetAttribute(gemm_qkv_kernel, cudaFuncAttributeMaxDynamicSharedMemorySize, GEMM_SMEM);
    cudaFuncSetAttribute(flash_mma_kernel, cudaFuncAttributeMaxDynamicSharedMemorySize, FLASH_SMEM);

    const int M = BATCH * SEQ;  // 4096

    // weight transposes (hi only) into combined [6144,4096] and wot
    transpose_h_kernel<<<dim3(DMODEL / 32, DMODEL / 32), 256>>>(w_q, wqkvh, DMODEL, DMODEL);
    transpose_h_kernel<<<dim3(NKV / 32, DMODEL / 32), 256>>>(
        w_k, wqkvh + (size_t)DMODEL * DMODEL, DMODEL, NKV);
    transpose_h_kernel<<<dim3(NKV / 32, DMODEL / 32), 256>>>(
        w_v, wqkvh + (size_t)(DMODEL + NKV) * DMODEL, DMODEL, NKV);
    transpose_h_kernel<<<dim3(DMODEL / 32, DMODEL / 32), 256>>>(w_o, woh, DMODEL, DMODEL);

    // x split (hi + lo)
    {
        int n4 = (M * DMODEL) / 4;
        convert_split_kernel<<<(n4 + 255) / 256, 256>>>(x, xh, xl, n4);
    }

    // fused QKV projection + rope + split (one GEMM over N=6144)
    gemm_qkv_kernel<<<dim3(NQKV / 128, M / 128), 256, GEMM_SMEM>>>(
        xh, xl, wqkvh, fc, fs, qsh, qsl, ksh, vsh, DMODEL);

    // flash attention (cp.async K/V pipeline, heavy tiles first)
    flash_mma_kernel<<<dim3(SEQ / 64, NQH, BATCH), 128, FLASH_SMEM>>>(
        qsh, qsl, ksh, vsh, ath, atl);

    // O projection
    gemm_mma_kernel<<<dim3(DMODEL / 128, M / 128), 256, GEMM_SMEM>>>(
        ath, atl, woh, out, M, DMODEL, DMODEL);
}

// round 12
// speedup vs baseline: 4.6305x; 1.1095x over previous
#include <cuda_runtime.h>
#include <cuda_fp16.h>
#include <math.h>
#include <stdint.h>

#define BATCH 2
#define SEQ 2048
#define DMODEL 4096
#define NQH 32
#define NKVH 8
#define HDIM 128
#define NKV (NKVH * HDIM)        // 1024
#define NQKV (DMODEL + 2 * NKV)  // 6144

// ---------------- scratch (device globals; allocation-free) ----------------
__device__ __half g_xh[(size_t)BATCH * SEQ * DMODEL];
__device__ __half g_xl[(size_t)BATCH * SEQ * DMODEL];
__device__ __half g_wqkv_h[(size_t)NQKV * DMODEL];   // [6144,4096] rows: q,k,v (hi only)
__device__ __half g_wot_h[(size_t)DMODEL * DMODEL];
__device__ __half g_atth[(size_t)BATCH * SEQ * DMODEL];
__device__ __half g_attl[(size_t)BATCH * SEQ * DMODEL];

__device__ __half g_qsh[(size_t)BATCH * SEQ * NQH * HDIM];
__device__ __half g_qsl[(size_t)BATCH * SEQ * NQH * HDIM];
__device__ __half g_ksh[(size_t)BATCH * SEQ * NKV];   // hi only
__device__ __half g_vsh[(size_t)BATCH * SEQ * NKV];   // hi only

__device__ __forceinline__ uint32_t smem_to_u32(const void* p) {
    uint32_t a;
    asm("{ .reg .u64 t; cvta.to.shared.u64 t, %1; cvt.u32.u64 %0, t; }"
        : "=r"(a) : "l"(p));
    return a;
}

#define CP_ASYNC_16(dst, src) \
    asm volatile("cp.async.cg.shared.global [%0], [%1], 16;" :: "r"(dst), "l"(src) : "memory")
#define CP_COMMIT() asm volatile("cp.async.commit_group;" ::: "memory")
#define CP_WAIT_0()  asm volatile("cp.async.wait_group 0;" ::: "memory")
#define CP_WAIT_1()  asm volatile("cp.async.wait_group 1;" ::: "memory")

#define LDMATRIX_X4(r0, r1, r2, r3, addr) \
    asm volatile("ldmatrix.sync.aligned.m8n8.x4.shared.b16 {%0,%1,%2,%3}, [%4];" \
        : "=r"(r0), "=r"(r1), "=r"(r2), "=r"(r3) : "r"(addr))
#define LDMATRIX_X4_T(r0, r1, r2, r3, addr) \
    asm volatile("ldmatrix.sync.aligned.m8n8.x4.trans.shared.b16 {%0,%1,%2,%3}, [%4];" \
        : "=r"(r0), "=r"(r1), "=r"(r2), "=r"(r3) : "r"(addr))

#define MMA_F16(d, a, b0, b1) \
    asm("mma.sync.aligned.m16n8k16.row.col.f32.f16.f16.f32 " \
        "{%0,%1,%2,%3}, {%4,%5,%6,%7}, {%8,%9}, {%0,%1,%2,%3};" \
        : "+f"((d)[0]), "+f"((d)[1]), "+f"((d)[2]), "+f"((d)[3]) \
        : "r"((a)[0]), "r"((a)[1]), "r"((a)[2]), "r"((a)[3]), "r"(b0), "r"(b1))

__device__ __forceinline__ uint32_t pack2h(float a, float b) {
    __half2 t = __floats2half2_rn(a, b);
    return *reinterpret_cast<uint32_t*>(&t);
}
__device__ __forceinline__ void split_pack_h(float a, float b, uint32_t& h, uint32_t& l) {
    __half ha = __float2half_rn(a), hb = __float2half_rn(b);
    h = pack2h(__half2float(ha), __half2float(hb));
    l = pack2h(a - __half2float(ha), b - __half2float(hb));
}

// ---------------- shared GEMM mainloop (device inline) -----------------------
// TBK=64, 2 stages of 3 tiles (Ah, Al, Bh), pitch 144B; 110.6KB -> 2 CTAs/SM.
#define TBK 64
#define APITCH 144
#define TILE_B (128 * APITCH)          // 18432
#define STAGE_B (3 * TILE_B)           // 55296
#define GEMM_SMEM (2 * STAGE_B)        // 110592

struct GemmCtx {
    float acc[2][8][4];
    int lane, wid, wm, wn, bm, bn;
};

__device__ __forceinline__ void gemm_mainloop(
    GemmCtx& g, char* smem_raw,
    const __half* __restrict__ Ah, const __half* __restrict__ Al,
    const __half* __restrict__ Bh, int K)
{
    const uint32_t sbase = smem_to_u32(smem_raw);
    const int tid = threadIdx.x;
    const int lane = g.lane, wm = g.wm, wn = g.wn, bm = g.bm, bn = g.bn;

    const __half* gsrc[3] = {Ah, Al, Bh};
    const int rbase3[3] = {bm, bm, bn};

    auto issue_stage = [&](int it, int buf) {
        const int k0 = it * TBK;
#pragma unroll
        for (int t = 0; t < 3; t++) {
            const __half* gp = gsrc[t] + (size_t)rbase3[t] * K + k0;
            const uint32_t db = sbase + buf * STAGE_B + t * TILE_B;
#pragma unroll
            for (int i = 0; i < 4; i++) {
                int c = i * 256 + tid;          // 1024 chunks of 16B per tile
                int r = c >> 3, ch = c & 7;
                const void* src = gp + (size_t)r * K + ch * 8;
                uint32_t dst = db + r * APITCH + ch * 16;
                CP_ASYNC_16(dst, src);
            }
        }
        CP_COMMIT();
    };

    const int lrow = (lane & 7) + ((lane >> 3) & 1) * 8;
    const int lk   = (lane >> 4) * 8;
    const int nrow = (lane >> 4) * 8 + (lane & 7);
    const int kadd = ((lane >> 3) & 1) * 8;

    // frag loader for one k16 quarter (A hi+lo, B hi)
    auto load_q = [&](uint32_t base, int kk,
                      uint32_t a_h[2][4], uint32_t a_l[2][4], uint32_t b_h[8][2]) {
#pragma unroll
        for (int p = 0; p < 4; p++) {
            uint32_t ab = base + 2 * TILE_B +
                          (wn * 64 + p * 16 + nrow) * APITCH + (kk * 16 + kadd) * 2;
            LDMATRIX_X4(b_h[2*p][0], b_h[2*p][1], b_h[2*p+1][0], b_h[2*p+1][1], ab);
        }
#pragma unroll
        for (int mt = 0; mt < 2; mt++) {
            uint32_t aa = base + (wm * 32 + mt * 16 + lrow) * APITCH +
                          (kk * 16 + lk) * 2;
            LDMATRIX_X4(a_h[mt][0], a_h[mt][1], a_h[mt][2], a_h[mt][3], aa);
            LDMATRIX_X4(a_l[mt][0], a_l[mt][1], a_l[mt][2], a_l[mt][3],
                        aa + TILE_B);
        }
    };

#pragma unroll
    for (int mt = 0; mt < 2; mt++)
#pragma unroll
        for (int nt = 0; nt < 8; nt++)
#pragma unroll
            for (int j = 0; j < 4; j++) g.acc[mt][nt][j] = 0.f;

    const int NITER = K / TBK;   // 64
    issue_stage(0, 0);

    for (int it = 0; it < NITER; it++) {
        CP_WAIT_0();
        __syncthreads();
        if (it + 1 < NITER) issue_stage(it + 1, (it + 1) & 1);
        const uint32_t base = sbase + (it & 1) * STAGE_B;

        uint32_t ah[2][2][4], al[2][2][4], bh[2][8][2];
        load_q(base, 0, ah[0], al[0], bh[0]);
#pragma unroll
        for (int kk = 0; kk < 4; kk++) {
            const int cur = kk & 1, nxt = cur ^ 1;
            if (kk < 3) load_q(base, kk + 1, ah[nxt], al[nxt], bh[nxt]);
            // term-major: pass 1 Ah*Bh, pass 2 Al*Bh
#pragma unroll
            for (int mt = 0; mt < 2; mt++)
#pragma unroll
                for (int nt = 0; nt < 8; nt++)
                    MMA_F16(g.acc[mt][nt], ah[cur][mt], bh[cur][nt][0], bh[cur][nt][1]);
#pragma unroll
            for (int mt = 0; mt < 2; mt++)
#pragma unroll
                for (int nt = 0; nt < 8; nt++)
                    MMA_F16(g.acc[mt][nt], al[cur][mt], bh[cur][nt][0], bh[cur][nt][1]);
        }
        __syncthreads();   // protect stage buffer before next overwrite
    }
}

// ---------------- GEMM -> fp32 C (O projection) ------------------------------
__global__ __launch_bounds__(256, 2) void gemm_mma_kernel(
    const __half* __restrict__ Ah, const __half* __restrict__ Al,
    const __half* __restrict__ Bh, float* __restrict__ C, int M, int N, int K)
{
    extern __shared__ __align__(128) char smem_raw[];
    GemmCtx g;
    g.lane = threadIdx.x & 31; g.wid = threadIdx.x >> 5;
    g.wm = g.wid & 3; g.wn = g.wid >> 2;
    g.bm = blockIdx.y * 128; g.bn = blockIdx.x * 128;
    gemm_mainloop(g, smem_raw, Ah, Al, Bh, K);

    const int gr = g.lane >> 2, t2 = (g.lane & 3) * 2;
#pragma unroll
    for (int mt = 0; mt < 2; mt++) {
#pragma unroll
        for (int nt = 0; nt < 8; nt++) {
            int row = g.bm + g.wm * 32 + mt * 16 + gr;
            int col = g.bn + g.wn * 64 + nt * 8 + t2;
            *(float2*)&C[(size_t)row * N + col] =
                make_float2(g.acc[mt][nt][0], g.acc[mt][nt][1]);
            *(float2*)&C[(size_t)(row + 8) * N + col] =
                make_float2(g.acc[mt][nt][2], g.acc[mt][nt][3]);
        }
    }
}

// ---------------- fused QKV GEMM: rope/scale/split epilogue ------------------
__device__ __forceinline__ void rope_split_store_h(
    __half* oh, __half* ol,
    const float* __restrict__ fc, const float* __restrict__ fs,
    int row, int col, float v0, float v1, int stride, int coloff, float scale,
    bool want_lo)
{
    int s = row & (SEQ - 1);
    int i = (col & 127) >> 1;
    float c  = __ldg(fc + s * 64 + i);
    float sn = __ldg(fs + s * 64 + i);
    float ra = (v0 * c - v1 * sn) * scale;
    float rb = (v0 * sn + v1 * c) * scale;
    uint32_t h, l;
    split_pack_h(ra, rb, h, l);
    size_t o = (size_t)row * stride + (col - coloff);
    *(uint32_t*)(oh + o) = h;
    if (want_lo) *(uint32_t*)(ol + o) = l;
}

__global__ __launch_bounds__(256, 2) void gemm_qkv_kernel(
    const __half* __restrict__ Ah, const __half* __restrict__ Al,
    const __half* __restrict__ Bh,
    const float* __restrict__ fc, const float* __restrict__ fs,
    __half* __restrict__ qh, __half* __restrict__ ql,
    __half* __restrict__ kh, __half* __restrict__ vh, int K)
{
    extern __shared__ __align__(128) char smem_raw[];
    GemmCtx g;
    g.lane = threadIdx.x & 31; g.wid = threadIdx.x >> 5;
    g.wm = g.wid & 3; g.wn = g.wid >> 2;
    g.bm = blockIdx.y * 128; g.bn = blockIdx.x * 128;
    gemm_mainloop(g, smem_raw, Ah, Al, Bh, K);

    const int gr = g.lane >> 2, t2 = (g.lane & 3) * 2;
    const float qscale = 0.0883883476483184f;  // 1/sqrt(128)

    if (g.bn < DMODEL) {            // Q: rope + scale + split (hi+lo)
#pragma unroll
        for (int mt = 0; mt < 2; mt++)
#pragma unroll
            for (int nt = 0; nt < 8; nt++) {
                int row = g.bm + g.wm * 32 + mt * 16 + gr;
                int col = g.bn + g.wn * 64 + nt * 8 + t2;
                rope_split_store_h(qh, ql, fc, fs, row, col,
                                   g.acc[mt][nt][0], g.acc[mt][nt][1], DMODEL, 0,
                                   qscale, true);
                rope_split_store_h(qh, ql, fc, fs, row + 8, col,
                                   g.acc[mt][nt][2], g.acc[mt][nt][3], DMODEL, 0,
                                   qscale, true);
            }
    } else if (g.bn < DMODEL + NKV) {  // K: rope, hi only
#pragma unroll
        for (int mt = 0; mt < 2; mt++)
#pragma unroll
            for (int nt = 0; nt < 8; nt++) {
                int row = g.bm + g.wm * 32 + mt * 16 + gr;
                int col = g.bn + g.wn * 64 + nt * 8 + t2;
                rope_split_store_h(kh, nullptr, fc, fs, row, col,
                                   g.acc[mt][nt][0], g.acc[mt][nt][1], NKV, DMODEL,
                                   1.0f, false);
                rope_split_store_h(kh, nullptr, fc, fs, row + 8, col,
                                   g.acc[mt][nt][2], g.acc[mt][nt][3], NKV, DMODEL,
                                   1.0f, false);
            }
    } else {                            // V: hi only
#pragma unroll
        for (int mt = 0; mt < 2; mt++)
#pragma unroll
            for (int nt = 0; nt < 8; nt++) {
                int row = g.bm + g.wm * 32 + mt * 16 + gr;
                int col = g.bn + g.wn * 64 + nt * 8 + t2 - (DMODEL + NKV);
                size_t o0 = (size_t)row * NKV + col;
                *(uint32_t*)(vh + o0) = pack2h(g.acc[mt][nt][0], g.acc[mt][nt][1]);
                size_t o1 = o0 + (size_t)8 * NKV;
                *(uint32_t*)(vh + o1) = pack2h(g.acc[mt][nt][2], g.acc[mt][nt][3]);
            }
    }
}

// ---------------- fp32 -> fp16 hi/lo split (x) --------------------------------
__global__ __launch_bounds__(256) void convert_split_kernel(
    const float* __restrict__ in, __half* __restrict__ oh,
    __half* __restrict__ ol, int n4)
{
    int i = blockIdx.x * blockDim.x + threadIdx.x;
    if (i >= n4) return;
    float4 v = ((const float4*)in)[i];
    uint32_t h0, l0, h1, l1;
    split_pack_h(v.x, v.y, h0, l0);
    split_pack_h(v.z, v.w, h1, l1);
    ((uint2*)oh)[i] = make_uint2(h0, h1);
    ((uint2*)ol)[i] = make_uint2(l0, l1);
}

// ---------------- fp32 [K,N] -> transposed fp16 [N,K] (hi only) --------------
__global__ __launch_bounds__(256) void transpose_h_kernel(
    const float* __restrict__ in, __half* __restrict__ oh, int K, int N)
{
    __shared__ float tile[32][33];
    const int k0 = blockIdx.y * 32, n0 = blockIdx.x * 32;
    const int tx = threadIdx.x & 31, ty = threadIdx.x >> 5;
#pragma unroll
    for (int i = 0; i < 32; i += 8)
        tile[ty + i][tx] = in[(size_t)(k0 + ty + i) * N + n0 + tx];
    __syncthreads();
#pragma unroll
    for (int i = 0; i < 32; i += 8) {
        float v = tile[tx][ty + i];
        oh[(size_t)(n0 + ty + i) * K + k0 + tx] = __float2half_rn(v);
    }
}

// ---------------- flash attention via mma.sync (fp16, A-side split) ----------
// BM=64, 4 warps x 16 rows, 2 CTAs/SM. Q hi+lo; K,V hi only.
// K/V loads via cp.async double buffering; heavy causal tiles launch first.
#define FP 272
#define FQH 0
#define FQL 17408
#define FKV0 34816            // buf0: K at +0, V at +17408
#define KVBUF_B 34816         // one K+V buffer
#define FLASH_SMEM 104448     // Q(2) + 2 x (K+V)

__global__ __launch_bounds__(128, 2) void flash_mma_kernel(
    const __half* __restrict__ Qh, const __half* __restrict__ Ql,
    const __half* __restrict__ Kh, const __half* __restrict__ Vh,
    __half* __restrict__ Oh, __half* __restrict__ Ol)
{
    extern __shared__ __align__(128) char sm[];
    const uint32_t sb = smem_to_u32(sm);
    const int qt = gridDim.x - 1 - blockIdx.x;   // heavy tiles first
    const int h = blockIdx.y, b = blockIdx.z;
    const int kvh = h >> 2;
    const int tid = threadIdx.x, lane = tid & 31, w = tid >> 5;
    const int q0 = qt * 64;

    const int lrow = (lane & 7) + ((lane >> 3) & 1) * 8;
    const int lk   = (lane >> 4) * 8;
    const int nrow = (lane >> 4) * 8 + (lane & 7);
    const int kadd = ((lane >> 3) & 1) * 8;
    const int trow = lane & 15;
    const int tcol = (lane >> 4) * 8;

    // cp.async K+V tile issue into buffer `buf`.
    // Token row stride is NKV halfs (off already includes kvh*HDIM).
    auto issue_kv = [&](int kt, int buf) {
        const size_t off = ((size_t)(b * SEQ + kt * 64) * NKVH + kvh) * HDIM;
        const __half* gk = Kh + off;
        const __half* gv = Vh + off;
        const uint32_t kb = sb + FKV0 + buf * KVBUF_B;
#pragma unroll
        for (int i = 0; i < 8; i++) {
            int c = i * 128 + tid;          // 1024 chunks per tile
            int r = c >> 4, ch = c & 15;
            uint32_t d = r * FP + ch * 16;
            CP_ASYNC_16(kb + d,         gk + (size_t)r * NKV + ch * 8);
            CP_ASYNC_16(kb + 17408 + d, gv + (size_t)r * NKV + ch * 8);
        }
        CP_COMMIT();
    };

    // Q hi/lo tile load (plain, one-time)
    {
        const size_t qoff = ((size_t)(b * SEQ + q0) * NQH + h) * HDIM;
        const uint4* gh = (const uint4*)(Qh + qoff);
        const uint4* gl = (const uint4*)(Ql + qoff);
        for (int i = tid; i < 1024; i += 128) {
            int r = i >> 4, c = i & 15;
            *(uint4*)(sm + FQH + r * FP + c * 16) = gh[(size_t)r * 512 + c];
            *(uint4*)(sm + FQL + r * FP + c * 16) = gl[(size_t)r * 512 + c];
        }
    }

    float m0 = -1e30f, m1 = -1e30f, l0 = 0.f, l1 = 0.f;
    float oacc[16][4];
#pragma unroll
    for (int nt = 0; nt < 16; nt++)
#pragma unroll
        for (int j = 0; j < 4; j++) oacc[nt][j] = 0.f;

    const int row0 = q0 + w * 16 + (lane >> 2);
    const int cb   = 2 * (lane & 3);
    const int ktiles = qt + 1;

    issue_kv(0, 0);

    for (int kt = 0; kt < ktiles; kt++) {
        if (kt + 1 < ktiles) issue_kv(kt + 1, (kt + 1) & 1);
        else CP_COMMIT();               // empty group keeps wait_1 semantics
        CP_WAIT_1();                    // tile kt resident
        __syncthreads();
        const uint32_t FKHb = FKV0 + (kt & 1) * KVBUF_B;
        const uint32_t FVHb = FKHb + 17408;

        float s[8][4];
#pragma unroll
        for (int nt = 0; nt < 8; nt++)
#pragma unroll
            for (int j = 0; j < 4; j++) s[nt][j] = 0.f;

#pragma unroll
        for (int ks = 0; ks < 8; ks++) {
            uint32_t ah[4], al[4];
            uint32_t aa = sb + FQH + (w * 16 + lrow) * FP + (ks * 16 + lk) * 2;
            LDMATRIX_X4(ah[0], ah[1], ah[2], ah[3], aa);
            LDMATRIX_X4(al[0], al[1], al[2], al[3], aa + (FQL - FQH));
            uint32_t bh[8][2];
#pragma unroll
            for (int p = 0; p < 4; p++) {
                uint32_t ba = sb + FKHb + (p * 16 + nrow) * FP + (ks * 16 + kadd) * 2;
                LDMATRIX_X4(bh[2*p][0], bh[2*p][1], bh[2*p+1][0], bh[2*p+1][1], ba);
            }
#pragma unroll
            for (int nt = 0; nt < 8; nt++) MMA_F16(s[nt], ah, bh[nt][0], bh[nt][1]);
#pragma unroll
            for (int nt = 0; nt < 8; nt++) MMA_F16(s[nt], al, bh[nt][0], bh[nt][1]);
        }

        if (kt == qt) {
            const int colb = kt * 64 + cb;
#pragma unroll
            for (int nt = 0; nt < 8; nt++) {
                int c0 = colb + 8 * nt;
                if (c0 > row0)     s[nt][0] = -1e30f;
                if (c0 + 1 > row0) s[nt][1] = -1e30f;
                if (c0 > row0 + 8)     s[nt][2] = -1e30f;
                if (c0 + 1 > row0 + 8) s[nt][3] = -1e30f;
            }
        }

        float mt0 = -1e30f, mt1 = -1e30f;
#pragma unroll
        for (int nt = 0; nt < 8; nt++) {
            mt0 = fmaxf(mt0, fmaxf(s[nt][0], s[nt][1]));
            mt1 = fmaxf(mt1, fmaxf(s[nt][2], s[nt][3]));
        }
        mt0 = fmaxf(mt0, __shfl_xor_sync(0xffffffffu, mt0, 1));
        mt0 = fmaxf(mt0, __shfl_xor_sync(0xffffffffu, mt0, 2));
        mt1 = fmaxf(mt1, __shfl_xor_sync(0xffffffffu, mt1, 1));
        mt1 = fmaxf(mt1, __shfl_xor_sync(0xffffffffu, mt1, 2));
        float mn0 = fmaxf(m0, mt0), mn1 = fmaxf(m1, mt1);
        float a0 = __expf(m0 - mn0), a1 = __expf(m1 - mn1);
        float ps0 = 0.f, ps1 = 0.f;
#pragma unroll
        for (int nt = 0; nt < 8; nt++) {
            s[nt][0] = __expf(s[nt][0] - mn0);
            s[nt][1] = __expf(s[nt][1] - mn0);
            s[nt][2] = __expf(s[nt][2] - mn1);
            s[nt][3] = __expf(s[nt][3] - mn1);
            ps0 += s[nt][0] + s[nt][1];
            ps1 += s[nt][2] + s[nt][3];
        }
        ps0 += __shfl_xor_sync(0xffffffffu, ps0, 1);
        ps0 += __shfl_xor_sync(0xffffffffu, ps0, 2);
        ps1 += __shfl_xor_sync(0xffffffffu, ps1, 1);
        ps1 += __shfl_xor_sync(0xffffffffu, ps1, 2);
        l0 = l0 * a0 + ps0;  m0 = mn0;
        l1 = l1 * a1 + ps1;  m1 = mn1;
#pragma unroll
        for (int nt = 0; nt < 16; nt++) {
            oacc[nt][0] *= a0; oacc[nt][1] *= a0;
            oacc[nt][2] *= a1; oacc[nt][3] *= a1;
        }

        // O += Ph*Vh + Pl*Vh (P residual corrected; V hi only)
#pragma unroll
        for (int j = 0; j < 4; j++) {
            uint32_t ph[4], pl[4];
            split_pack_h(s[2*j][0],   s[2*j][1],   ph[0], pl[0]);
            split_pack_h(s[2*j][2],   s[2*j][3],   ph[1], pl[1]);
            split_pack_h(s[2*j+1][0], s[2*j+1][1], ph[2], pl[2]);
            split_pack_h(s[2*j+1][2], s[2*j+1][3], ph[3], pl[3]);
            uint32_t vfh[8][4];
#pragma unroll
            for (int t = 0; t < 8; t++) {
                uint32_t va = sb + FVHb + (j * 16 + trow) * FP + (t * 16 + tcol) * 2;
                LDMATRIX_X4_T(vfh[t][0], vfh[t][1], vfh[t][2], vfh[t][3], va);
            }
#pragma unroll
            for (int t = 0; t < 8; t++) {
                MMA_F16(oacc[2*t],   ph, vfh[t][0], vfh[t][1]);
                MMA_F16(oacc[2*t+1], ph, vfh[t][2], vfh[t][3]);
            }
#pragma unroll
            for (int t = 0; t < 8; t++) {
                MMA_F16(oacc[2*t],   pl, vfh[t][0], vfh[t][1]);
                MMA_F16(oacc[2*t+1], pl, vfh[t][2], vfh[t][3]);
            }
        }
        __syncthreads();   // all smem reads of this buffer done before reuse
    }

    const float inv0 = 1.f / l0, inv1 = 1.f / l1;
    const size_t o0 = ((size_t)(b * SEQ + row0)) * DMODEL + h * HDIM + cb;
    const size_t o1 = ((size_t)(b * SEQ + row0 + 8)) * DMODEL + h * HDIM + cb;
#pragma unroll
    for (int nt = 0; nt < 16; nt++) {
        uint32_t hh, ll;
        split_pack_h(oacc[nt][0] * inv0, oacc[nt][1] * inv0, hh, ll);
        *(uint32_t*)(Oh + o0 + 8 * nt) = hh;
        *(uint32_t*)(Ol + o0 + 8 * nt) = ll;
        split_pack_h(oacc[nt][2] * inv1, oacc[nt][3] * inv1, hh, ll);
        *(uint32_t*)(Oh + o1 + 8 * nt) = hh;
        *(uint32_t*)(Ol + o1 + 8 * nt) = ll;
    }
}

// ---------------- host launcher ---------------------------------------------
extern "C" void kernel_launch(void* const* d_in, const int* in_sizes, int n_in,
                              void* d_out, int out_size)
{
    const float* x   = (const float*)d_in[0];
    const float* w_q = (const float*)d_in[1];
    const float* w_k = (const float*)d_in[2];
    const float* w_v = (const float*)d_in[3];
    const float* w_o = (const float*)d_in[4];
    const float* fc  = (const float*)d_in[5];
    const float* fs  = (const float*)d_in[6];
    float* out = (float*)d_out;

    __half *xh, *xl, *wqkvh, *woh, *ath, *atl, *qsh, *qsl, *ksh, *vsh;
    cudaGetSymbolAddress((void**)&xh,    g_xh);     cudaGetSymbolAddress((void**)&xl,  g_xl);
    cudaGetSymbolAddress((void**)&wqkvh, g_wqkv_h);
    cudaGetSymbolAddress((void**)&woh,   g_wot_h);
    cudaGetSymbolAddress((void**)&ath,   g_atth);   cudaGetSymbolAddress((void**)&atl, g_attl);
    cudaGetSymbolAddress((void**)&qsh,   g_qsh);    cudaGetSymbolAddress((void**)&qsl, g_qsl);
    cudaGetSymbolAddress((void**)&ksh,   g_ksh);    cudaGetSymbolAddress((void**)&vsh, g_vsh);

    cudaFuncSetAttribute(gemm_mma_kernel, cudaFuncAttributeMaxDynamicSharedMemorySize, GEMM_SMEM);
    cudaFuncSetAttribute(gemm_qkv_kernel, cudaFuncAttributeMaxDynamicSharedMemorySize, GEMM_SMEM);
    cudaFuncSetAttribute(flash_mma_kernel, cudaFuncAttributeMaxDynamicSharedMemorySize, FLASH_SMEM);

    const int M = BATCH * SEQ;  // 4096

    // weight transposes (hi only) into combined [6144,4096] and wot
    transpose_h_kernel<<<dim3(DMODEL / 32, DMODEL / 32), 256>>>(w_q, wqkvh, DMODEL, DMODEL);
    transpose_h_kernel<<<dim3(NKV / 32, DMODEL / 32), 256>>>(
        w_k, wqkvh + (size_t)DMODEL * DMODEL, DMODEL, NKV);
    transpose_h_kernel<<<dim3(NKV / 32, DMODEL / 32), 256>>>(
        w_v, wqkvh + (size_t)(DMODEL + NKV) * DMODEL, DMODEL, NKV);
    transpose_h_kernel<<<dim3(DMODEL / 32, DMODEL / 32), 256>>>(w_o, woh, DMODEL, DMODEL);

    // x split (hi + lo)
    {
        int n4 = (M * DMODEL) / 4;
        convert_split_kernel<<<(n4 + 255) / 256, 256>>>(x, xh, xl, n4);
    }

    // fused QKV projection + rope + split (one GEMM over N=6144)
    gemm_qkv_kernel<<<dim3(NQKV / 128, M / 128), 256, GEMM_SMEM>>>(
        xh, xl, wqkvh, fc, fs, qsh, qsl, ksh, vsh, DMODEL);

    // flash attention (cp.async K/V pipeline, heavy tiles first)
    flash_mma_kernel<<<dim3(SEQ / 64, NQH, BATCH), 128, FLASH_SMEM>>>(
        qsh, qsl, ksh, vsh, ath, atl);

    // O projection
    gemm_mma_kernel<<<dim3(DMODEL / 128, M / 128), 256, GEMM_SMEM>>>(
        ath, atl, woh, out, M, DMODEL, DMODEL);
}